// round 10
// baseline (speedup 1.0000x reference)
#include <cuda_runtime.h>
#include <math.h>

// Problem constants: K=16 neighbors, B=4 segments, sigma_g=0.1 -> exp(-nd2*50),
// lambda_tex=5, weight=1, D=64 features.
#define KNB   16
#define KP1   17
#define NSEG  4
#define MAXN  20480
#define FULLM 0xffffffffu

// Scratch (static __device__ — no allocation allowed)
__device__ float  g_featn[MAXN * 64];   // normalized features
__device__ int    g_nbr[MAXN * KNB];    // global neighbor indices
__device__ float  g_norm[MAXN * 3];     // unit normals (LAPACK-sign-faithful)
__device__ double g_acc;                // loss accumulator

// ---------------------------------------------------------------------------
__global__ void zero_acc_kernel() { g_acc = 0.0; }

// ---------------------------------------------------------------------------
// Warp per row: L2-normalize 64-d features. lane holds elems {lane, lane+32}.
__global__ void featnorm_kernel(const float* __restrict__ f, int N) {
    int warp = (blockIdx.x * blockDim.x + threadIdx.x) >> 5;
    int lane = threadIdx.x & 31;
    if (warp >= N) return;
    float a = f[warp * 64 + lane];
    float b = f[warp * 64 + 32 + lane];
    float s = a * a + b * b;
    #pragma unroll
    for (int o = 16; o; o >>= 1) s += __shfl_xor_sync(FULLM, s, o);
    float n = fmaxf(__fsqrt_rn(s), 1e-12f);
    g_featn[warp * 64 + lane]      = __fdiv_rn(a, n);
    g_featn[warp * 64 + 32 + lane] = __fdiv_rn(b, n);
}

// ---------------------------------------------------------------------------
// Thread-per-query KNN, two-pass threshold decomposition.
//
// SPEC FACTS (hard-won, R3..R9):
//  * The reference == the SERIAL swap chain's semantics (R3/R5, 8.7e-8);
//    true stable top-k differs on boundary ties (R4/R6/R7, 1.660091e-3).
//  * The chain's final KEY MULTISET is always the exact 17 smallest d2 values
//    (tie quirks only change which ids survive among equal keys).
// Therefore:
//  Pass 1: thr = 17th-smallest d2 via key-only min/max chain (cheap).
//  Pass 2: if #{d2 <= thr} == 17, the neighbor SET is forced; emit directly
//          (downstream consumers are order-invariant over the K neighbors).
//  Fallback (#{d2 <= thr} != 17, genuine boundary tie, ~1e-3 of queries):
//          rerun the verbatim R5 serial chain for this thread — exact.
// Self is dropped by identity (d2_self == 0 exactly: sq and dot round
// identically), matching the passing R3/R5 rule.
__device__ __forceinline__ float cand_d2(float4 Q, float4 P) {
    float dot = __fadd_rn(__fadd_rn(__fmul_rn(Q.x, P.x),
                                    __fmul_rn(Q.y, P.y)),
                          __fmul_rn(Q.z, P.z));
    return __fadd_rn(__fadd_rn(Q.w, P.w), __fmul_rn(-2.0f, dot));
}

#define KNN_BLK 128

__global__ void __launch_bounds__(KNN_BLK, 2)
knn_kernel(const float* __restrict__ pos, int M, int Mpad, int bps) {
    extern __shared__ float4 sp[];
    int seg  = blockIdx.x / bps;
    int lb   = blockIdx.x % bps;
    int base = seg * M;
    const float INF = __int_as_float(0x7f800000);

    for (int t = threadIdx.x; t < Mpad; t += blockDim.x) {
        if (t < M) {
            float x = pos[(base + t) * 3 + 0];
            float y = pos[(base + t) * 3 + 1];
            float z = pos[(base + t) * 3 + 2];
            float sq = __fadd_rn(__fadd_rn(__fmul_rn(x, x), __fmul_rn(y, y)),
                                 __fmul_rn(z, z));
            sp[t] = make_float4(x, y, z, sq);
        } else {
            sp[t] = make_float4(0.0f, 0.0f, 0.0f, INF);
        }
    }
    __syncthreads();

    int q = lb * KNN_BLK + threadIdx.x;
    if (q >= M) return;
    float4 Q = sp[q];

    // ---- Pass 1: 17th-smallest d2 (key-only min/max chain) ----
    float key[KP1];
    #pragma unroll
    for (int t = 0; t < KP1; t++) key[t] = 3.4e38f;

    {
        int j = 0;
        int M4 = M & ~3;
        for (; j < M4; j += 4) {
            float d0 = cand_d2(Q, sp[j + 0]);
            float d1 = cand_d2(Q, sp[j + 1]);
            float d2 = cand_d2(Q, sp[j + 2]);
            float d3 = cand_d2(Q, sp[j + 3]);
            #define KCHAIN(D)                                              \
                if ((D) < key[KP1 - 1]) {                                  \
                    float kd = (D);                                        \
                    _Pragma("unroll")                                      \
                    for (int t = 0; t < KP1; t++) {                        \
                        float o = key[t];                                  \
                        key[t] = fminf(kd, o);                             \
                        kd     = fmaxf(kd, o);                             \
                    }                                                      \
                }
            KCHAIN(d0); KCHAIN(d1); KCHAIN(d2); KCHAIN(d3);
        }
        for (; j < M; j++) {
            float d = cand_d2(Q, sp[j]);
            KCHAIN(d);
            #undef KCHAIN
        }
    }
    float thr = key[KP1 - 1];

    // ---- Pass 2: threshold scan; emit forced set ----
    int outp = (base + q) * KNB;
    int w = 0;      // non-self matches written
    int c = 0;      // total matches incl. self
    for (int j = 0; j < M; j++) {
        float d2 = cand_d2(Q, sp[j]);
        if (d2 <= thr) {
            c++;
            if (j != q) {
                if (w < KNB) g_nbr[outp + w] = base + j;
                w++;
            }
        }
    }

    // ---- Rare exact fallback: boundary tie -> verbatim R5 chain ----
    if (c != KP1) {
        float fk[KP1];
        int   fi[KP1];
        #pragma unroll
        for (int t = 0; t < KP1; t++) { fk[t] = 3.4e38f; fi[t] = -1; }
        for (int j = 0; j < M; j++) {
            float kd = cand_d2(Q, sp[j]);
            if (kd < fk[KP1 - 1]) {
                int ki = j;
                #pragma unroll
                for (int t = 0; t < KP1; t++) {
                    if (kd < fk[t]) {
                        float tk = fk[t]; fk[t] = kd; kd = tk;
                        int   ti = fi[t]; fi[t] = ki; ki = ti;
                    }
                }
            }
        }
        int w2 = 0;
        #pragma unroll
        for (int t = 0; t < KP1; t++) {
            if (fi[t] != q && w2 < KNB) { g_nbr[outp + w2] = base + fi[t]; w2++; }
        }
    }
}

// ===========================================================================
// Faithful fp32 port of the LAPACK ssyevd(N=3, jobz='V', uplo='L') path:
// ssytrd (slarfg Householder) -> ssteqr('I') -> sormtr. All math in
// round-to-nearest intrinsics so fast-math flags cannot change decisions.
// ===========================================================================
__device__ __forceinline__ float f_div(float a, float b) { return __fdiv_rn(a, b); }
__device__ __forceinline__ float f_sqrt(float a)         { return __fsqrt_rn(a); }
// Fortran SIGN(a,b): |a| if b >= 0 (incl. -0.0 since -0>=0 in C), else -|a|.
__device__ __forceinline__ float f_sign(float a, float b) {
    float aa = fabsf(a);
    return (b >= 0.0f) ? aa : -aa;
}

__device__ float slapy2f(float x, float y) {
    float xa = fabsf(x), ya = fabsf(y);
    float w = fmaxf(xa, ya), zm = fminf(xa, ya);
    if (zm == 0.0f) return w;
    float q = f_div(zm, w);
    return __fmul_rn(w, f_sqrt(__fadd_rn(1.0f, __fmul_rn(q, q))));
}

// LAPACK >= 3.10 slartg (unscaled branch; our magnitudes are mid-range).
__device__ void slartgf(float f, float g, float* c, float* s, float* r) {
    if (g == 0.0f)      { *c = 1.0f; *s = 0.0f; *r = f; }
    else if (f == 0.0f) { *c = 0.0f; *s = f_sign(1.0f, g); *r = fabsf(g); }
    else {
        float d = f_sqrt(__fadd_rn(__fmul_rn(f, f), __fmul_rn(g, g)));
        *c = f_div(fabsf(f), d);
        *r = f_sign(d, f);
        *s = f_div(g, *r);
    }
}

__device__ void slaev2f(float a, float b, float c_, float* rt1, float* rt2,
                        float* cs1, float* sn1) {
    float sm  = __fadd_rn(a, c_);
    float df  = __fadd_rn(a, -c_);
    float adf = fabsf(df);
    float tb  = __fadd_rn(b, b);
    float ab  = fabsf(tb);
    float acmx, acmn;
    if (fabsf(a) > fabsf(c_)) { acmx = a; acmn = c_; }
    else                      { acmx = c_; acmn = a; }
    float rt;
    if (adf > ab) {
        float q = f_div(ab, adf);
        rt = __fmul_rn(adf, f_sqrt(__fadd_rn(1.0f, __fmul_rn(q, q))));
    } else if (adf < ab) {
        float q = f_div(adf, ab);
        rt = __fmul_rn(ab, f_sqrt(__fadd_rn(1.0f, __fmul_rn(q, q))));
    } else {
        rt = __fmul_rn(ab, f_sqrt(2.0f));
    }
    int sgn1;
    if (sm < 0.0f) {
        *rt1 = __fmul_rn(0.5f, __fadd_rn(sm, -rt)); sgn1 = -1;
        *rt2 = __fadd_rn(__fmul_rn(f_div(acmx, *rt1), acmn),
                         -__fmul_rn(f_div(b, *rt1), b));
    } else if (sm > 0.0f) {
        *rt1 = __fmul_rn(0.5f, __fadd_rn(sm, rt)); sgn1 = 1;
        *rt2 = __fadd_rn(__fmul_rn(f_div(acmx, *rt1), acmn),
                         -__fmul_rn(f_div(b, *rt1), b));
    } else {
        *rt1 = __fmul_rn(0.5f, rt); *rt2 = __fmul_rn(-0.5f, rt); sgn1 = 1;
    }
    float cs; int sgn2;
    if (df >= 0.0f) { cs = __fadd_rn(df, rt);  sgn2 = 1;  }
    else            { cs = __fadd_rn(df, -rt); sgn2 = -1; }
    float acs = fabsf(cs);
    float c1, s1;
    if (acs > ab) {
        float ct = f_div(-tb, cs);
        s1 = f_div(1.0f, f_sqrt(__fadd_rn(1.0f, __fmul_rn(ct, ct))));
        c1 = __fmul_rn(ct, s1);
    } else {
        if (ab == 0.0f) { c1 = 1.0f; s1 = 0.0f; }
        else {
            float tn = f_div(-cs, tb);
            c1 = f_div(1.0f, f_sqrt(__fadd_rn(1.0f, __fmul_rn(tn, tn))));
            s1 = __fmul_rn(tn, c1);
        }
    }
    if (sgn1 == sgn2) { float tn = c1; c1 = -s1; s1 = tn; }
    *cs1 = c1; *sn1 = s1;
}

// ssteqr('I', n=3): d[3], e[2], z = identity on entry; eigenvectors of the
// tridiagonal in z columns, ascending eigenvalues, LAPACK sign conventions.
__device__ void ssteqr3(float* d, float* e, float z[3][3]) {
    const float eps    = 5.9604645e-08f;   // slamch('E') fp32 = 2^-24
    const float eps2   = eps * eps;
    const float safmin = 1.1754944e-38f;
    const int   n = 3;
    const int   nmaxit = n * 30;
    int jtot = 0;
    int l1 = 1;                            // 1-based throughout

    for (int guard = 0; guard < 64; guard++) {
        if (l1 > n) break;
        if (l1 > 1) e[l1 - 2] = 0.0f;
        int m;
        for (m = l1; m <= n - 1; m++) {
            float tst = fabsf(e[m - 1]);
            if (tst == 0.0f) break;
            if (tst <= __fmul_rn(__fmul_rn(f_sqrt(fabsf(d[m - 1])),
                                           f_sqrt(fabsf(d[m]))), eps)) {
                e[m - 1] = 0.0f;
                break;
            }
        }
        int l = l1, lsv = l, lend = m, lendsv = lend;
        l1 = m + 1;
        if (lend == l) continue;

        if (fabsf(d[lend - 1]) < fabsf(d[l - 1])) { lend = lsv; l = lendsv; }

        if (lend > l) {
            // ---- QL iteration ----
            for (;;) {
                int mm_;
                for (mm_ = l; mm_ <= lend - 1; mm_++) {
                    float tst = __fmul_rn(e[mm_ - 1], e[mm_ - 1]);
                    if (tst <= __fadd_rn(__fmul_rn(__fmul_rn(eps2, fabsf(d[mm_ - 1])),
                                                   fabsf(d[mm_])), safmin))
                        break;
                }
                int m2 = mm_;                        // == lend if no break
                if (m2 < lend) e[m2 - 1] = 0.0f;
                float p = d[l - 1];
                if (m2 == l) {                       // eigenvalue found
                    d[l - 1] = p;
                    l++;
                    if (l <= lend) continue;
                    break;
                }
                if (m2 == l + 1) {                   // 2x2: slaev2
                    float rt1, rt2, cc, ss;
                    slaev2f(d[l - 1], e[l - 1], d[l], &rt1, &rt2, &cc, &ss);
                    for (int i2 = 0; i2 < 3; i2++) { // slasr 'R','V','B', 2 cols
                        float t = z[i2][l];
                        z[i2][l]     = __fadd_rn(__fmul_rn(cc, t), -__fmul_rn(ss, z[i2][l - 1]));
                        z[i2][l - 1] = __fadd_rn(__fmul_rn(ss, t),  __fmul_rn(cc, z[i2][l - 1]));
                    }
                    d[l - 1] = rt1; d[l] = rt2; e[l - 1] = 0.0f;
                    l += 2;
                    if (l <= lend) continue;
                    break;
                }
                if (jtot == nmaxit) break;
                jtot++;
                float g = f_div(__fadd_rn(d[l], -p), __fmul_rn(2.0f, e[l - 1]));
                float r = slapy2f(g, 1.0f);
                g = __fadd_rn(__fadd_rn(d[m2 - 1], -p),
                              f_div(e[l - 1], __fadd_rn(g, f_sign(r, g))));
                float s = 1.0f, c = 1.0f;
                p = 0.0f;
                float csv[2], snv[2];
                for (int i2 = m2 - 1; i2 >= l; i2--) {
                    float fv = __fmul_rn(s, e[i2 - 1]);
                    float bv = __fmul_rn(c, e[i2 - 1]);
                    slartgf(g, fv, &c, &s, &r);
                    if (i2 != m2 - 1) e[i2] = r;
                    g = __fadd_rn(d[i2], -p);
                    r = __fadd_rn(__fmul_rn(__fadd_rn(d[i2 - 1], -g), s),
                                  __fmul_rn(__fmul_rn(2.0f, c), bv));
                    p = __fmul_rn(s, r);
                    d[i2] = __fadd_rn(g, p);
                    g = __fadd_rn(__fmul_rn(c, r), -bv);
                    csv[i2 - l] = c; snv[i2 - l] = -s;
                }
                int cnt = m2 - l + 1;               // slasr 'R','V','B'
                for (int jj = cnt - 1; jj >= 1; jj--) {
                    float cc = csv[jj - 1], ss = snv[jj - 1];
                    for (int i2 = 0; i2 < 3; i2++) {
                        float t = z[i2][l - 1 + jj];
                        z[i2][l - 1 + jj]     = __fadd_rn(__fmul_rn(cc, t), -__fmul_rn(ss, z[i2][l - 2 + jj]));
                        z[i2][l - 2 + jj]     = __fadd_rn(__fmul_rn(ss, t),  __fmul_rn(cc, z[i2][l - 2 + jj]));
                    }
                }
                d[l - 1] = __fadd_rn(d[l - 1], -p);
                e[l - 1] = g;
            }
        } else {
            // ---- QR iteration (lend < l) ----
            for (;;) {
                int mm_;
                for (mm_ = l; mm_ >= lend + 1; mm_--) {
                    float tst = __fmul_rn(e[mm_ - 2], e[mm_ - 2]);
                    if (tst <= __fadd_rn(__fmul_rn(__fmul_rn(eps2, fabsf(d[mm_ - 1])),
                                                   fabsf(d[mm_ - 2])), safmin))
                        break;
                }
                int m2 = mm_;                        // == lend if no break
                if (m2 > lend) e[m2 - 2] = 0.0f;
                float p = d[l - 1];
                if (m2 == l) {
                    d[l - 1] = p;
                    l--;
                    if (l >= lend) continue;
                    break;
                }
                if (m2 == l - 1) {
                    float rt1, rt2, cc, ss;
                    slaev2f(d[l - 2], e[l - 2], d[l - 1], &rt1, &rt2, &cc, &ss);
                    for (int i2 = 0; i2 < 3; i2++) { // slasr 'R','V','F', 2 cols
                        float t = z[i2][l - 1];
                        z[i2][l - 1] = __fadd_rn(__fmul_rn(cc, t), -__fmul_rn(ss, z[i2][l - 2]));
                        z[i2][l - 2] = __fadd_rn(__fmul_rn(ss, t),  __fmul_rn(cc, z[i2][l - 2]));
                    }
                    d[l - 2] = rt1; d[l - 1] = rt2; e[l - 2] = 0.0f;
                    l -= 2;
                    if (l >= lend) continue;
                    break;
                }
                if (jtot == nmaxit) break;
                jtot++;
                float g = f_div(__fadd_rn(d[l - 2], -p), __fmul_rn(2.0f, e[l - 2]));
                float r = slapy2f(g, 1.0f);
                g = __fadd_rn(__fadd_rn(d[m2 - 1], -p),
                              f_div(e[l - 2], __fadd_rn(g, f_sign(r, g))));
                float s = 1.0f, c = 1.0f;
                p = 0.0f;
                float csv[2], snv[2];
                for (int i2 = m2; i2 <= l - 1; i2++) {
                    float fv = __fmul_rn(s, e[i2 - 1]);
                    float bv = __fmul_rn(c, e[i2 - 1]);
                    slartgf(g, fv, &c, &s, &r);
                    if (i2 != m2) e[i2 - 2] = r;
                    g = __fadd_rn(d[i2 - 1], -p);
                    r = __fadd_rn(__fmul_rn(__fadd_rn(d[i2], -g), s),
                                  __fmul_rn(__fmul_rn(2.0f, c), bv));
                    p = __fmul_rn(s, r);
                    d[i2 - 1] = __fadd_rn(g, p);
                    g = __fadd_rn(__fmul_rn(c, r), -bv);
                    csv[i2 - m2] = c; snv[i2 - m2] = s;
                }
                int cnt = l - m2 + 1;               // slasr 'R','V','F'
                for (int jj = 1; jj <= cnt - 1; jj++) {
                    float cc = csv[jj - 1], ss = snv[jj - 1];
                    for (int i2 = 0; i2 < 3; i2++) {
                        float t = z[i2][m2 - 1 + jj];
                        z[i2][m2 - 1 + jj] = __fadd_rn(__fmul_rn(cc, t), -__fmul_rn(ss, z[i2][m2 - 2 + jj]));
                        z[i2][m2 - 2 + jj] = __fadd_rn(__fmul_rn(ss, t),  __fmul_rn(cc, z[i2][m2 - 2 + jj]));
                    }
                }
                d[l - 1] = __fadd_rn(d[l - 1], -p);
                e[l - 2] = g;
            }
        }
    }

    // Sort eigenvalues ascending, swapping columns (no sign change).
    for (int ii = 2; ii <= n; ii++) {
        int i = ii - 1, k = i;
        float p = d[i - 1];
        for (int jj = ii; jj <= n; jj++)
            if (d[jj - 1] < p) { k = jj; p = d[jj - 1]; }
        if (k != i) {
            d[k - 1] = d[i - 1]; d[i - 1] = p;
            for (int r_ = 0; r_ < 3; r_++) {
                float t = z[r_][i - 1]; z[r_][i - 1] = z[r_][k - 1]; z[r_][k - 1] = t;
            }
        }
    }
}

// One thread per point: covariance of K neighbors, then LAPACK-faithful
// smallest-eigenvalue eigenvector (ssytrd + ssteqr + Householder apply).
__global__ void normals_kernel(const float* __restrict__ pos, int N) {
    int i = blockIdx.x * blockDim.x + threadIdx.x;
    if (i >= N) return;

    float px[KNB], py[KNB], pz[KNB];
    float mx = 0.f, my = 0.f, mz = 0.f;
    #pragma unroll
    for (int t = 0; t < KNB; t++) {
        int j = g_nbr[i * KNB + t];
        px[t] = pos[j * 3 + 0];
        py[t] = pos[j * 3 + 1];
        pz[t] = pos[j * 3 + 2];
        mx += px[t]; my += py[t]; mz += pz[t];
    }
    const float invK = 1.0f / (float)KNB;
    mx *= invK; my *= invK; mz *= invK;

    float c00 = 0.f, c10 = 0.f, c20 = 0.f, c11 = 0.f, c21 = 0.f, c22 = 0.f;
    #pragma unroll
    for (int t = 0; t < KNB; t++) {
        float dx = px[t] - mx, dy = py[t] - my, dz = pz[t] - mz;
        c00 += dx * dx; c10 += dy * dx; c20 += dz * dx;
        c11 += dy * dy; c21 += dz * dy; c22 += dz * dz;
    }
    c00 *= invK; c10 *= invK; c20 *= invK;
    c11 *= invK; c21 *= invK; c22 *= invK;

    // ---- ssytrd (lower, N=3): one Householder annihilating c20 ----
    float e0, e1, d1c, d2c, tau1, v3;
    if (c20 == 0.0f) {                     // xnorm == 0 -> tau = 0, H = I
        tau1 = 0.0f; v3 = 0.0f;
        e0 = c10; d1c = c11; d2c = c22; e1 = c21;
    } else {
        float alpha = c10;
        float beta  = -f_sign(slapy2f(alpha, fabsf(c20)), alpha);
        tau1 = f_div(__fadd_rn(beta, -alpha), beta);
        v3   = f_div(c20, __fadd_rn(alpha, -beta));
        e0   = beta;
        float x1 = __fmul_rn(tau1, __fadd_rn(c11, __fmul_rn(c21, v3)));
        float x2 = __fmul_rn(tau1, __fadd_rn(c21, __fmul_rn(c22, v3)));
        float al = __fmul_rn(__fmul_rn(-0.5f, tau1),
                             __fadd_rn(x1, __fmul_rn(x2, v3)));
        float w1 = __fadd_rn(x1, al);
        float w2 = __fadd_rn(x2, __fmul_rn(al, v3));
        d1c = __fadd_rn(c11, -__fmul_rn(2.0f, w1));
        e1  = __fadd_rn(c21, -__fadd_rn(__fmul_rn(v3, w1), w2));
        d2c = __fadd_rn(c22, -__fmul_rn(__fmul_rn(2.0f, v3), w2));
    }

    float d[3] = { c00, d1c, d2c };
    float e[2] = { e0, e1 };
    float z[3][3] = { {1.f, 0.f, 0.f}, {0.f, 1.f, 0.f}, {0.f, 0.f, 1.f} };
    ssteqr3(d, e, z);

    // ---- sormtr: v_full = Q * z[:,0], Q = I - tau*u*u', u = (0,1,v3) ----
    float z1 = z[1][0], z2 = z[2][0];
    float q11 = 1.0f - tau1;
    float q12 = -__fmul_rn(tau1, v3);
    float q22 = 1.0f - __fmul_rn(tau1, __fmul_rn(v3, v3));
    float vx = z[0][0];
    float vy = __fadd_rn(__fmul_rn(q11, z1), __fmul_rn(q12, z2));
    float vz = __fadd_rn(__fmul_rn(q12, z1), __fmul_rn(q22, z2));

    float nn = fmaxf(f_sqrt(vx * vx + vy * vy + vz * vz), 1e-12f);
    g_norm[i * 3 + 0] = f_div(vx, nn);
    g_norm[i * 3 + 1] = f_div(vy, nn);
    g_norm[i * 3 + 2] = f_div(vz, nn);
}

// ---------------------------------------------------------------------------
// Warp per point: 16 edges; fd2 via warp reduce; scalar terms per-lane.
__global__ void edge_kernel(const float* __restrict__ rgb,
                            const int* __restrict__ target, int N) {
    int warp = (blockIdx.x * blockDim.x + threadIdx.x) >> 5;
    int lane = threadIdx.x & 31;
    if (warp >= N) return;
    int i = warp;

    float f0 = g_featn[i * 64 + lane];
    float f1 = g_featn[i * 64 + 32 + lane];
    int   ti = target[i];
    float nix = g_norm[i * 3 + 0], niy = g_norm[i * 3 + 1], niz = g_norm[i * 3 + 2];
    float rix = rgb[i * 3 + 0],    riy = rgb[i * 3 + 1],    riz = rgb[i * 3 + 2];

    float acc = 0.0f;
    #pragma unroll
    for (int t = 0; t < KNB; t++) {
        int j = g_nbr[i * KNB + t];
        float d0 = f0 - g_featn[j * 64 + lane];
        float d1 = f1 - g_featn[j * 64 + 32 + lane];
        float s  = d0 * d0 + d1 * d1;
        #pragma unroll
        for (int o = 16; o; o >>= 1) s += __shfl_xor_sync(FULLM, s, o);

        bool gate = (target[j] == ti);
        float dx = nix - g_norm[j * 3 + 0];
        float dy = niy - g_norm[j * 3 + 1];
        float dz = niz - g_norm[j * 3 + 2];
        float nd2 = dx * dx + dy * dy + dz * dz;
        float geo = expf(-nd2 * 50.0f);          // exp(-nd2 / (2*0.1^2))

        float cx = rix - rgb[j * 3 + 0];
        float cy = riy - rgb[j * 3 + 1];
        float cz = riz - rgb[j * 3 + 2];
        float rd2 = cx * cx + cy * cy + cz * cz;
        float inv = tanhf(5.0f * rd2);

        if (gate) acc += geo * inv * s;
    }
    if (lane == 0) atomicAdd(&g_acc, (double)acc);
}

// ---------------------------------------------------------------------------
__global__ void finalize_kernel(float* out, int N) {
    out[0] = (float)(g_acc / (double)((long long)N * KNB));
}

// ---------------------------------------------------------------------------
extern "C" void kernel_launch(void* const* d_in, const int* in_sizes, int n_in,
                              void* d_out, int out_size) {
    const float* features = (const float*)d_in[0];
    const float* pos      = (const float*)d_in[1];
    const float* rgb      = (const float*)d_in[2];
    const int*   target   = (const int*)d_in[3];
    // d_in[4] = batch (sorted equal segments; implied by N/NSEG)

    int N = in_sizes[3];
    if (N > MAXN) N = MAXN;
    int M = N / NSEG;
    int Mpad = (M + 31) & ~31;

    zero_acc_kernel<<<1, 1>>>();

    int warpBlocks = (N + 3) / 4;                 // 4 warps (128 thr) per block
    featnorm_kernel<<<warpBlocks, 128>>>(features, N);

    int bps = (M + KNN_BLK - 1) / KNN_BLK;        // blocks per segment
    size_t smem = (size_t)Mpad * sizeof(float4);  // ~80 KB for M=5000
    cudaFuncSetAttribute(knn_kernel,
                         cudaFuncAttributeMaxDynamicSharedMemorySize,
                         (int)smem);
    knn_kernel<<<NSEG * bps, KNN_BLK, smem>>>(pos, M, Mpad, bps);

    normals_kernel<<<(N + 127) / 128, 128>>>(pos, N);

    edge_kernel<<<warpBlocks, 128>>>(rgb, target, N);

    finalize_kernel<<<1, 1>>>((float*)d_out, N);
}

// round 11
// speedup vs baseline: 1.5735x; 1.5735x over previous
#include <cuda_runtime.h>
#include <math.h>

// Problem constants: K=16 neighbors, B=4 segments, sigma_g=0.1 -> exp(-nd2*50),
// lambda_tex=5, weight=1, D=64 features.
#define KNB   16
#define KP1   17
#define NSEG  4
#define MAXN  20480
#define QPB   16            // queries per block = warps per block (512 threads)
#define FULLM 0xffffffffu

// Scratch (static __device__ — no allocation allowed)
__device__ float  g_featn[MAXN * 64];   // normalized features
__device__ int    g_nbr[MAXN * KNB];    // global neighbor indices
__device__ float  g_norm[MAXN * 3];     // unit normals (LAPACK-sign-faithful)
__device__ double g_acc;                // loss accumulator

// ---------------------------------------------------------------------------
__global__ void zero_acc_kernel() { g_acc = 0.0; }

// ---------------------------------------------------------------------------
// Warp per row: L2-normalize 64-d features. lane holds elems {lane, lane+32}.
__global__ void featnorm_kernel(const float* __restrict__ f, int N) {
    int warp = (blockIdx.x * blockDim.x + threadIdx.x) >> 5;
    int lane = threadIdx.x & 31;
    if (warp >= N) return;
    float a = f[warp * 64 + lane];
    float b = f[warp * 64 + 32 + lane];
    float s = a * a + b * b;
    #pragma unroll
    for (int o = 16; o; o >>= 1) s += __shfl_xor_sync(FULLM, s, o);
    float n = fmaxf(__fsqrt_rn(s), 1e-12f);
    g_featn[warp * 64 + lane]      = __fdiv_rn(a, n);
    g_featn[warp * 64 + 32 + lane] = __fdiv_rn(b, n);
}

// ---------------------------------------------------------------------------
// Warp-per-query KNN, two-pass threshold decomposition, fully warp-uniform.
//
// SPEC FACTS (R3..R10):
//  * Reference == serial swap chain semantics (R3/R5/R9: 8.7e-8); true stable
//    top-k differs on boundary ties (R4/R6/R7: 1.66e-3).
//  * The chain's final KEY MULTISET is exactly the 17 smallest d2 values, so
//    thr (17th smallest) is selection-algorithm independent.
//  * Neighbor SET determines the loss; emission ORDER only perturbs covariance
//    rounding (~1ulp -> rel_err 2.6e-7, validated PASSING in R10).
//
// Pass 1: warp-parallel scan; ballot prefilter; broadcast insert into a
//         KEY-ONLY min/max chain (warp-uniform) -> thr.
// Pass 2: warp-parallel threshold scan, ballot compaction, index-order emit.
// Fallback (c != 17, genuine boundary tie, ~2e-3 of queries): verbatim R5
//         id-chain (warp-uniform), lane 0 emits — exact by construction.
__device__ __forceinline__ float cand_d2(float4 Q, float4 P) {
    float dot = __fadd_rn(__fadd_rn(__fmul_rn(Q.x, P.x),
                                    __fmul_rn(Q.y, P.y)),
                          __fmul_rn(Q.z, P.z));
    return __fadd_rn(__fadd_rn(Q.w, P.w), __fmul_rn(-2.0f, dot));
}

__global__ void __launch_bounds__(QPB * 32, 2)
knn_kernel(const float* __restrict__ pos, int M, int Mpad, int bps) {
    extern __shared__ float4 sp[];
    int seg  = blockIdx.x / bps;
    int lb   = blockIdx.x % bps;
    int base = seg * M;
    const float INF = __int_as_float(0x7f800000);

    for (int t = threadIdx.x; t < Mpad; t += blockDim.x) {
        if (t < M) {
            float x = pos[(base + t) * 3 + 0];
            float y = pos[(base + t) * 3 + 1];
            float z = pos[(base + t) * 3 + 2];
            float sq = __fadd_rn(__fadd_rn(__fmul_rn(x, x), __fmul_rn(y, y)),
                                 __fmul_rn(z, z));
            sp[t] = make_float4(x, y, z, sq);
        } else {
            sp[t] = make_float4(0.0f, 0.0f, 0.0f, INF);  // d2=+inf: never passes
        }
    }
    __syncthreads();

    int warp = threadIdx.x >> 5;
    int lane = threadIdx.x & 31;
    int q = lb * QPB + warp;
    if (q >= M) return;                 // uniform per warp

    float4 Q = sp[q];

    // ---- Pass 1: thr = 17th-smallest d2 (key-only chain, warp-uniform) ----
    float key[KP1];
    #pragma unroll
    for (int t = 0; t < KP1; t++) key[t] = 3.4e38f;

    for (int j0 = 0; j0 < Mpad; j0 += 32) {
        float d2 = cand_d2(Q, sp[j0 + lane]);
        unsigned m = __ballot_sync(FULLM, d2 < key[KP1 - 1]);
        while (m) {
            int src = __ffs(m) - 1;
            m &= m - 1;
            float kd = __shfl_sync(FULLM, d2, src);
            if (kd < key[KP1 - 1]) {
                #pragma unroll
                for (int t = 0; t < KP1; t++) {
                    float o = key[t];
                    key[t] = fminf(kd, o);
                    kd     = fmaxf(kd, o);
                }
            }
        }
    }
    float thr = key[KP1 - 1];

    // ---- Pass 2: threshold scan + ballot compaction, index-order emit ----
    int outp = (base + q) * KNB;
    int w = 0;          // non-self matches written (warp-uniform)
    int c = 0;          // total matches incl. self (warp-uniform)
    for (int j0 = 0; j0 < Mpad; j0 += 32) {
        int j = j0 + lane;
        float d2 = cand_d2(Q, sp[j]);
        bool hit = (d2 <= thr);                   // padded: INF > thr
        unsigned hm = __ballot_sync(FULLM, hit);
        c += __popc(hm);
        bool emit = hit && (j != q);
        unsigned em = __ballot_sync(FULLM, emit);
        int pos = w + __popc(em & ((1u << lane) - 1u));
        if (emit && pos < KNB)
            g_nbr[outp + pos] = base + j;
        w += __popc(em);
    }

    // ---- Rare exact fallback: boundary tie -> verbatim R5 id-chain ----
    if (c != KP1) {
        float fk[KP1];
        int   fi[KP1];
        #pragma unroll
        for (int t = 0; t < KP1; t++) { fk[t] = 3.4e38f; fi[t] = -1; }
        for (int j0 = 0; j0 < Mpad; j0 += 32) {
            float d2 = cand_d2(Q, sp[j0 + lane]);
            unsigned m = __ballot_sync(FULLM, d2 < fk[KP1 - 1]);
            while (m) {
                int src = __ffs(m) - 1;
                m &= m - 1;
                float kd = __shfl_sync(FULLM, d2, src);
                int   ki = j0 + src;
                if (kd < fk[KP1 - 1]) {
                    #pragma unroll
                    for (int t = 0; t < KP1; t++) {
                        if (kd < fk[t]) {
                            float tk = fk[t]; fk[t] = kd; kd = tk;
                            int   ti = fi[t]; fi[t] = ki; ki = ti;
                        }
                    }
                }
            }
        }
        if (lane == 0) {
            int w2 = 0;
            #pragma unroll
            for (int t = 0; t < KP1; t++) {
                if (fi[t] != q && w2 < KNB) {
                    g_nbr[outp + w2] = base + fi[t]; w2++;
                }
            }
        }
    }
}

// ===========================================================================
// Faithful fp32 port of the LAPACK ssyevd(N=3, jobz='V', uplo='L') path:
// ssytrd (slarfg Householder) -> ssteqr('I') -> sormtr. All math in
// round-to-nearest intrinsics so fast-math flags cannot change decisions.
// ===========================================================================
__device__ __forceinline__ float f_div(float a, float b) { return __fdiv_rn(a, b); }
__device__ __forceinline__ float f_sqrt(float a)         { return __fsqrt_rn(a); }
// Fortran SIGN(a,b): |a| if b >= 0 (incl. -0.0 since -0>=0 in C), else -|a|.
__device__ __forceinline__ float f_sign(float a, float b) {
    float aa = fabsf(a);
    return (b >= 0.0f) ? aa : -aa;
}

__device__ float slapy2f(float x, float y) {
    float xa = fabsf(x), ya = fabsf(y);
    float w = fmaxf(xa, ya), zm = fminf(xa, ya);
    if (zm == 0.0f) return w;
    float q = f_div(zm, w);
    return __fmul_rn(w, f_sqrt(__fadd_rn(1.0f, __fmul_rn(q, q))));
}

// LAPACK >= 3.10 slartg (unscaled branch; our magnitudes are mid-range).
__device__ void slartgf(float f, float g, float* c, float* s, float* r) {
    if (g == 0.0f)      { *c = 1.0f; *s = 0.0f; *r = f; }
    else if (f == 0.0f) { *c = 0.0f; *s = f_sign(1.0f, g); *r = fabsf(g); }
    else {
        float d = f_sqrt(__fadd_rn(__fmul_rn(f, f), __fmul_rn(g, g)));
        *c = f_div(fabsf(f), d);
        *r = f_sign(d, f);
        *s = f_div(g, *r);
    }
}

__device__ void slaev2f(float a, float b, float c_, float* rt1, float* rt2,
                        float* cs1, float* sn1) {
    float sm  = __fadd_rn(a, c_);
    float df  = __fadd_rn(a, -c_);
    float adf = fabsf(df);
    float tb  = __fadd_rn(b, b);
    float ab  = fabsf(tb);
    float acmx, acmn;
    if (fabsf(a) > fabsf(c_)) { acmx = a; acmn = c_; }
    else                      { acmx = c_; acmn = a; }
    float rt;
    if (adf > ab) {
        float q = f_div(ab, adf);
        rt = __fmul_rn(adf, f_sqrt(__fadd_rn(1.0f, __fmul_rn(q, q))));
    } else if (adf < ab) {
        float q = f_div(adf, ab);
        rt = __fmul_rn(ab, f_sqrt(__fadd_rn(1.0f, __fmul_rn(q, q))));
    } else {
        rt = __fmul_rn(ab, f_sqrt(2.0f));
    }
    int sgn1;
    if (sm < 0.0f) {
        *rt1 = __fmul_rn(0.5f, __fadd_rn(sm, -rt)); sgn1 = -1;
        *rt2 = __fadd_rn(__fmul_rn(f_div(acmx, *rt1), acmn),
                         -__fmul_rn(f_div(b, *rt1), b));
    } else if (sm > 0.0f) {
        *rt1 = __fmul_rn(0.5f, __fadd_rn(sm, rt)); sgn1 = 1;
        *rt2 = __fadd_rn(__fmul_rn(f_div(acmx, *rt1), acmn),
                         -__fmul_rn(f_div(b, *rt1), b));
    } else {
        *rt1 = __fmul_rn(0.5f, rt); *rt2 = __fmul_rn(-0.5f, rt); sgn1 = 1;
    }
    float cs; int sgn2;
    if (df >= 0.0f) { cs = __fadd_rn(df, rt);  sgn2 = 1;  }
    else            { cs = __fadd_rn(df, -rt); sgn2 = -1; }
    float acs = fabsf(cs);
    float c1, s1;
    if (acs > ab) {
        float ct = f_div(-tb, cs);
        s1 = f_div(1.0f, f_sqrt(__fadd_rn(1.0f, __fmul_rn(ct, ct))));
        c1 = __fmul_rn(ct, s1);
    } else {
        if (ab == 0.0f) { c1 = 1.0f; s1 = 0.0f; }
        else {
            float tn = f_div(-cs, tb);
            c1 = f_div(1.0f, f_sqrt(__fadd_rn(1.0f, __fmul_rn(tn, tn))));
            s1 = __fmul_rn(tn, c1);
        }
    }
    if (sgn1 == sgn2) { float tn = c1; c1 = -s1; s1 = tn; }
    *cs1 = c1; *sn1 = s1;
}

// ssteqr('I', n=3): d[3], e[2], z = identity on entry; eigenvectors of the
// tridiagonal in z columns, ascending eigenvalues, LAPACK sign conventions.
__device__ void ssteqr3(float* d, float* e, float z[3][3]) {
    const float eps    = 5.9604645e-08f;   // slamch('E') fp32 = 2^-24
    const float eps2   = eps * eps;
    const float safmin = 1.1754944e-38f;
    const int   n = 3;
    const int   nmaxit = n * 30;
    int jtot = 0;
    int l1 = 1;                            // 1-based throughout

    for (int guard = 0; guard < 64; guard++) {
        if (l1 > n) break;
        if (l1 > 1) e[l1 - 2] = 0.0f;
        int m;
        for (m = l1; m <= n - 1; m++) {
            float tst = fabsf(e[m - 1]);
            if (tst == 0.0f) break;
            if (tst <= __fmul_rn(__fmul_rn(f_sqrt(fabsf(d[m - 1])),
                                           f_sqrt(fabsf(d[m]))), eps)) {
                e[m - 1] = 0.0f;
                break;
            }
        }
        int l = l1, lsv = l, lend = m, lendsv = lend;
        l1 = m + 1;
        if (lend == l) continue;

        if (fabsf(d[lend - 1]) < fabsf(d[l - 1])) { lend = lsv; l = lendsv; }

        if (lend > l) {
            // ---- QL iteration ----
            for (;;) {
                int mm_;
                for (mm_ = l; mm_ <= lend - 1; mm_++) {
                    float tst = __fmul_rn(e[mm_ - 1], e[mm_ - 1]);
                    if (tst <= __fadd_rn(__fmul_rn(__fmul_rn(eps2, fabsf(d[mm_ - 1])),
                                                   fabsf(d[mm_])), safmin))
                        break;
                }
                int m2 = mm_;                        // == lend if no break
                if (m2 < lend) e[m2 - 1] = 0.0f;
                float p = d[l - 1];
                if (m2 == l) {                       // eigenvalue found
                    d[l - 1] = p;
                    l++;
                    if (l <= lend) continue;
                    break;
                }
                if (m2 == l + 1) {                   // 2x2: slaev2
                    float rt1, rt2, cc, ss;
                    slaev2f(d[l - 1], e[l - 1], d[l], &rt1, &rt2, &cc, &ss);
                    for (int i2 = 0; i2 < 3; i2++) { // slasr 'R','V','B', 2 cols
                        float t = z[i2][l];
                        z[i2][l]     = __fadd_rn(__fmul_rn(cc, t), -__fmul_rn(ss, z[i2][l - 1]));
                        z[i2][l - 1] = __fadd_rn(__fmul_rn(ss, t),  __fmul_rn(cc, z[i2][l - 1]));
                    }
                    d[l - 1] = rt1; d[l] = rt2; e[l - 1] = 0.0f;
                    l += 2;
                    if (l <= lend) continue;
                    break;
                }
                if (jtot == nmaxit) break;
                jtot++;
                float g = f_div(__fadd_rn(d[l], -p), __fmul_rn(2.0f, e[l - 1]));
                float r = slapy2f(g, 1.0f);
                g = __fadd_rn(__fadd_rn(d[m2 - 1], -p),
                              f_div(e[l - 1], __fadd_rn(g, f_sign(r, g))));
                float s = 1.0f, c = 1.0f;
                p = 0.0f;
                float csv[2], snv[2];
                for (int i2 = m2 - 1; i2 >= l; i2--) {
                    float fv = __fmul_rn(s, e[i2 - 1]);
                    float bv = __fmul_rn(c, e[i2 - 1]);
                    slartgf(g, fv, &c, &s, &r);
                    if (i2 != m2 - 1) e[i2] = r;
                    g = __fadd_rn(d[i2], -p);
                    r = __fadd_rn(__fmul_rn(__fadd_rn(d[i2 - 1], -g), s),
                                  __fmul_rn(__fmul_rn(2.0f, c), bv));
                    p = __fmul_rn(s, r);
                    d[i2] = __fadd_rn(g, p);
                    g = __fadd_rn(__fmul_rn(c, r), -bv);
                    csv[i2 - l] = c; snv[i2 - l] = -s;
                }
                int cnt = m2 - l + 1;               // slasr 'R','V','B'
                for (int jj = cnt - 1; jj >= 1; jj--) {
                    float cc = csv[jj - 1], ss = snv[jj - 1];
                    for (int i2 = 0; i2 < 3; i2++) {
                        float t = z[i2][l - 1 + jj];
                        z[i2][l - 1 + jj]     = __fadd_rn(__fmul_rn(cc, t), -__fmul_rn(ss, z[i2][l - 2 + jj]));
                        z[i2][l - 2 + jj]     = __fadd_rn(__fmul_rn(ss, t),  __fmul_rn(cc, z[i2][l - 2 + jj]));
                    }
                }
                d[l - 1] = __fadd_rn(d[l - 1], -p);
                e[l - 1] = g;
            }
        } else {
            // ---- QR iteration (lend < l) ----
            for (;;) {
                int mm_;
                for (mm_ = l; mm_ >= lend + 1; mm_--) {
                    float tst = __fmul_rn(e[mm_ - 2], e[mm_ - 2]);
                    if (tst <= __fadd_rn(__fmul_rn(__fmul_rn(eps2, fabsf(d[mm_ - 1])),
                                                   fabsf(d[mm_ - 2])), safmin))
                        break;
                }
                int m2 = mm_;                        // == lend if no break
                if (m2 > lend) e[m2 - 2] = 0.0f;
                float p = d[l - 1];
                if (m2 == l) {
                    d[l - 1] = p;
                    l--;
                    if (l >= lend) continue;
                    break;
                }
                if (m2 == l - 1) {
                    float rt1, rt2, cc, ss;
                    slaev2f(d[l - 2], e[l - 2], d[l - 1], &rt1, &rt2, &cc, &ss);
                    for (int i2 = 0; i2 < 3; i2++) { // slasr 'R','V','F', 2 cols
                        float t = z[i2][l - 1];
                        z[i2][l - 1] = __fadd_rn(__fmul_rn(cc, t), -__fmul_rn(ss, z[i2][l - 2]));
                        z[i2][l - 2] = __fadd_rn(__fmul_rn(ss, t),  __fmul_rn(cc, z[i2][l - 2]));
                    }
                    d[l - 2] = rt1; d[l - 1] = rt2; e[l - 2] = 0.0f;
                    l -= 2;
                    if (l >= lend) continue;
                    break;
                }
                if (jtot == nmaxit) break;
                jtot++;
                float g = f_div(__fadd_rn(d[l - 2], -p), __fmul_rn(2.0f, e[l - 2]));
                float r = slapy2f(g, 1.0f);
                g = __fadd_rn(__fadd_rn(d[m2 - 1], -p),
                              f_div(e[l - 2], __fadd_rn(g, f_sign(r, g))));
                float s = 1.0f, c = 1.0f;
                p = 0.0f;
                float csv[2], snv[2];
                for (int i2 = m2; i2 <= l - 1; i2++) {
                    float fv = __fmul_rn(s, e[i2 - 1]);
                    float bv = __fmul_rn(c, e[i2 - 1]);
                    slartgf(g, fv, &c, &s, &r);
                    if (i2 != m2) e[i2 - 2] = r;
                    g = __fadd_rn(d[i2 - 1], -p);
                    r = __fadd_rn(__fmul_rn(__fadd_rn(d[i2], -g), s),
                                  __fmul_rn(__fmul_rn(2.0f, c), bv));
                    p = __fmul_rn(s, r);
                    d[i2 - 1] = __fadd_rn(g, p);
                    g = __fadd_rn(__fmul_rn(c, r), -bv);
                    csv[i2 - m2] = c; snv[i2 - m2] = s;
                }
                int cnt = l - m2 + 1;               // slasr 'R','V','F'
                for (int jj = 1; jj <= cnt - 1; jj++) {
                    float cc = csv[jj - 1], ss = snv[jj - 1];
                    for (int i2 = 0; i2 < 3; i2++) {
                        float t = z[i2][m2 - 1 + jj];
                        z[i2][m2 - 1 + jj] = __fadd_rn(__fmul_rn(cc, t), -__fmul_rn(ss, z[i2][m2 - 2 + jj]));
                        z[i2][m2 - 2 + jj] = __fadd_rn(__fmul_rn(ss, t),  __fmul_rn(cc, z[i2][m2 - 2 + jj]));
                    }
                }
                d[l - 1] = __fadd_rn(d[l - 1], -p);
                e[l - 2] = g;
            }
        }
    }

    // Sort eigenvalues ascending, swapping columns (no sign change).
    for (int ii = 2; ii <= n; ii++) {
        int i = ii - 1, k = i;
        float p = d[i - 1];
        for (int jj = ii; jj <= n; jj++)
            if (d[jj - 1] < p) { k = jj; p = d[jj - 1]; }
        if (k != i) {
            d[k - 1] = d[i - 1]; d[i - 1] = p;
            for (int r_ = 0; r_ < 3; r_++) {
                float t = z[r_][i - 1]; z[r_][i - 1] = z[r_][k - 1]; z[r_][k - 1] = t;
            }
        }
    }
}

// One thread per point: covariance of K neighbors, then LAPACK-faithful
// smallest-eigenvalue eigenvector (ssytrd + ssteqr + Householder apply).
__global__ void normals_kernel(const float* __restrict__ pos, int N) {
    int i = blockIdx.x * blockDim.x + threadIdx.x;
    if (i >= N) return;

    float px[KNB], py[KNB], pz[KNB];
    float mx = 0.f, my = 0.f, mz = 0.f;
    #pragma unroll
    for (int t = 0; t < KNB; t++) {
        int j = g_nbr[i * KNB + t];
        px[t] = pos[j * 3 + 0];
        py[t] = pos[j * 3 + 1];
        pz[t] = pos[j * 3 + 2];
        mx += px[t]; my += py[t]; mz += pz[t];
    }
    const float invK = 1.0f / (float)KNB;
    mx *= invK; my *= invK; mz *= invK;

    float c00 = 0.f, c10 = 0.f, c20 = 0.f, c11 = 0.f, c21 = 0.f, c22 = 0.f;
    #pragma unroll
    for (int t = 0; t < KNB; t++) {
        float dx = px[t] - mx, dy = py[t] - my, dz = pz[t] - mz;
        c00 += dx * dx; c10 += dy * dx; c20 += dz * dx;
        c11 += dy * dy; c21 += dz * dy; c22 += dz * dz;
    }
    c00 *= invK; c10 *= invK; c20 *= invK;
    c11 *= invK; c21 *= invK; c22 *= invK;

    // ---- ssytrd (lower, N=3): one Householder annihilating c20 ----
    float e0, e1, d1c, d2c, tau1, v3;
    if (c20 == 0.0f) {                     // xnorm == 0 -> tau = 0, H = I
        tau1 = 0.0f; v3 = 0.0f;
        e0 = c10; d1c = c11; d2c = c22; e1 = c21;
    } else {
        float alpha = c10;
        float beta  = -f_sign(slapy2f(alpha, fabsf(c20)), alpha);
        tau1 = f_div(__fadd_rn(beta, -alpha), beta);
        v3   = f_div(c20, __fadd_rn(alpha, -beta));
        e0   = beta;
        float x1 = __fmul_rn(tau1, __fadd_rn(c11, __fmul_rn(c21, v3)));
        float x2 = __fmul_rn(tau1, __fadd_rn(c21, __fmul_rn(c22, v3)));
        float al = __fmul_rn(__fmul_rn(-0.5f, tau1),
                             __fadd_rn(x1, __fmul_rn(x2, v3)));
        float w1 = __fadd_rn(x1, al);
        float w2 = __fadd_rn(x2, __fmul_rn(al, v3));
        d1c = __fadd_rn(c11, -__fmul_rn(2.0f, w1));
        e1  = __fadd_rn(c21, -__fadd_rn(__fmul_rn(v3, w1), w2));
        d2c = __fadd_rn(c22, -__fmul_rn(__fmul_rn(2.0f, v3), w2));
    }

    float d[3] = { c00, d1c, d2c };
    float e[2] = { e0, e1 };
    float z[3][3] = { {1.f, 0.f, 0.f}, {0.f, 1.f, 0.f}, {0.f, 0.f, 1.f} };
    ssteqr3(d, e, z);

    // ---- sormtr: v_full = Q * z[:,0], Q = I - tau*u*u', u = (0,1,v3) ----
    float z1 = z[1][0], z2 = z[2][0];
    float q11 = 1.0f - tau1;
    float q12 = -__fmul_rn(tau1, v3);
    float q22 = 1.0f - __fmul_rn(tau1, __fmul_rn(v3, v3));
    float vx = z[0][0];
    float vy = __fadd_rn(__fmul_rn(q11, z1), __fmul_rn(q12, z2));
    float vz = __fadd_rn(__fmul_rn(q12, z1), __fmul_rn(q22, z2));

    float nn = fmaxf(f_sqrt(vx * vx + vy * vy + vz * vz), 1e-12f);
    g_norm[i * 3 + 0] = f_div(vx, nn);
    g_norm[i * 3 + 1] = f_div(vy, nn);
    g_norm[i * 3 + 2] = f_div(vz, nn);
}

// ---------------------------------------------------------------------------
// Warp per point: 16 edges; fd2 via warp reduce; scalar terms per-lane.
__global__ void edge_kernel(const float* __restrict__ rgb,
                            const int* __restrict__ target, int N) {
    int warp = (blockIdx.x * blockDim.x + threadIdx.x) >> 5;
    int lane = threadIdx.x & 31;
    if (warp >= N) return;
    int i = warp;

    float f0 = g_featn[i * 64 + lane];
    float f1 = g_featn[i * 64 + 32 + lane];
    int   ti = target[i];
    float nix = g_norm[i * 3 + 0], niy = g_norm[i * 3 + 1], niz = g_norm[i * 3 + 2];
    float rix = rgb[i * 3 + 0],    riy = rgb[i * 3 + 1],    riz = rgb[i * 3 + 2];

    float acc = 0.0f;
    #pragma unroll
    for (int t = 0; t < KNB; t++) {
        int j = g_nbr[i * KNB + t];
        float d0 = f0 - g_featn[j * 64 + lane];
        float d1 = f1 - g_featn[j * 64 + 32 + lane];
        float s  = d0 * d0 + d1 * d1;
        #pragma unroll
        for (int o = 16; o; o >>= 1) s += __shfl_xor_sync(FULLM, s, o);

        bool gate = (target[j] == ti);
        float dx = nix - g_norm[j * 3 + 0];
        float dy = niy - g_norm[j * 3 + 1];
        float dz = niz - g_norm[j * 3 + 2];
        float nd2 = dx * dx + dy * dy + dz * dz;
        float geo = expf(-nd2 * 50.0f);          // exp(-nd2 / (2*0.1^2))

        float cx = rix - rgb[j * 3 + 0];
        float cy = riy - rgb[j * 3 + 1];
        float cz = riz - rgb[j * 3 + 2];
        float rd2 = cx * cx + cy * cy + cz * cz;
        float inv = tanhf(5.0f * rd2);

        if (gate) acc += geo * inv * s;
    }
    if (lane == 0) atomicAdd(&g_acc, (double)acc);
}

// ---------------------------------------------------------------------------
__global__ void finalize_kernel(float* out, int N) {
    out[0] = (float)(g_acc / (double)((long long)N * KNB));
}

// ---------------------------------------------------------------------------
extern "C" void kernel_launch(void* const* d_in, const int* in_sizes, int n_in,
                              void* d_out, int out_size) {
    const float* features = (const float*)d_in[0];
    const float* pos      = (const float*)d_in[1];
    const float* rgb      = (const float*)d_in[2];
    const int*   target   = (const int*)d_in[3];
    // d_in[4] = batch (sorted equal segments; implied by N/NSEG)

    int N = in_sizes[3];
    if (N > MAXN) N = MAXN;
    int M = N / NSEG;
    int Mpad = (M + 31) & ~31;

    zero_acc_kernel<<<1, 1>>>();

    int warpBlocks = (N + 3) / 4;                 // 4 warps (128 thr) per block
    featnorm_kernel<<<warpBlocks, 128>>>(features, N);

    int bps = (M + QPB - 1) / QPB;                // blocks per segment
    size_t smem = (size_t)Mpad * sizeof(float4);  // ~80 KB for M=5000
    cudaFuncSetAttribute(knn_kernel,
                         cudaFuncAttributeMaxDynamicSharedMemorySize,
                         (int)smem);
    knn_kernel<<<NSEG * bps, QPB * 32, smem>>>(pos, M, Mpad, bps);

    normals_kernel<<<(N + 127) / 128, 128>>>(pos, N);

    edge_kernel<<<warpBlocks, 128>>>(rgb, target, N);

    finalize_kernel<<<1, 1>>>((float*)d_out, N);
}

// round 12
// speedup vs baseline: 1.6494x; 1.0482x over previous
#include <cuda_runtime.h>
#include <math.h>

// Problem constants: K=16 neighbors, B=4 segments, sigma_g=0.1 -> exp(-nd2*50),
// lambda_tex=5, weight=1, D=64 features.
#define KNB   16
#define KP1   17
#define NSEG  4
#define MAXN  20480
#define QPB   16            // queries per block = warps per block (512 threads)
#define FULLM 0xffffffffu

// Scratch (static __device__ — no allocation allowed)
__device__ float  g_featn[MAXN * 64];   // normalized features
__device__ int    g_nbr[MAXN * KNB];    // global neighbor indices
__device__ float  g_norm[MAXN * 3];     // unit normals (LAPACK-sign-faithful)
__device__ double g_acc;                // loss accumulator

// ---------------------------------------------------------------------------
__global__ void zero_acc_kernel() { g_acc = 0.0; }

// ---------------------------------------------------------------------------
// Warp per row: L2-normalize 64-d features. lane holds elems {lane, lane+32}.
__global__ void featnorm_kernel(const float* __restrict__ f, int N) {
    int warp = (blockIdx.x * blockDim.x + threadIdx.x) >> 5;
    int lane = threadIdx.x & 31;
    if (warp >= N) return;
    float a = f[warp * 64 + lane];
    float b = f[warp * 64 + 32 + lane];
    float s = a * a + b * b;
    #pragma unroll
    for (int o = 16; o; o >>= 1) s += __shfl_xor_sync(FULLM, s, o);
    float n = fmaxf(__fsqrt_rn(s), 1e-12f);
    g_featn[warp * 64 + lane]      = __fdiv_rn(a, n);
    g_featn[warp * 64 + 32 + lane] = __fdiv_rn(b, n);
}

// ---------------------------------------------------------------------------
// Warp-per-query KNN, two-pass threshold decomposition, fully warp-uniform.
//
// SPEC FACTS (R3..R11):
//  * Reference == serial swap chain semantics; true stable top-k differs on
//    boundary ties. BUT: pass 2's count check makes pass 1 SELF-CERTIFYING —
//    any thr with #{d2 <= thr} == 17 selects exactly the 17-smallest set
//    (thr in [d17, d18) by counting); any other count -> exact R5 fallback.
//  * Key-only max-evict is multiset-safe (evicting either of two equal keys
//    leaves the same multiset) — id-tie semantics cannot apply to keys.
//  * Emission order only perturbs covariance rounding (~1ulp, rel_err 2.6e-7,
//    PASSING in R10/R11).
//
// Pass 1: DISTRIBUTED key-only top-17 (one key per lane 0..16); insertion =
//         replace-a-max-slot + fmax shfl reduce. thr = final max.
// Pass 2: warp-parallel threshold scan, single ballot (self always hits, so
//         count = emitted + 1), index-order emit.
// Fallback (count != 17, genuine boundary tie, ~2e-3 of queries): verbatim
//         R5 id-chain (warp-uniform), lane 0 emits — exact by construction.
__device__ __forceinline__ float cand_d2(float4 Q, float4 P) {
    float dot = __fadd_rn(__fadd_rn(__fmul_rn(Q.x, P.x),
                                    __fmul_rn(Q.y, P.y)),
                          __fmul_rn(Q.z, P.z));
    return __fadd_rn(__fadd_rn(Q.w, P.w), __fmul_rn(-2.0f, dot));
}

__global__ void __launch_bounds__(QPB * 32, 2)
knn_kernel(const float* __restrict__ pos, int M, int Mpad, int bps) {
    extern __shared__ float4 sp[];
    int seg  = blockIdx.x / bps;
    int lb   = blockIdx.x % bps;
    int base = seg * M;
    const float INF = __int_as_float(0x7f800000);

    for (int t = threadIdx.x; t < Mpad; t += blockDim.x) {
        if (t < M) {
            float x = pos[(base + t) * 3 + 0];
            float y = pos[(base + t) * 3 + 1];
            float z = pos[(base + t) * 3 + 2];
            float sq = __fadd_rn(__fadd_rn(__fmul_rn(x, x), __fmul_rn(y, y)),
                                 __fmul_rn(z, z));
            sp[t] = make_float4(x, y, z, sq);
        } else {
            sp[t] = make_float4(0.0f, 0.0f, 0.0f, INF);  // d2=+inf: never passes
        }
    }
    __syncthreads();

    int warp = threadIdx.x >> 5;
    int lane = threadIdx.x & 31;
    int q = lb * QPB + warp;
    if (q >= M) return;                 // uniform per warp

    float4 Q = sp[q];

    // ---- Pass 1: thr = 17th-smallest d2 (distributed key-only top-17) ----
    float kkey   = 3.4e38f;             // lane t (t<=16): one unsorted slot
    float curmax = 3.4e38f;             // uniform: max over slots 0..16

    for (int j0 = 0; j0 < Mpad; j0 += 32) {
        float d2 = cand_d2(Q, sp[j0 + lane]);
        unsigned m = __ballot_sync(FULLM, d2 < curmax);
        while (m) {
            int src = __ffs(m) - 1;
            m &= m - 1;
            float kd = __shfl_sync(FULLM, d2, src);
            if (kd < curmax) {          // uniform recheck (within-batch stale)
                // Replace one max-holding slot (any tied slot is fine:
                // key multiset is identical either way).
                unsigned mx = __ballot_sync(FULLM,
                                            (lane < KP1) && (kkey == curmax));
                if (lane == __ffs(mx) - 1) kkey = kd;
                // Recompute curmax: fmax shfl reduce over slots 0..16.
                float rk = (lane < KP1) ? kkey : -INF;
                #pragma unroll
                for (int o = 16; o; o >>= 1)
                    rk = fmaxf(rk, __shfl_xor_sync(FULLM, rk, o));
                curmax = rk;
            }
        }
    }
    float thr = curmax;

    // ---- Pass 2: threshold scan, single ballot, index-order emit ----
    // Self always hits (d2_self == 0 <= thr), so total hits = emitted + 1.
    int outp = (base + q) * KNB;
    int w = 0;          // non-self matches written (warp-uniform)
    for (int j0 = 0; j0 < Mpad; j0 += 32) {
        int j = j0 + lane;
        float d2 = cand_d2(Q, sp[j]);
        bool emit = (d2 <= thr) && (j != q);      // padded: INF > thr
        unsigned em = __ballot_sync(FULLM, emit);
        int pos = w + __popc(em & ((1u << lane) - 1u));
        if (emit && pos < KNB)
            g_nbr[outp + pos] = base + j;
        w += __popc(em);
    }

    // ---- Rare exact fallback: count != 17 -> verbatim R5 id-chain ----
    if (w + 1 != KP1) {
        float fk[KP1];
        int   fi[KP1];
        #pragma unroll
        for (int t = 0; t < KP1; t++) { fk[t] = 3.4e38f; fi[t] = -1; }
        for (int j0 = 0; j0 < Mpad; j0 += 32) {
            float d2 = cand_d2(Q, sp[j0 + lane]);
            unsigned m = __ballot_sync(FULLM, d2 < fk[KP1 - 1]);
            while (m) {
                int src = __ffs(m) - 1;
                m &= m - 1;
                float kd = __shfl_sync(FULLM, d2, src);
                int   ki = j0 + src;
                if (kd < fk[KP1 - 1]) {
                    #pragma unroll
                    for (int t = 0; t < KP1; t++) {
                        if (kd < fk[t]) {
                            float tk = fk[t]; fk[t] = kd; kd = tk;
                            int   ti = fi[t]; fi[t] = ki; ki = ti;
                        }
                    }
                }
            }
        }
        if (lane == 0) {
            int w2 = 0;
            #pragma unroll
            for (int t = 0; t < KP1; t++) {
                if (fi[t] != q && w2 < KNB) {
                    g_nbr[outp + w2] = base + fi[t]; w2++;
                }
            }
        }
    }
}

// ===========================================================================
// Faithful fp32 port of the LAPACK ssyevd(N=3, jobz='V', uplo='L') path:
// ssytrd (slarfg Householder) -> ssteqr('I') -> sormtr. All math in
// round-to-nearest intrinsics so fast-math flags cannot change decisions.
// ===========================================================================
__device__ __forceinline__ float f_div(float a, float b) { return __fdiv_rn(a, b); }
__device__ __forceinline__ float f_sqrt(float a)         { return __fsqrt_rn(a); }
// Fortran SIGN(a,b): |a| if b >= 0 (incl. -0.0 since -0>=0 in C), else -|a|.
__device__ __forceinline__ float f_sign(float a, float b) {
    float aa = fabsf(a);
    return (b >= 0.0f) ? aa : -aa;
}

__device__ float slapy2f(float x, float y) {
    float xa = fabsf(x), ya = fabsf(y);
    float w = fmaxf(xa, ya), zm = fminf(xa, ya);
    if (zm == 0.0f) return w;
    float q = f_div(zm, w);
    return __fmul_rn(w, f_sqrt(__fadd_rn(1.0f, __fmul_rn(q, q))));
}

// LAPACK >= 3.10 slartg (unscaled branch; our magnitudes are mid-range).
__device__ void slartgf(float f, float g, float* c, float* s, float* r) {
    if (g == 0.0f)      { *c = 1.0f; *s = 0.0f; *r = f; }
    else if (f == 0.0f) { *c = 0.0f; *s = f_sign(1.0f, g); *r = fabsf(g); }
    else {
        float d = f_sqrt(__fadd_rn(__fmul_rn(f, f), __fmul_rn(g, g)));
        *c = f_div(fabsf(f), d);
        *r = f_sign(d, f);
        *s = f_div(g, *r);
    }
}

__device__ void slaev2f(float a, float b, float c_, float* rt1, float* rt2,
                        float* cs1, float* sn1) {
    float sm  = __fadd_rn(a, c_);
    float df  = __fadd_rn(a, -c_);
    float adf = fabsf(df);
    float tb  = __fadd_rn(b, b);
    float ab  = fabsf(tb);
    float acmx, acmn;
    if (fabsf(a) > fabsf(c_)) { acmx = a; acmn = c_; }
    else                      { acmx = c_; acmn = a; }
    float rt;
    if (adf > ab) {
        float q = f_div(ab, adf);
        rt = __fmul_rn(adf, f_sqrt(__fadd_rn(1.0f, __fmul_rn(q, q))));
    } else if (adf < ab) {
        float q = f_div(adf, ab);
        rt = __fmul_rn(ab, f_sqrt(__fadd_rn(1.0f, __fmul_rn(q, q))));
    } else {
        rt = __fmul_rn(ab, f_sqrt(2.0f));
    }
    int sgn1;
    if (sm < 0.0f) {
        *rt1 = __fmul_rn(0.5f, __fadd_rn(sm, -rt)); sgn1 = -1;
        *rt2 = __fadd_rn(__fmul_rn(f_div(acmx, *rt1), acmn),
                         -__fmul_rn(f_div(b, *rt1), b));
    } else if (sm > 0.0f) {
        *rt1 = __fmul_rn(0.5f, __fadd_rn(sm, rt)); sgn1 = 1;
        *rt2 = __fadd_rn(__fmul_rn(f_div(acmx, *rt1), acmn),
                         -__fmul_rn(f_div(b, *rt1), b));
    } else {
        *rt1 = __fmul_rn(0.5f, rt); *rt2 = __fmul_rn(-0.5f, rt); sgn1 = 1;
    }
    float cs; int sgn2;
    if (df >= 0.0f) { cs = __fadd_rn(df, rt);  sgn2 = 1;  }
    else            { cs = __fadd_rn(df, -rt); sgn2 = -1; }
    float acs = fabsf(cs);
    float c1, s1;
    if (acs > ab) {
        float ct = f_div(-tb, cs);
        s1 = f_div(1.0f, f_sqrt(__fadd_rn(1.0f, __fmul_rn(ct, ct))));
        c1 = __fmul_rn(ct, s1);
    } else {
        if (ab == 0.0f) { c1 = 1.0f; s1 = 0.0f; }
        else {
            float tn = f_div(-cs, tb);
            c1 = f_div(1.0f, f_sqrt(__fadd_rn(1.0f, __fmul_rn(tn, tn))));
            s1 = __fmul_rn(tn, c1);
        }
    }
    if (sgn1 == sgn2) { float tn = c1; c1 = -s1; s1 = tn; }
    *cs1 = c1; *sn1 = s1;
}

// ssteqr('I', n=3): d[3], e[2], z = identity on entry; eigenvectors of the
// tridiagonal in z columns, ascending eigenvalues, LAPACK sign conventions.
__device__ void ssteqr3(float* d, float* e, float z[3][3]) {
    const float eps    = 5.9604645e-08f;   // slamch('E') fp32 = 2^-24
    const float eps2   = eps * eps;
    const float safmin = 1.1754944e-38f;
    const int   n = 3;
    const int   nmaxit = n * 30;
    int jtot = 0;
    int l1 = 1;                            // 1-based throughout

    for (int guard = 0; guard < 64; guard++) {
        if (l1 > n) break;
        if (l1 > 1) e[l1 - 2] = 0.0f;
        int m;
        for (m = l1; m <= n - 1; m++) {
            float tst = fabsf(e[m - 1]);
            if (tst == 0.0f) break;
            if (tst <= __fmul_rn(__fmul_rn(f_sqrt(fabsf(d[m - 1])),
                                           f_sqrt(fabsf(d[m]))), eps)) {
                e[m - 1] = 0.0f;
                break;
            }
        }
        int l = l1, lsv = l, lend = m, lendsv = lend;
        l1 = m + 1;
        if (lend == l) continue;

        if (fabsf(d[lend - 1]) < fabsf(d[l - 1])) { lend = lsv; l = lendsv; }

        if (lend > l) {
            // ---- QL iteration ----
            for (;;) {
                int mm_;
                for (mm_ = l; mm_ <= lend - 1; mm_++) {
                    float tst = __fmul_rn(e[mm_ - 1], e[mm_ - 1]);
                    if (tst <= __fadd_rn(__fmul_rn(__fmul_rn(eps2, fabsf(d[mm_ - 1])),
                                                   fabsf(d[mm_])), safmin))
                        break;
                }
                int m2 = mm_;                        // == lend if no break
                if (m2 < lend) e[m2 - 1] = 0.0f;
                float p = d[l - 1];
                if (m2 == l) {                       // eigenvalue found
                    d[l - 1] = p;
                    l++;
                    if (l <= lend) continue;
                    break;
                }
                if (m2 == l + 1) {                   // 2x2: slaev2
                    float rt1, rt2, cc, ss;
                    slaev2f(d[l - 1], e[l - 1], d[l], &rt1, &rt2, &cc, &ss);
                    for (int i2 = 0; i2 < 3; i2++) { // slasr 'R','V','B', 2 cols
                        float t = z[i2][l];
                        z[i2][l]     = __fadd_rn(__fmul_rn(cc, t), -__fmul_rn(ss, z[i2][l - 1]));
                        z[i2][l - 1] = __fadd_rn(__fmul_rn(ss, t),  __fmul_rn(cc, z[i2][l - 1]));
                    }
                    d[l - 1] = rt1; d[l] = rt2; e[l - 1] = 0.0f;
                    l += 2;
                    if (l <= lend) continue;
                    break;
                }
                if (jtot == nmaxit) break;
                jtot++;
                float g = f_div(__fadd_rn(d[l], -p), __fmul_rn(2.0f, e[l - 1]));
                float r = slapy2f(g, 1.0f);
                g = __fadd_rn(__fadd_rn(d[m2 - 1], -p),
                              f_div(e[l - 1], __fadd_rn(g, f_sign(r, g))));
                float s = 1.0f, c = 1.0f;
                p = 0.0f;
                float csv[2], snv[2];
                for (int i2 = m2 - 1; i2 >= l; i2--) {
                    float fv = __fmul_rn(s, e[i2 - 1]);
                    float bv = __fmul_rn(c, e[i2 - 1]);
                    slartgf(g, fv, &c, &s, &r);
                    if (i2 != m2 - 1) e[i2] = r;
                    g = __fadd_rn(d[i2], -p);
                    r = __fadd_rn(__fmul_rn(__fadd_rn(d[i2 - 1], -g), s),
                                  __fmul_rn(__fmul_rn(2.0f, c), bv));
                    p = __fmul_rn(s, r);
                    d[i2] = __fadd_rn(g, p);
                    g = __fadd_rn(__fmul_rn(c, r), -bv);
                    csv[i2 - l] = c; snv[i2 - l] = -s;
                }
                int cnt = m2 - l + 1;               // slasr 'R','V','B'
                for (int jj = cnt - 1; jj >= 1; jj--) {
                    float cc = csv[jj - 1], ss = snv[jj - 1];
                    for (int i2 = 0; i2 < 3; i2++) {
                        float t = z[i2][l - 1 + jj];
                        z[i2][l - 1 + jj]     = __fadd_rn(__fmul_rn(cc, t), -__fmul_rn(ss, z[i2][l - 2 + jj]));
                        z[i2][l - 2 + jj]     = __fadd_rn(__fmul_rn(ss, t),  __fmul_rn(cc, z[i2][l - 2 + jj]));
                    }
                }
                d[l - 1] = __fadd_rn(d[l - 1], -p);
                e[l - 1] = g;
            }
        } else {
            // ---- QR iteration (lend < l) ----
            for (;;) {
                int mm_;
                for (mm_ = l; mm_ >= lend + 1; mm_--) {
                    float tst = __fmul_rn(e[mm_ - 2], e[mm_ - 2]);
                    if (tst <= __fadd_rn(__fmul_rn(__fmul_rn(eps2, fabsf(d[mm_ - 1])),
                                                   fabsf(d[mm_ - 2])), safmin))
                        break;
                }
                int m2 = mm_;                        // == lend if no break
                if (m2 > lend) e[m2 - 2] = 0.0f;
                float p = d[l - 1];
                if (m2 == l) {
                    d[l - 1] = p;
                    l--;
                    if (l >= lend) continue;
                    break;
                }
                if (m2 == l - 1) {
                    float rt1, rt2, cc, ss;
                    slaev2f(d[l - 2], e[l - 2], d[l - 1], &rt1, &rt2, &cc, &ss);
                    for (int i2 = 0; i2 < 3; i2++) { // slasr 'R','V','F', 2 cols
                        float t = z[i2][l - 1];
                        z[i2][l - 1] = __fadd_rn(__fmul_rn(cc, t), -__fmul_rn(ss, z[i2][l - 2]));
                        z[i2][l - 2] = __fadd_rn(__fmul_rn(ss, t),  __fmul_rn(cc, z[i2][l - 2]));
                    }
                    d[l - 2] = rt1; d[l - 1] = rt2; e[l - 2] = 0.0f;
                    l -= 2;
                    if (l >= lend) continue;
                    break;
                }
                if (jtot == nmaxit) break;
                jtot++;
                float g = f_div(__fadd_rn(d[l - 2], -p), __fmul_rn(2.0f, e[l - 2]));
                float r = slapy2f(g, 1.0f);
                g = __fadd_rn(__fadd_rn(d[m2 - 1], -p),
                              f_div(e[l - 2], __fadd_rn(g, f_sign(r, g))));
                float s = 1.0f, c = 1.0f;
                p = 0.0f;
                float csv[2], snv[2];
                for (int i2 = m2; i2 <= l - 1; i2++) {
                    float fv = __fmul_rn(s, e[i2 - 1]);
                    float bv = __fmul_rn(c, e[i2 - 1]);
                    slartgf(g, fv, &c, &s, &r);
                    if (i2 != m2) e[i2 - 2] = r;
                    g = __fadd_rn(d[i2 - 1], -p);
                    r = __fadd_rn(__fmul_rn(__fadd_rn(d[i2], -g), s),
                                  __fmul_rn(__fmul_rn(2.0f, c), bv));
                    p = __fmul_rn(s, r);
                    d[i2 - 1] = __fadd_rn(g, p);
                    g = __fadd_rn(__fmul_rn(c, r), -bv);
                    csv[i2 - m2] = c; snv[i2 - m2] = s;
                }
                int cnt = l - m2 + 1;               // slasr 'R','V','F'
                for (int jj = 1; jj <= cnt - 1; jj++) {
                    float cc = csv[jj - 1], ss = snv[jj - 1];
                    for (int i2 = 0; i2 < 3; i2++) {
                        float t = z[i2][m2 - 1 + jj];
                        z[i2][m2 - 1 + jj] = __fadd_rn(__fmul_rn(cc, t), -__fmul_rn(ss, z[i2][m2 - 2 + jj]));
                        z[i2][m2 - 2 + jj] = __fadd_rn(__fmul_rn(ss, t),  __fmul_rn(cc, z[i2][m2 - 2 + jj]));
                    }
                }
                d[l - 1] = __fadd_rn(d[l - 1], -p);
                e[l - 2] = g;
            }
        }
    }

    // Sort eigenvalues ascending, swapping columns (no sign change).
    for (int ii = 2; ii <= n; ii++) {
        int i = ii - 1, k = i;
        float p = d[i - 1];
        for (int jj = ii; jj <= n; jj++)
            if (d[jj - 1] < p) { k = jj; p = d[jj - 1]; }
        if (k != i) {
            d[k - 1] = d[i - 1]; d[i - 1] = p;
            for (int r_ = 0; r_ < 3; r_++) {
                float t = z[r_][i - 1]; z[r_][i - 1] = z[r_][k - 1]; z[r_][k - 1] = t;
            }
        }
    }
}

// One thread per point: covariance of K neighbors, then LAPACK-faithful
// smallest-eigenvalue eigenvector (ssytrd + ssteqr + Householder apply).
__global__ void normals_kernel(const float* __restrict__ pos, int N) {
    int i = blockIdx.x * blockDim.x + threadIdx.x;
    if (i >= N) return;

    float px[KNB], py[KNB], pz[KNB];
    float mx = 0.f, my = 0.f, mz = 0.f;
    #pragma unroll
    for (int t = 0; t < KNB; t++) {
        int j = g_nbr[i * KNB + t];
        px[t] = pos[j * 3 + 0];
        py[t] = pos[j * 3 + 1];
        pz[t] = pos[j * 3 + 2];
        mx += px[t]; my += py[t]; mz += pz[t];
    }
    const float invK = 1.0f / (float)KNB;
    mx *= invK; my *= invK; mz *= invK;

    float c00 = 0.f, c10 = 0.f, c20 = 0.f, c11 = 0.f, c21 = 0.f, c22 = 0.f;
    #pragma unroll
    for (int t = 0; t < KNB; t++) {
        float dx = px[t] - mx, dy = py[t] - my, dz = pz[t] - mz;
        c00 += dx * dx; c10 += dy * dx; c20 += dz * dx;
        c11 += dy * dy; c21 += dz * dy; c22 += dz * dz;
    }
    c00 *= invK; c10 *= invK; c20 *= invK;
    c11 *= invK; c21 *= invK; c22 *= invK;

    // ---- ssytrd (lower, N=3): one Householder annihilating c20 ----
    float e0, e1, d1c, d2c, tau1, v3;
    if (c20 == 0.0f) {                     // xnorm == 0 -> tau = 0, H = I
        tau1 = 0.0f; v3 = 0.0f;
        e0 = c10; d1c = c11; d2c = c22; e1 = c21;
    } else {
        float alpha = c10;
        float beta  = -f_sign(slapy2f(alpha, fabsf(c20)), alpha);
        tau1 = f_div(__fadd_rn(beta, -alpha), beta);
        v3   = f_div(c20, __fadd_rn(alpha, -beta));
        e0   = beta;
        float x1 = __fmul_rn(tau1, __fadd_rn(c11, __fmul_rn(c21, v3)));
        float x2 = __fmul_rn(tau1, __fadd_rn(c21, __fmul_rn(c22, v3)));
        float al = __fmul_rn(__fmul_rn(-0.5f, tau1),
                             __fadd_rn(x1, __fmul_rn(x2, v3)));
        float w1 = __fadd_rn(x1, al);
        float w2 = __fadd_rn(x2, __fmul_rn(al, v3));
        d1c = __fadd_rn(c11, -__fmul_rn(2.0f, w1));
        e1  = __fadd_rn(c21, -__fadd_rn(__fmul_rn(v3, w1), w2));
        d2c = __fadd_rn(c22, -__fmul_rn(__fmul_rn(2.0f, v3), w2));
    }

    float d[3] = { c00, d1c, d2c };
    float e[2] = { e0, e1 };
    float z[3][3] = { {1.f, 0.f, 0.f}, {0.f, 1.f, 0.f}, {0.f, 0.f, 1.f} };
    ssteqr3(d, e, z);

    // ---- sormtr: v_full = Q * z[:,0], Q = I - tau*u*u', u = (0,1,v3) ----
    float z1 = z[1][0], z2 = z[2][0];
    float q11 = 1.0f - tau1;
    float q12 = -__fmul_rn(tau1, v3);
    float q22 = 1.0f - __fmul_rn(tau1, __fmul_rn(v3, v3));
    float vx = z[0][0];
    float vy = __fadd_rn(__fmul_rn(q11, z1), __fmul_rn(q12, z2));
    float vz = __fadd_rn(__fmul_rn(q12, z1), __fmul_rn(q22, z2));

    float nn = fmaxf(f_sqrt(vx * vx + vy * vy + vz * vz), 1e-12f);
    g_norm[i * 3 + 0] = f_div(vx, nn);
    g_norm[i * 3 + 1] = f_div(vy, nn);
    g_norm[i * 3 + 2] = f_div(vz, nn);
}

// ---------------------------------------------------------------------------
// Warp per point: 16 edges; fd2 via warp reduce; scalar terms per-lane.
__global__ void edge_kernel(const float* __restrict__ rgb,
                            const int* __restrict__ target, int N) {
    int warp = (blockIdx.x * blockDim.x + threadIdx.x) >> 5;
    int lane = threadIdx.x & 31;
    if (warp >= N) return;
    int i = warp;

    float f0 = g_featn[i * 64 + lane];
    float f1 = g_featn[i * 64 + 32 + lane];
    int   ti = target[i];
    float nix = g_norm[i * 3 + 0], niy = g_norm[i * 3 + 1], niz = g_norm[i * 3 + 2];
    float rix = rgb[i * 3 + 0],    riy = rgb[i * 3 + 1],    riz = rgb[i * 3 + 2];

    float acc = 0.0f;
    #pragma unroll
    for (int t = 0; t < KNB; t++) {
        int j = g_nbr[i * KNB + t];
        float d0 = f0 - g_featn[j * 64 + lane];
        float d1 = f1 - g_featn[j * 64 + 32 + lane];
        float s  = d0 * d0 + d1 * d1;
        #pragma unroll
        for (int o = 16; o; o >>= 1) s += __shfl_xor_sync(FULLM, s, o);

        bool gate = (target[j] == ti);
        float dx = nix - g_norm[j * 3 + 0];
        float dy = niy - g_norm[j * 3 + 1];
        float dz = niz - g_norm[j * 3 + 2];
        float nd2 = dx * dx + dy * dy + dz * dz;
        float geo = expf(-nd2 * 50.0f);          // exp(-nd2 / (2*0.1^2))

        float cx = rix - rgb[j * 3 + 0];
        float cy = riy - rgb[j * 3 + 1];
        float cz = riz - rgb[j * 3 + 2];
        float rd2 = cx * cx + cy * cy + cz * cz;
        float inv = tanhf(5.0f * rd2);

        if (gate) acc += geo * inv * s;
    }
    if (lane == 0) atomicAdd(&g_acc, (double)acc);
}

// ---------------------------------------------------------------------------
__global__ void finalize_kernel(float* out, int N) {
    out[0] = (float)(g_acc / (double)((long long)N * KNB));
}

// ---------------------------------------------------------------------------
extern "C" void kernel_launch(void* const* d_in, const int* in_sizes, int n_in,
                              void* d_out, int out_size) {
    const float* features = (const float*)d_in[0];
    const float* pos      = (const float*)d_in[1];
    const float* rgb      = (const float*)d_in[2];
    const int*   target   = (const int*)d_in[3];
    // d_in[4] = batch (sorted equal segments; implied by N/NSEG)

    int N = in_sizes[3];
    if (N > MAXN) N = MAXN;
    int M = N / NSEG;
    int Mpad = (M + 31) & ~31;

    zero_acc_kernel<<<1, 1>>>();

    int warpBlocks = (N + 3) / 4;                 // 4 warps (128 thr) per block
    featnorm_kernel<<<warpBlocks, 128>>>(features, N);

    int bps = (M + QPB - 1) / QPB;                // blocks per segment
    size_t smem = (size_t)Mpad * sizeof(float4);  // ~80 KB for M=5000
    cudaFuncSetAttribute(knn_kernel,
                         cudaFuncAttributeMaxDynamicSharedMemorySize,
                         (int)smem);
    knn_kernel<<<NSEG * bps, QPB * 32, smem>>>(pos, M, Mpad, bps);

    normals_kernel<<<(N + 127) / 128, 128>>>(pos, N);

    edge_kernel<<<warpBlocks, 128>>>(rgb, target, N);

    finalize_kernel<<<1, 1>>>((float*)d_out, N);
}

// round 14
// speedup vs baseline: 1.9864x; 1.2043x over previous
#include <cuda_runtime.h>
#include <math.h>

// Problem constants: K=16 neighbors, B=4 segments, sigma_g=0.1 -> exp(-nd2*50),
// lambda_tex=5, weight=1, D=64 features.
#define KNB   16
#define KP1   17
#define NSEG  4
#define MAXN  20480
#define QPB   16            // queries per block = warps per block (512 threads)
#define CAP   256           // per-warp capture buffer entries
#define FULLM 0xffffffffu

// Scratch (static __device__ — no allocation allowed)
__device__ float  g_featn[MAXN * 64];   // normalized features
__device__ int    g_nbr[MAXN * KNB];    // global neighbor indices
__device__ float  g_norm[MAXN * 3];     // unit normals (LAPACK-sign-faithful)
__device__ double g_acc;                // loss accumulator

// ---------------------------------------------------------------------------
__global__ void zero_acc_kernel() { g_acc = 0.0; }

// ---------------------------------------------------------------------------
// Warp per row: L2-normalize 64-d features. lane holds elems {lane, lane+32}.
__global__ void featnorm_kernel(const float* __restrict__ f, int N) {
    int warp = (blockIdx.x * blockDim.x + threadIdx.x) >> 5;
    int lane = threadIdx.x & 31;
    if (warp >= N) return;
    float a = f[warp * 64 + lane];
    float b = f[warp * 64 + 32 + lane];
    float s = a * a + b * b;
    #pragma unroll
    for (int o = 16; o; o >>= 1) s += __shfl_xor_sync(FULLM, s, o);
    float n = fmaxf(__fsqrt_rn(s), 1e-12f);
    g_featn[warp * 64 + lane]      = __fdiv_rn(a, n);
    g_featn[warp * 64 + 32 + lane] = __fdiv_rn(b, n);
}

// ---------------------------------------------------------------------------
// Warp-per-query KNN: single main scan with capture buffer + tiny filter pass.
//
// SPEC FACTS (R3..R12, all bench-validated):
//  * Count check makes selection SELF-CERTIFYING: any thr with
//    #{d2 <= thr} == 17 forces the exact 17-smallest set; other counts ->
//    exact R5 fallback chain.
//  * Key-only max-evict is multiset-safe; thr is selection-algorithm-indep.
//  * Emission in ascending index order reproduces rel_err 2.621058e-07.
//  * CAPTURE INVARIANT: curmax is non-increasing and ends at thr, so every
//    final-set member has d2 <= curmax at its scan time -> capturing with the
//    NON-STRICT test guarantees final set ⊆ captured ids (appended in
//    ascending index order). Filtering the buffer by d2 <= thr + count check
//    is therefore exact; overflow (cnt > CAP) falls back to a full scan.
__device__ __forceinline__ float cand_d2(float4 Q, float4 P) {
    float dot = __fadd_rn(__fadd_rn(__fmul_rn(Q.x, P.x),
                                    __fmul_rn(Q.y, P.y)),
                          __fmul_rn(Q.z, P.z));
    return __fadd_rn(__fadd_rn(Q.w, P.w), __fmul_rn(-2.0f, dot));
}

__global__ void __launch_bounds__(QPB * 32, 2)
knn_kernel(const float* __restrict__ pos, int M, int Mpad, int bps) {
    extern __shared__ float4 sp[];
    int* capbuf = (int*)(sp + Mpad);    // QPB * CAP ints
    int seg  = blockIdx.x / bps;
    int lb   = blockIdx.x % bps;
    int base = seg * M;
    const float INF = __int_as_float(0x7f800000);

    for (int t = threadIdx.x; t < Mpad; t += blockDim.x) {
        if (t < M) {
            float x = pos[(base + t) * 3 + 0];
            float y = pos[(base + t) * 3 + 1];
            float z = pos[(base + t) * 3 + 2];
            float sq = __fadd_rn(__fadd_rn(__fmul_rn(x, x), __fmul_rn(y, y)),
                                 __fmul_rn(z, z));
            sp[t] = make_float4(x, y, z, sq);
        } else {
            sp[t] = make_float4(0.0f, 0.0f, 0.0f, INF);  // d2=+inf: never captured
        }
    }
    __syncthreads();

    int warp = threadIdx.x >> 5;
    int lane = threadIdx.x & 31;
    int q = lb * QPB + warp;
    if (q >= M) return;                 // uniform per warp

    float4 Q = sp[q];
    int* mybuf = capbuf + warp * CAP;

    // ---- Main scan: distributed key-only top-17 + capture (2 cand/lane) ----
    float kkey   = 3.4e38f;             // lane t (t<=16): one unsorted slot
    float curmax = 3.4e38f;             // uniform: max over slots 0..16
    int   cnt    = 0;                   // captures (uniform)

    #define PROC(MASK, D2VAR, JBASE)                                        \
        while (MASK) {                                                      \
            int src = __ffs(MASK) - 1;                                      \
            MASK &= MASK - 1;                                               \
            float kd = __shfl_sync(FULLM, D2VAR, src);                      \
            if (kd <= curmax) {         /* uniform recheck, non-strict */   \
                int ki = (JBASE) + src;                                     \
                if (cnt < CAP) { if (lane == 0) mybuf[cnt] = ki; }          \
                cnt++;                                                      \
                if (kd < curmax) {      /* strict: structure update */      \
                    unsigned mx = __ballot_sync(FULLM,                      \
                                      (lane < KP1) && (kkey == curmax));    \
                    if (lane == __ffs(mx) - 1) kkey = kd;                   \
                    float rk = (lane < KP1) ? kkey : -INF;                  \
                    _Pragma("unroll")                                       \
                    for (int o = 16; o; o >>= 1)                            \
                        rk = fmaxf(rk, __shfl_xor_sync(FULLM, rk, o));      \
                    curmax = rk;                                            \
                }                                                           \
            }                                                               \
        }

    for (int j0 = 0; j0 < Mpad; j0 += 64) {
        float d2a = cand_d2(Q, sp[j0 + lane]);
        float d2b = cand_d2(Q, sp[j0 + 32 + lane]);
        // a-batch fully before b-batch: preserves ascending index order.
        unsigned ma = __ballot_sync(FULLM, d2a <= curmax);
        PROC(ma, d2a, j0);
        unsigned mb = __ballot_sync(FULLM, d2b <= curmax);
        PROC(mb, d2b, j0 + 32);
    }
    #undef PROC
    float thr = curmax;
    __syncwarp();                       // lane-0 capture writes -> all lanes

    // ---- Filter pass: emit captured ids with d2 <= thr, index order ----
    int outp = (base + q) * KNB;
    int w = 0;                          // non-self emitted (uniform)
    if (cnt <= CAP) {
        for (int b0 = 0; b0 < cnt; b0 += 32) {
            int idx = b0 + lane;
            bool valid = (idx < cnt);
            int id = valid ? mybuf[idx] : 0;
            float d2 = valid ? cand_d2(Q, sp[id]) : INF;
            bool emit = valid && (d2 <= thr) && (id != q);
            unsigned em = __ballot_sync(FULLM, emit);
            int pos = w + __popc(em & ((1u << lane) - 1u));
            if (emit && pos < KNB)
                g_nbr[outp + pos] = base + id;
            w += __popc(em);
        }
    } else {
        // Overflow (adversarial only): full threshold scan, index order.
        for (int j0 = 0; j0 < Mpad; j0 += 32) {
            int j = j0 + lane;
            float d2 = cand_d2(Q, sp[j]);
            bool emit = (d2 <= thr) && (j != q);
            unsigned em = __ballot_sync(FULLM, emit);
            int pos = w + __popc(em & ((1u << lane) - 1u));
            if (emit && pos < KNB)
                g_nbr[outp + pos] = base + j;
            w += __popc(em);
        }
    }

    // ---- Rare exact fallback: count != 17 -> verbatim R5 id-chain ----
    if (w + 1 != KP1) {
        float fk[KP1];
        int   fi[KP1];
        #pragma unroll
        for (int t = 0; t < KP1; t++) { fk[t] = 3.4e38f; fi[t] = -1; }
        for (int j0 = 0; j0 < Mpad; j0 += 32) {
            float d2 = cand_d2(Q, sp[j0 + lane]);
            unsigned m = __ballot_sync(FULLM, d2 < fk[KP1 - 1]);
            while (m) {
                int src = __ffs(m) - 1;
                m &= m - 1;
                float kd = __shfl_sync(FULLM, d2, src);
                int   ki = j0 + src;
                if (kd < fk[KP1 - 1]) {
                    #pragma unroll
                    for (int t = 0; t < KP1; t++) {
                        if (kd < fk[t]) {
                            float tk = fk[t]; fk[t] = kd; kd = tk;
                            int   ti = fi[t]; fi[t] = ki; ki = ti;
                        }
                    }
                }
            }
        }
        if (lane == 0) {
            int w2 = 0;
            #pragma unroll
            for (int t = 0; t < KP1; t++) {
                if (fi[t] != q && w2 < KNB) {
                    g_nbr[outp + w2] = base + fi[t]; w2++;
                }
            }
        }
    }
}

// ===========================================================================
// Faithful fp32 port of the LAPACK ssyevd(N=3, jobz='V', uplo='L') path:
// ssytrd (slarfg Householder) -> ssteqr('I') -> sormtr. All math in
// round-to-nearest intrinsics so fast-math flags cannot change decisions.
// ===========================================================================
__device__ __forceinline__ float f_div(float a, float b) { return __fdiv_rn(a, b); }
__device__ __forceinline__ float f_sqrt(float a)         { return __fsqrt_rn(a); }
// Fortran SIGN(a,b): |a| if b >= 0 (incl. -0.0 since -0>=0 in C), else -|a|.
__device__ __forceinline__ float f_sign(float a, float b) {
    float aa = fabsf(a);
    return (b >= 0.0f) ? aa : -aa;
}

__device__ float slapy2f(float x, float y) {
    float xa = fabsf(x), ya = fabsf(y);
    float w = fmaxf(xa, ya), zm = fminf(xa, ya);
    if (zm == 0.0f) return w;
    float q = f_div(zm, w);
    return __fmul_rn(w, f_sqrt(__fadd_rn(1.0f, __fmul_rn(q, q))));
}

// LAPACK >= 3.10 slartg (unscaled branch; our magnitudes are mid-range).
__device__ void slartgf(float f, float g, float* c, float* s, float* r) {
    if (g == 0.0f)      { *c = 1.0f; *s = 0.0f; *r = f; }
    else if (f == 0.0f) { *c = 0.0f; *s = f_sign(1.0f, g); *r = fabsf(g); }
    else {
        float d = f_sqrt(__fadd_rn(__fmul_rn(f, f), __fmul_rn(g, g)));
        *c = f_div(fabsf(f), d);
        *r = f_sign(d, f);
        *s = f_div(g, *r);
    }
}

__device__ void slaev2f(float a, float b, float c_, float* rt1, float* rt2,
                        float* cs1, float* sn1) {
    float sm  = __fadd_rn(a, c_);
    float df  = __fadd_rn(a, -c_);
    float adf = fabsf(df);
    float tb  = __fadd_rn(b, b);
    float ab  = fabsf(tb);
    float acmx, acmn;
    if (fabsf(a) > fabsf(c_)) { acmx = a; acmn = c_; }
    else                      { acmx = c_; acmn = a; }
    float rt;
    if (adf > ab) {
        float q = f_div(ab, adf);
        rt = __fmul_rn(adf, f_sqrt(__fadd_rn(1.0f, __fmul_rn(q, q))));
    } else if (adf < ab) {
        float q = f_div(adf, ab);
        rt = __fmul_rn(ab, f_sqrt(__fadd_rn(1.0f, __fmul_rn(q, q))));
    } else {
        rt = __fmul_rn(ab, f_sqrt(2.0f));
    }
    int sgn1;
    if (sm < 0.0f) {
        *rt1 = __fmul_rn(0.5f, __fadd_rn(sm, -rt)); sgn1 = -1;
        *rt2 = __fadd_rn(__fmul_rn(f_div(acmx, *rt1), acmn),
                         -__fmul_rn(f_div(b, *rt1), b));
    } else if (sm > 0.0f) {
        *rt1 = __fmul_rn(0.5f, __fadd_rn(sm, rt)); sgn1 = 1;
        *rt2 = __fadd_rn(__fmul_rn(f_div(acmx, *rt1), acmn),
                         -__fmul_rn(f_div(b, *rt1), b));
    } else {
        *rt1 = __fmul_rn(0.5f, rt); *rt2 = __fmul_rn(-0.5f, rt); sgn1 = 1;
    }
    float cs; int sgn2;
    if (df >= 0.0f) { cs = __fadd_rn(df, rt);  sgn2 = 1;  }
    else            { cs = __fadd_rn(df, -rt); sgn2 = -1; }
    float acs = fabsf(cs);
    float c1, s1;
    if (acs > ab) {
        float ct = f_div(-tb, cs);
        s1 = f_div(1.0f, f_sqrt(__fadd_rn(1.0f, __fmul_rn(ct, ct))));
        c1 = __fmul_rn(ct, s1);
    } else {
        if (ab == 0.0f) { c1 = 1.0f; s1 = 0.0f; }
        else {
            float tn = f_div(-cs, tb);
            c1 = f_div(1.0f, f_sqrt(__fadd_rn(1.0f, __fmul_rn(tn, tn))));
            s1 = __fmul_rn(tn, c1);
        }
    }
    if (sgn1 == sgn2) { float tn = c1; c1 = -s1; s1 = tn; }
    *cs1 = c1; *sn1 = s1;
}

// ssteqr('I', n=3): d[3], e[2], z = identity on entry; eigenvectors of the
// tridiagonal in z columns, ascending eigenvalues, LAPACK sign conventions.
__device__ void ssteqr3(float* d, float* e, float z[3][3]) {
    const float eps    = 5.9604645e-08f;   // slamch('E') fp32 = 2^-24
    const float eps2   = eps * eps;
    const float safmin = 1.1754944e-38f;
    const int   n = 3;
    const int   nmaxit = n * 30;
    int jtot = 0;
    int l1 = 1;                            // 1-based throughout

    for (int guard = 0; guard < 64; guard++) {
        if (l1 > n) break;
        if (l1 > 1) e[l1 - 2] = 0.0f;
        int m;
        for (m = l1; m <= n - 1; m++) {
            float tst = fabsf(e[m - 1]);
            if (tst == 0.0f) break;
            if (tst <= __fmul_rn(__fmul_rn(f_sqrt(fabsf(d[m - 1])),
                                           f_sqrt(fabsf(d[m]))), eps)) {
                e[m - 1] = 0.0f;
                break;
            }
        }
        int l = l1, lsv = l, lend = m, lendsv = lend;
        l1 = m + 1;
        if (lend == l) continue;

        if (fabsf(d[lend - 1]) < fabsf(d[l - 1])) { lend = lsv; l = lendsv; }

        if (lend > l) {
            // ---- QL iteration ----
            for (;;) {
                int mm_;
                for (mm_ = l; mm_ <= lend - 1; mm_++) {
                    float tst = __fmul_rn(e[mm_ - 1], e[mm_ - 1]);
                    if (tst <= __fadd_rn(__fmul_rn(__fmul_rn(eps2, fabsf(d[mm_ - 1])),
                                                   fabsf(d[mm_])), safmin))
                        break;
                }
                int m2 = mm_;                        // == lend if no break
                if (m2 < lend) e[m2 - 1] = 0.0f;
                float p = d[l - 1];
                if (m2 == l) {                       // eigenvalue found
                    d[l - 1] = p;
                    l++;
                    if (l <= lend) continue;
                    break;
                }
                if (m2 == l + 1) {                   // 2x2: slaev2
                    float rt1, rt2, cc, ss;
                    slaev2f(d[l - 1], e[l - 1], d[l], &rt1, &rt2, &cc, &ss);
                    for (int i2 = 0; i2 < 3; i2++) { // slasr 'R','V','B', 2 cols
                        float t = z[i2][l];
                        z[i2][l]     = __fadd_rn(__fmul_rn(cc, t), -__fmul_rn(ss, z[i2][l - 1]));
                        z[i2][l - 1] = __fadd_rn(__fmul_rn(ss, t),  __fmul_rn(cc, z[i2][l - 1]));
                    }
                    d[l - 1] = rt1; d[l] = rt2; e[l - 1] = 0.0f;
                    l += 2;
                    if (l <= lend) continue;
                    break;
                }
                if (jtot == nmaxit) break;
                jtot++;
                float g = f_div(__fadd_rn(d[l], -p), __fmul_rn(2.0f, e[l - 1]));
                float r = slapy2f(g, 1.0f);
                g = __fadd_rn(__fadd_rn(d[m2 - 1], -p),
                              f_div(e[l - 1], __fadd_rn(g, f_sign(r, g))));
                float s = 1.0f, c = 1.0f;
                p = 0.0f;
                float csv[2], snv[2];
                for (int i2 = m2 - 1; i2 >= l; i2--) {
                    float fv = __fmul_rn(s, e[i2 - 1]);
                    float bv = __fmul_rn(c, e[i2 - 1]);
                    slartgf(g, fv, &c, &s, &r);
                    if (i2 != m2 - 1) e[i2] = r;
                    g = __fadd_rn(d[i2], -p);
                    r = __fadd_rn(__fmul_rn(__fadd_rn(d[i2 - 1], -g), s),
                                  __fmul_rn(__fmul_rn(2.0f, c), bv));
                    p = __fmul_rn(s, r);
                    d[i2] = __fadd_rn(g, p);
                    g = __fadd_rn(__fmul_rn(c, r), -bv);
                    csv[i2 - l] = c; snv[i2 - l] = -s;
                }
                int cnt = m2 - l + 1;               // slasr 'R','V','B'
                for (int jj = cnt - 1; jj >= 1; jj--) {
                    float cc = csv[jj - 1], ss = snv[jj - 1];
                    for (int i2 = 0; i2 < 3; i2++) {
                        float t = z[i2][l - 1 + jj];
                        z[i2][l - 1 + jj]     = __fadd_rn(__fmul_rn(cc, t), -__fmul_rn(ss, z[i2][l - 2 + jj]));
                        z[i2][l - 2 + jj]     = __fadd_rn(__fmul_rn(ss, t),  __fmul_rn(cc, z[i2][l - 2 + jj]));
                    }
                }
                d[l - 1] = __fadd_rn(d[l - 1], -p);
                e[l - 1] = g;
            }
        } else {
            // ---- QR iteration (lend < l) ----
            for (;;) {
                int mm_;
                for (mm_ = l; mm_ >= lend + 1; mm_--) {
                    float tst = __fmul_rn(e[mm_ - 2], e[mm_ - 2]);
                    if (tst <= __fadd_rn(__fmul_rn(__fmul_rn(eps2, fabsf(d[mm_ - 1])),
                                                   fabsf(d[mm_ - 2])), safmin))
                        break;
                }
                int m2 = mm_;                        // == lend if no break
                if (m2 > lend) e[m2 - 2] = 0.0f;
                float p = d[l - 1];
                if (m2 == l) {
                    d[l - 1] = p;
                    l--;
                    if (l >= lend) continue;
                    break;
                }
                if (m2 == l - 1) {
                    float rt1, rt2, cc, ss;
                    slaev2f(d[l - 2], e[l - 2], d[l - 1], &rt1, &rt2, &cc, &ss);
                    for (int i2 = 0; i2 < 3; i2++) { // slasr 'R','V','F', 2 cols
                        float t = z[i2][l - 1];
                        z[i2][l - 1] = __fadd_rn(__fmul_rn(cc, t), -__fmul_rn(ss, z[i2][l - 2]));
                        z[i2][l - 2] = __fadd_rn(__fmul_rn(ss, t),  __fmul_rn(cc, z[i2][l - 2]));
                    }
                    d[l - 2] = rt1; d[l - 1] = rt2; e[l - 2] = 0.0f;
                    l -= 2;
                    if (l >= lend) continue;
                    break;
                }
                if (jtot == nmaxit) break;
                jtot++;
                float g = f_div(__fadd_rn(d[l - 2], -p), __fmul_rn(2.0f, e[l - 2]));
                float r = slapy2f(g, 1.0f);
                g = __fadd_rn(__fadd_rn(d[m2 - 1], -p),
                              f_div(e[l - 2], __fadd_rn(g, f_sign(r, g))));
                float s = 1.0f, c = 1.0f;
                p = 0.0f;
                float csv[2], snv[2];
                for (int i2 = m2; i2 <= l - 1; i2++) {
                    float fv = __fmul_rn(s, e[i2 - 1]);
                    float bv = __fmul_rn(c, e[i2 - 1]);
                    slartgf(g, fv, &c, &s, &r);
                    if (i2 != m2) e[i2 - 2] = r;
                    g = __fadd_rn(d[i2 - 1], -p);
                    r = __fadd_rn(__fmul_rn(__fadd_rn(d[i2], -g), s),
                                  __fmul_rn(__fmul_rn(2.0f, c), bv));
                    p = __fmul_rn(s, r);
                    d[i2 - 1] = __fadd_rn(g, p);
                    g = __fadd_rn(__fmul_rn(c, r), -bv);
                    csv[i2 - m2] = c; snv[i2 - m2] = s;
                }
                int cnt = l - m2 + 1;               // slasr 'R','V','F'
                for (int jj = 1; jj <= cnt - 1; jj++) {
                    float cc = csv[jj - 1], ss = snv[jj - 1];
                    for (int i2 = 0; i2 < 3; i2++) {
                        float t = z[i2][m2 - 1 + jj];
                        z[i2][m2 - 1 + jj] = __fadd_rn(__fmul_rn(cc, t), -__fmul_rn(ss, z[i2][m2 - 2 + jj]));
                        z[i2][m2 - 2 + jj] = __fadd_rn(__fmul_rn(ss, t),  __fmul_rn(cc, z[i2][m2 - 2 + jj]));
                    }
                }
                d[l - 1] = __fadd_rn(d[l - 1], -p);
                e[l - 2] = g;
            }
        }
    }

    // Sort eigenvalues ascending, swapping columns (no sign change).
    for (int ii = 2; ii <= n; ii++) {
        int i = ii - 1, k = i;
        float p = d[i - 1];
        for (int jj = ii; jj <= n; jj++)
            if (d[jj - 1] < p) { k = jj; p = d[jj - 1]; }
        if (k != i) {
            d[k - 1] = d[i - 1]; d[i - 1] = p;
            for (int r_ = 0; r_ < 3; r_++) {
                float t = z[r_][i - 1]; z[r_][i - 1] = z[r_][k - 1]; z[r_][k - 1] = t;
            }
        }
    }
}

// One thread per point: covariance of K neighbors, then LAPACK-faithful
// smallest-eigenvalue eigenvector (ssytrd + ssteqr + Householder apply).
__global__ void normals_kernel(const float* __restrict__ pos, int N) {
    int i = blockIdx.x * blockDim.x + threadIdx.x;
    if (i >= N) return;

    float px[KNB], py[KNB], pz[KNB];
    float mx = 0.f, my = 0.f, mz = 0.f;
    #pragma unroll
    for (int t = 0; t < KNB; t++) {
        int j = g_nbr[i * KNB + t];
        px[t] = pos[j * 3 + 0];
        py[t] = pos[j * 3 + 1];
        pz[t] = pos[j * 3 + 2];
        mx += px[t]; my += py[t]; mz += pz[t];
    }
    const float invK = 1.0f / (float)KNB;
    mx *= invK; my *= invK; mz *= invK;

    float c00 = 0.f, c10 = 0.f, c20 = 0.f, c11 = 0.f, c21 = 0.f, c22 = 0.f;
    #pragma unroll
    for (int t = 0; t < KNB; t++) {
        float dx = px[t] - mx, dy = py[t] - my, dz = pz[t] - mz;
        c00 += dx * dx; c10 += dy * dx; c20 += dz * dx;
        c11 += dy * dy; c21 += dz * dy; c22 += dz * dz;
    }
    c00 *= invK; c10 *= invK; c20 *= invK;
    c11 *= invK; c21 *= invK; c22 *= invK;

    // ---- ssytrd (lower, N=3): one Householder annihilating c20 ----
    float e0, e1, d1c, d2c, tau1, v3;
    if (c20 == 0.0f) {                     // xnorm == 0 -> tau = 0, H = I
        tau1 = 0.0f; v3 = 0.0f;
        e0 = c10; d1c = c11; d2c = c22; e1 = c21;
    } else {
        float alpha = c10;
        float beta  = -f_sign(slapy2f(alpha, fabsf(c20)), alpha);
        tau1 = f_div(__fadd_rn(beta, -alpha), beta);
        v3   = f_div(c20, __fadd_rn(alpha, -beta));
        e0   = beta;
        float x1 = __fmul_rn(tau1, __fadd_rn(c11, __fmul_rn(c21, v3)));
        float x2 = __fmul_rn(tau1, __fadd_rn(c21, __fmul_rn(c22, v3)));
        float al = __fmul_rn(__fmul_rn(-0.5f, tau1),
                             __fadd_rn(x1, __fmul_rn(x2, v3)));
        float w1 = __fadd_rn(x1, al);
        float w2 = __fadd_rn(x2, __fmul_rn(al, v3));
        d1c = __fadd_rn(c11, -__fmul_rn(2.0f, w1));
        e1  = __fadd_rn(c21, -__fadd_rn(__fmul_rn(v3, w1), w2));
        d2c = __fadd_rn(c22, -__fmul_rn(__fmul_rn(2.0f, v3), w2));
    }

    float d[3] = { c00, d1c, d2c };
    float e[2] = { e0, e1 };
    float z[3][3] = { {1.f, 0.f, 0.f}, {0.f, 1.f, 0.f}, {0.f, 0.f, 1.f} };
    ssteqr3(d, e, z);

    // ---- sormtr: v_full = Q * z[:,0], Q = I - tau*u*u', u = (0,1,v3) ----
    float z1 = z[1][0], z2 = z[2][0];
    float q11 = 1.0f - tau1;
    float q12 = -__fmul_rn(tau1, v3);
    float q22 = 1.0f - __fmul_rn(tau1, __fmul_rn(v3, v3));
    float vx = z[0][0];
    float vy = __fadd_rn(__fmul_rn(q11, z1), __fmul_rn(q12, z2));
    float vz = __fadd_rn(__fmul_rn(q12, z1), __fmul_rn(q22, z2));

    float nn = fmaxf(f_sqrt(vx * vx + vy * vy + vz * vz), 1e-12f);
    g_norm[i * 3 + 0] = f_div(vx, nn);
    g_norm[i * 3 + 1] = f_div(vy, nn);
    g_norm[i * 3 + 2] = f_div(vz, nn);
}

// ---------------------------------------------------------------------------
// Warp per point: 16 edges; fd2 via warp reduce; scalar terms per-lane.
__global__ void edge_kernel(const float* __restrict__ rgb,
                            const int* __restrict__ target, int N) {
    int warp = (blockIdx.x * blockDim.x + threadIdx.x) >> 5;
    int lane = threadIdx.x & 31;
    if (warp >= N) return;
    int i = warp;

    float f0 = g_featn[i * 64 + lane];
    float f1 = g_featn[i * 64 + 32 + lane];
    int   ti = target[i];
    float nix = g_norm[i * 3 + 0], niy = g_norm[i * 3 + 1], niz = g_norm[i * 3 + 2];
    float rix = rgb[i * 3 + 0],    riy = rgb[i * 3 + 1],    riz = rgb[i * 3 + 2];

    float acc = 0.0f;
    #pragma unroll
    for (int t = 0; t < KNB; t++) {
        int j = g_nbr[i * KNB + t];
        float d0 = f0 - g_featn[j * 64 + lane];
        float d1 = f1 - g_featn[j * 64 + 32 + lane];
        float s  = d0 * d0 + d1 * d1;
        #pragma unroll
        for (int o = 16; o; o >>= 1) s += __shfl_xor_sync(FULLM, s, o);

        bool gate = (target[j] == ti);
        float dx = nix - g_norm[j * 3 + 0];
        float dy = niy - g_norm[j * 3 + 1];
        float dz = niz - g_norm[j * 3 + 2];
        float nd2 = dx * dx + dy * dy + dz * dz;
        float geo = expf(-nd2 * 50.0f);          // exp(-nd2 / (2*0.1^2))

        float cx = rix - rgb[j * 3 + 0];
        float cy = riy - rgb[j * 3 + 1];
        float cz = riz - rgb[j * 3 + 2];
        float rd2 = cx * cx + cy * cy + cz * cz;
        float inv = tanhf(5.0f * rd2);

        if (gate) acc += geo * inv * s;
    }
    if (lane == 0) atomicAdd(&g_acc, (double)acc);
}

// ---------------------------------------------------------------------------
__global__ void finalize_kernel(float* out, int N) {
    out[0] = (float)(g_acc / (double)((long long)N * KNB));
}

// ---------------------------------------------------------------------------
extern "C" void kernel_launch(void* const* d_in, const int* in_sizes, int n_in,
                              void* d_out, int out_size) {
    const float* features = (const float*)d_in[0];
    const float* pos      = (const float*)d_in[1];
    const float* rgb      = (const float*)d_in[2];
    const int*   target   = (const int*)d_in[3];
    // d_in[4] = batch (sorted equal segments; implied by N/NSEG)

    int N = in_sizes[3];
    if (N > MAXN) N = MAXN;
    int M = N / NSEG;
    int Mpad = (M + 63) & ~63;                    // 64-aligned (2 cand/lane)

    zero_acc_kernel<<<1, 1>>>();

    int warpBlocks = (N + 3) / 4;                 // 4 warps (128 thr) per block
    featnorm_kernel<<<warpBlocks, 128>>>(features, N);

    int bps = (M + QPB - 1) / QPB;                // blocks per segment
    size_t smem = (size_t)Mpad * sizeof(float4)   // staged positions
                + (size_t)QPB * CAP * sizeof(int);// capture buffers
    cudaFuncSetAttribute(knn_kernel,
                         cudaFuncAttributeMaxDynamicSharedMemorySize,
                         (int)smem);
    knn_kernel<<<NSEG * bps, QPB * 32, smem>>>(pos, M, Mpad, bps);

    normals_kernel<<<(N + 127) / 128, 128>>>(pos, N);

    edge_kernel<<<warpBlocks, 128>>>(rgb, target, N);

    finalize_kernel<<<1, 1>>>((float*)d_out, N);
}

// round 15
// speedup vs baseline: 2.2429x; 1.1291x over previous
#include <cuda_runtime.h>
#include <math.h>

// Problem constants: K=16 neighbors, B=4 segments, sigma_g=0.1 -> exp(-nd2*50),
// lambda_tex=5, weight=1, D=64 features.
#define KNB   16
#define KP1   17
#define NSEG  4
#define MAXN  20480
#define QPB   16            // queries per block = warps per block (512 threads)
#define CAP   256           // per-warp capture buffer entries
#define FULLM 0xffffffffu

// Scratch (static __device__ — no allocation allowed)
__device__ float  g_featn[MAXN * 64];   // normalized features
__device__ int    g_nbr[MAXN * KNB];    // global neighbor indices
__device__ float  g_norm[MAXN * 3];     // unit normals (LAPACK-sign-faithful)
__device__ double g_acc;                // loss accumulator

// ---------------------------------------------------------------------------
__global__ void zero_acc_kernel() { g_acc = 0.0; }

// ---------------------------------------------------------------------------
// Warp per row: L2-normalize 64-d features. lane holds elems {lane, lane+32}.
__global__ void featnorm_kernel(const float* __restrict__ f, int N) {
    int warp = (blockIdx.x * blockDim.x + threadIdx.x) >> 5;
    int lane = threadIdx.x & 31;
    if (warp >= N) return;
    float a = f[warp * 64 + lane];
    float b = f[warp * 64 + 32 + lane];
    float s = a * a + b * b;
    #pragma unroll
    for (int o = 16; o; o >>= 1) s += __shfl_xor_sync(FULLM, s, o);
    float n = fmaxf(__fsqrt_rn(s), 1e-12f);
    g_featn[warp * 64 + lane]      = __fdiv_rn(a, n);
    g_featn[warp * 64 + 32 + lane] = __fdiv_rn(b, n);
}

// ---------------------------------------------------------------------------
// Warp-per-query KNN: single main scan with capture buffer + tiny filter pass.
//
// SPEC FACTS (R3..R14, all bench-validated):
//  * Count check makes selection SELF-CERTIFYING: any thr with
//    #{d2 <= thr} == 17 forces the exact 17-smallest set; other counts ->
//    exact R5 fallback chain.
//  * Key-only max-evict is multiset-safe; thr is selection-algorithm-indep.
//  * Emission in ascending index order reproduces rel_err 2.621058e-07.
//  * CAPTURE INVARIANT: curmax is non-increasing and ends at thr, so every
//    final-set member has d2 <= curmax at its scan time -> capturing with the
//    NON-STRICT test guarantees final set ⊆ captured ids (appended in
//    ascending index order). Filtering the buffer by d2 <= thr + count check
//    is therefore exact; overflow (cnt > CAP) falls back to a full scan.
//  * R15: max-recompute via redux.sync on the order-preserving unsigned
//    encoding — computes the SAME exact max value as the shfl reduce
//    (bit-identical trajectory), one instruction instead of 5 dependent shfls.
__device__ __forceinline__ float cand_d2(float4 Q, float4 P) {
    float dot = __fadd_rn(__fadd_rn(__fmul_rn(Q.x, P.x),
                                    __fmul_rn(Q.y, P.y)),
                          __fmul_rn(Q.z, P.z));
    return __fadd_rn(__fadd_rn(Q.w, P.w), __fmul_rn(-2.0f, dot));
}

// Order-preserving float <-> unsigned (total order, handles negatives).
__device__ __forceinline__ unsigned f2u(float f) {
    unsigned b = __float_as_uint(f);
    return (b & 0x80000000u) ? ~b : (b | 0x80000000u);
}
__device__ __forceinline__ float u2f(unsigned u) {
    return __uint_as_float((u & 0x80000000u) ? (u ^ 0x80000000u) : ~u);
}

__global__ void __launch_bounds__(QPB * 32, 2)
knn_kernel(const float* __restrict__ pos, int M, int Mpad, int bps) {
    extern __shared__ float4 sp[];
    int* capbuf = (int*)(sp + Mpad);    // QPB * CAP ints
    int seg  = blockIdx.x / bps;
    int lb   = blockIdx.x % bps;
    int base = seg * M;
    const float INF = __int_as_float(0x7f800000);

    for (int t = threadIdx.x; t < Mpad; t += blockDim.x) {
        if (t < M) {
            float x = pos[(base + t) * 3 + 0];
            float y = pos[(base + t) * 3 + 1];
            float z = pos[(base + t) * 3 + 2];
            float sq = __fadd_rn(__fadd_rn(__fmul_rn(x, x), __fmul_rn(y, y)),
                                 __fmul_rn(z, z));
            sp[t] = make_float4(x, y, z, sq);
        } else {
            sp[t] = make_float4(0.0f, 0.0f, 0.0f, INF);  // d2=+inf: never captured
        }
    }
    __syncthreads();

    int warp = threadIdx.x >> 5;
    int lane = threadIdx.x & 31;
    int q = lb * QPB + warp;
    if (q >= M) return;                 // uniform per warp

    float4 Q = sp[q];
    int* mybuf = capbuf + warp * CAP;

    // ---- Main scan: distributed key-only top-17 + capture (2 cand/lane) ----
    float kkey   = 3.4e38f;             // lane t (t<=16): one unsorted slot
    float curmax = 3.4e38f;             // uniform: max over slots 0..16
    int   cnt    = 0;                   // captures (uniform)

    #define PROC(MASK, D2VAR, JBASE)                                        \
        while (MASK) {                                                      \
            int src = __ffs(MASK) - 1;                                      \
            MASK &= MASK - 1;                                               \
            float kd = __shfl_sync(FULLM, D2VAR, src);                      \
            if (kd <= curmax) {         /* uniform recheck, non-strict */   \
                int ki = (JBASE) + src;                                     \
                if (cnt < CAP) { if (lane == 0) mybuf[cnt] = ki; }          \
                cnt++;                                                      \
                if (kd < curmax) {      /* strict: structure update */      \
                    unsigned mx = __ballot_sync(FULLM,                      \
                                      (lane < KP1) && (kkey == curmax));    \
                    if (lane == __ffs(mx) - 1) kkey = kd;                   \
                    unsigned enc = (lane < KP1) ? f2u(kkey) : 0u;           \
                    curmax = u2f(__reduce_max_sync(FULLM, enc));            \
                }                                                           \
            }                                                               \
        }

    for (int j0 = 0; j0 < Mpad; j0 += 64) {
        float d2a = cand_d2(Q, sp[j0 + lane]);
        float d2b = cand_d2(Q, sp[j0 + 32 + lane]);
        // a-batch fully before b-batch: preserves ascending index order.
        unsigned ma = __ballot_sync(FULLM, d2a <= curmax);
        PROC(ma, d2a, j0);
        unsigned mb = __ballot_sync(FULLM, d2b <= curmax);
        PROC(mb, d2b, j0 + 32);
    }
    #undef PROC
    float thr = curmax;
    __syncwarp();                       // lane-0 capture writes -> all lanes

    // ---- Filter pass: emit captured ids with d2 <= thr, index order ----
    int outp = (base + q) * KNB;
    int w = 0;                          // non-self emitted (uniform)
    if (cnt <= CAP) {
        for (int b0 = 0; b0 < cnt; b0 += 32) {
            int idx = b0 + lane;
            bool valid = (idx < cnt);
            int id = valid ? mybuf[idx] : 0;
            float d2 = valid ? cand_d2(Q, sp[id]) : INF;
            bool emit = valid && (d2 <= thr) && (id != q);
            unsigned em = __ballot_sync(FULLM, emit);
            int pos = w + __popc(em & ((1u << lane) - 1u));
            if (emit && pos < KNB)
                g_nbr[outp + pos] = base + id;
            w += __popc(em);
        }
    } else {
        // Overflow (adversarial only): full threshold scan, index order.
        for (int j0 = 0; j0 < Mpad; j0 += 32) {
            int j = j0 + lane;
            float d2 = cand_d2(Q, sp[j]);
            bool emit = (d2 <= thr) && (j != q);
            unsigned em = __ballot_sync(FULLM, emit);
            int pos = w + __popc(em & ((1u << lane) - 1u));
            if (emit && pos < KNB)
                g_nbr[outp + pos] = base + j;
            w += __popc(em);
        }
    }

    // ---- Rare exact fallback: count != 17 -> verbatim R5 id-chain ----
    if (w + 1 != KP1) {
        float fk[KP1];
        int   fi[KP1];
        #pragma unroll
        for (int t = 0; t < KP1; t++) { fk[t] = 3.4e38f; fi[t] = -1; }
        for (int j0 = 0; j0 < Mpad; j0 += 32) {
            float d2 = cand_d2(Q, sp[j0 + lane]);
            unsigned m = __ballot_sync(FULLM, d2 < fk[KP1 - 1]);
            while (m) {
                int src = __ffs(m) - 1;
                m &= m - 1;
                float kd = __shfl_sync(FULLM, d2, src);
                int   ki = j0 + src;
                if (kd < fk[KP1 - 1]) {
                    #pragma unroll
                    for (int t = 0; t < KP1; t++) {
                        if (kd < fk[t]) {
                            float tk = fk[t]; fk[t] = kd; kd = tk;
                            int   ti = fi[t]; fi[t] = ki; ki = ti;
                        }
                    }
                }
            }
        }
        if (lane == 0) {
            int w2 = 0;
            #pragma unroll
            for (int t = 0; t < KP1; t++) {
                if (fi[t] != q && w2 < KNB) {
                    g_nbr[outp + w2] = base + fi[t]; w2++;
                }
            }
        }
    }
}

// ===========================================================================
// Faithful fp32 port of the LAPACK ssyevd(N=3, jobz='V', uplo='L') path:
// ssytrd (slarfg Householder) -> ssteqr('I') -> sormtr. All math in
// round-to-nearest intrinsics so fast-math flags cannot change decisions.
// ===========================================================================
__device__ __forceinline__ float f_div(float a, float b) { return __fdiv_rn(a, b); }
__device__ __forceinline__ float f_sqrt(float a)         { return __fsqrt_rn(a); }
// Fortran SIGN(a,b): |a| if b >= 0 (incl. -0.0 since -0>=0 in C), else -|a|.
__device__ __forceinline__ float f_sign(float a, float b) {
    float aa = fabsf(a);
    return (b >= 0.0f) ? aa : -aa;
}

__device__ float slapy2f(float x, float y) {
    float xa = fabsf(x), ya = fabsf(y);
    float w = fmaxf(xa, ya), zm = fminf(xa, ya);
    if (zm == 0.0f) return w;
    float q = f_div(zm, w);
    return __fmul_rn(w, f_sqrt(__fadd_rn(1.0f, __fmul_rn(q, q))));
}

// LAPACK >= 3.10 slartg (unscaled branch; our magnitudes are mid-range).
__device__ void slartgf(float f, float g, float* c, float* s, float* r) {
    if (g == 0.0f)      { *c = 1.0f; *s = 0.0f; *r = f; }
    else if (f == 0.0f) { *c = 0.0f; *s = f_sign(1.0f, g); *r = fabsf(g); }
    else {
        float d = f_sqrt(__fadd_rn(__fmul_rn(f, f), __fmul_rn(g, g)));
        *c = f_div(fabsf(f), d);
        *r = f_sign(d, f);
        *s = f_div(g, *r);
    }
}

__device__ void slaev2f(float a, float b, float c_, float* rt1, float* rt2,
                        float* cs1, float* sn1) {
    float sm  = __fadd_rn(a, c_);
    float df  = __fadd_rn(a, -c_);
    float adf = fabsf(df);
    float tb  = __fadd_rn(b, b);
    float ab  = fabsf(tb);
    float acmx, acmn;
    if (fabsf(a) > fabsf(c_)) { acmx = a; acmn = c_; }
    else                      { acmx = c_; acmn = a; }
    float rt;
    if (adf > ab) {
        float q = f_div(ab, adf);
        rt = __fmul_rn(adf, f_sqrt(__fadd_rn(1.0f, __fmul_rn(q, q))));
    } else if (adf < ab) {
        float q = f_div(adf, ab);
        rt = __fmul_rn(ab, f_sqrt(__fadd_rn(1.0f, __fmul_rn(q, q))));
    } else {
        rt = __fmul_rn(ab, f_sqrt(2.0f));
    }
    int sgn1;
    if (sm < 0.0f) {
        *rt1 = __fmul_rn(0.5f, __fadd_rn(sm, -rt)); sgn1 = -1;
        *rt2 = __fadd_rn(__fmul_rn(f_div(acmx, *rt1), acmn),
                         -__fmul_rn(f_div(b, *rt1), b));
    } else if (sm > 0.0f) {
        *rt1 = __fmul_rn(0.5f, __fadd_rn(sm, rt)); sgn1 = 1;
        *rt2 = __fadd_rn(__fmul_rn(f_div(acmx, *rt1), acmn),
                         -__fmul_rn(f_div(b, *rt1), b));
    } else {
        *rt1 = __fmul_rn(0.5f, rt); *rt2 = __fmul_rn(-0.5f, rt); sgn1 = 1;
    }
    float cs; int sgn2;
    if (df >= 0.0f) { cs = __fadd_rn(df, rt);  sgn2 = 1;  }
    else            { cs = __fadd_rn(df, -rt); sgn2 = -1; }
    float acs = fabsf(cs);
    float c1, s1;
    if (acs > ab) {
        float ct = f_div(-tb, cs);
        s1 = f_div(1.0f, f_sqrt(__fadd_rn(1.0f, __fmul_rn(ct, ct))));
        c1 = __fmul_rn(ct, s1);
    } else {
        if (ab == 0.0f) { c1 = 1.0f; s1 = 0.0f; }
        else {
            float tn = f_div(-cs, tb);
            c1 = f_div(1.0f, f_sqrt(__fadd_rn(1.0f, __fmul_rn(tn, tn))));
            s1 = __fmul_rn(tn, c1);
        }
    }
    if (sgn1 == sgn2) { float tn = c1; c1 = -s1; s1 = tn; }
    *cs1 = c1; *sn1 = s1;
}

// ssteqr('I', n=3): d[3], e[2], z = identity on entry; eigenvectors of the
// tridiagonal in z columns, ascending eigenvalues, LAPACK sign conventions.
__device__ void ssteqr3(float* d, float* e, float z[3][3]) {
    const float eps    = 5.9604645e-08f;   // slamch('E') fp32 = 2^-24
    const float eps2   = eps * eps;
    const float safmin = 1.1754944e-38f;
    const int   n = 3;
    const int   nmaxit = n * 30;
    int jtot = 0;
    int l1 = 1;                            // 1-based throughout

    for (int guard = 0; guard < 64; guard++) {
        if (l1 > n) break;
        if (l1 > 1) e[l1 - 2] = 0.0f;
        int m;
        for (m = l1; m <= n - 1; m++) {
            float tst = fabsf(e[m - 1]);
            if (tst == 0.0f) break;
            if (tst <= __fmul_rn(__fmul_rn(f_sqrt(fabsf(d[m - 1])),
                                           f_sqrt(fabsf(d[m]))), eps)) {
                e[m - 1] = 0.0f;
                break;
            }
        }
        int l = l1, lsv = l, lend = m, lendsv = lend;
        l1 = m + 1;
        if (lend == l) continue;

        if (fabsf(d[lend - 1]) < fabsf(d[l - 1])) { lend = lsv; l = lendsv; }

        if (lend > l) {
            // ---- QL iteration ----
            for (;;) {
                int mm_;
                for (mm_ = l; mm_ <= lend - 1; mm_++) {
                    float tst = __fmul_rn(e[mm_ - 1], e[mm_ - 1]);
                    if (tst <= __fadd_rn(__fmul_rn(__fmul_rn(eps2, fabsf(d[mm_ - 1])),
                                                   fabsf(d[mm_])), safmin))
                        break;
                }
                int m2 = mm_;                        // == lend if no break
                if (m2 < lend) e[m2 - 1] = 0.0f;
                float p = d[l - 1];
                if (m2 == l) {                       // eigenvalue found
                    d[l - 1] = p;
                    l++;
                    if (l <= lend) continue;
                    break;
                }
                if (m2 == l + 1) {                   // 2x2: slaev2
                    float rt1, rt2, cc, ss;
                    slaev2f(d[l - 1], e[l - 1], d[l], &rt1, &rt2, &cc, &ss);
                    for (int i2 = 0; i2 < 3; i2++) { // slasr 'R','V','B', 2 cols
                        float t = z[i2][l];
                        z[i2][l]     = __fadd_rn(__fmul_rn(cc, t), -__fmul_rn(ss, z[i2][l - 1]));
                        z[i2][l - 1] = __fadd_rn(__fmul_rn(ss, t),  __fmul_rn(cc, z[i2][l - 1]));
                    }
                    d[l - 1] = rt1; d[l] = rt2; e[l - 1] = 0.0f;
                    l += 2;
                    if (l <= lend) continue;
                    break;
                }
                if (jtot == nmaxit) break;
                jtot++;
                float g = f_div(__fadd_rn(d[l], -p), __fmul_rn(2.0f, e[l - 1]));
                float r = slapy2f(g, 1.0f);
                g = __fadd_rn(__fadd_rn(d[m2 - 1], -p),
                              f_div(e[l - 1], __fadd_rn(g, f_sign(r, g))));
                float s = 1.0f, c = 1.0f;
                p = 0.0f;
                float csv[2], snv[2];
                for (int i2 = m2 - 1; i2 >= l; i2--) {
                    float fv = __fmul_rn(s, e[i2 - 1]);
                    float bv = __fmul_rn(c, e[i2 - 1]);
                    slartgf(g, fv, &c, &s, &r);
                    if (i2 != m2 - 1) e[i2] = r;
                    g = __fadd_rn(d[i2], -p);
                    r = __fadd_rn(__fmul_rn(__fadd_rn(d[i2 - 1], -g), s),
                                  __fmul_rn(__fmul_rn(2.0f, c), bv));
                    p = __fmul_rn(s, r);
                    d[i2] = __fadd_rn(g, p);
                    g = __fadd_rn(__fmul_rn(c, r), -bv);
                    csv[i2 - l] = c; snv[i2 - l] = -s;
                }
                int cnt = m2 - l + 1;               // slasr 'R','V','B'
                for (int jj = cnt - 1; jj >= 1; jj--) {
                    float cc = csv[jj - 1], ss = snv[jj - 1];
                    for (int i2 = 0; i2 < 3; i2++) {
                        float t = z[i2][l - 1 + jj];
                        z[i2][l - 1 + jj]     = __fadd_rn(__fmul_rn(cc, t), -__fmul_rn(ss, z[i2][l - 2 + jj]));
                        z[i2][l - 2 + jj]     = __fadd_rn(__fmul_rn(ss, t),  __fmul_rn(cc, z[i2][l - 2 + jj]));
                    }
                }
                d[l - 1] = __fadd_rn(d[l - 1], -p);
                e[l - 1] = g;
            }
        } else {
            // ---- QR iteration (lend < l) ----
            for (;;) {
                int mm_;
                for (mm_ = l; mm_ >= lend + 1; mm_--) {
                    float tst = __fmul_rn(e[mm_ - 2], e[mm_ - 2]);
                    if (tst <= __fadd_rn(__fmul_rn(__fmul_rn(eps2, fabsf(d[mm_ - 1])),
                                                   fabsf(d[mm_ - 2])), safmin))
                        break;
                }
                int m2 = mm_;                        // == lend if no break
                if (m2 > lend) e[m2 - 2] = 0.0f;
                float p = d[l - 1];
                if (m2 == l) {
                    d[l - 1] = p;
                    l--;
                    if (l >= lend) continue;
                    break;
                }
                if (m2 == l - 1) {
                    float rt1, rt2, cc, ss;
                    slaev2f(d[l - 2], e[l - 2], d[l - 1], &rt1, &rt2, &cc, &ss);
                    for (int i2 = 0; i2 < 3; i2++) { // slasr 'R','V','F', 2 cols
                        float t = z[i2][l - 1];
                        z[i2][l - 1] = __fadd_rn(__fmul_rn(cc, t), -__fmul_rn(ss, z[i2][l - 2]));
                        z[i2][l - 2] = __fadd_rn(__fmul_rn(ss, t),  __fmul_rn(cc, z[i2][l - 2]));
                    }
                    d[l - 2] = rt1; d[l - 1] = rt2; e[l - 2] = 0.0f;
                    l -= 2;
                    if (l >= lend) continue;
                    break;
                }
                if (jtot == nmaxit) break;
                jtot++;
                float g = f_div(__fadd_rn(d[l - 2], -p), __fmul_rn(2.0f, e[l - 2]));
                float r = slapy2f(g, 1.0f);
                g = __fadd_rn(__fadd_rn(d[m2 - 1], -p),
                              f_div(e[l - 2], __fadd_rn(g, f_sign(r, g))));
                float s = 1.0f, c = 1.0f;
                p = 0.0f;
                float csv[2], snv[2];
                for (int i2 = m2; i2 <= l - 1; i2++) {
                    float fv = __fmul_rn(s, e[i2 - 1]);
                    float bv = __fmul_rn(c, e[i2 - 1]);
                    slartgf(g, fv, &c, &s, &r);
                    if (i2 != m2) e[i2 - 2] = r;
                    g = __fadd_rn(d[i2 - 1], -p);
                    r = __fadd_rn(__fmul_rn(__fadd_rn(d[i2], -g), s),
                                  __fmul_rn(__fmul_rn(2.0f, c), bv));
                    p = __fmul_rn(s, r);
                    d[i2 - 1] = __fadd_rn(g, p);
                    g = __fadd_rn(__fmul_rn(c, r), -bv);
                    csv[i2 - m2] = c; snv[i2 - m2] = s;
                }
                int cnt = l - m2 + 1;               // slasr 'R','V','F'
                for (int jj = 1; jj <= cnt - 1; jj++) {
                    float cc = csv[jj - 1], ss = snv[jj - 1];
                    for (int i2 = 0; i2 < 3; i2++) {
                        float t = z[i2][m2 - 1 + jj];
                        z[i2][m2 - 1 + jj] = __fadd_rn(__fmul_rn(cc, t), -__fmul_rn(ss, z[i2][m2 - 2 + jj]));
                        z[i2][m2 - 2 + jj] = __fadd_rn(__fmul_rn(ss, t),  __fmul_rn(cc, z[i2][m2 - 2 + jj]));
                    }
                }
                d[l - 1] = __fadd_rn(d[l - 1], -p);
                e[l - 2] = g;
            }
        }
    }

    // Sort eigenvalues ascending, swapping columns (no sign change).
    for (int ii = 2; ii <= n; ii++) {
        int i = ii - 1, k = i;
        float p = d[i - 1];
        for (int jj = ii; jj <= n; jj++)
            if (d[jj - 1] < p) { k = jj; p = d[jj - 1]; }
        if (k != i) {
            d[k - 1] = d[i - 1]; d[i - 1] = p;
            for (int r_ = 0; r_ < 3; r_++) {
                float t = z[r_][i - 1]; z[r_][i - 1] = z[r_][k - 1]; z[r_][k - 1] = t;
            }
        }
    }
}

// One thread per point: covariance of K neighbors, then LAPACK-faithful
// smallest-eigenvalue eigenvector (ssytrd + ssteqr + Householder apply).
__global__ void normals_kernel(const float* __restrict__ pos, int N) {
    int i = blockIdx.x * blockDim.x + threadIdx.x;
    if (i >= N) return;

    float px[KNB], py[KNB], pz[KNB];
    float mx = 0.f, my = 0.f, mz = 0.f;
    #pragma unroll
    for (int t = 0; t < KNB; t++) {
        int j = g_nbr[i * KNB + t];
        px[t] = pos[j * 3 + 0];
        py[t] = pos[j * 3 + 1];
        pz[t] = pos[j * 3 + 2];
        mx += px[t]; my += py[t]; mz += pz[t];
    }
    const float invK = 1.0f / (float)KNB;
    mx *= invK; my *= invK; mz *= invK;

    float c00 = 0.f, c10 = 0.f, c20 = 0.f, c11 = 0.f, c21 = 0.f, c22 = 0.f;
    #pragma unroll
    for (int t = 0; t < KNB; t++) {
        float dx = px[t] - mx, dy = py[t] - my, dz = pz[t] - mz;
        c00 += dx * dx; c10 += dy * dx; c20 += dz * dx;
        c11 += dy * dy; c21 += dz * dy; c22 += dz * dz;
    }
    c00 *= invK; c10 *= invK; c20 *= invK;
    c11 *= invK; c21 *= invK; c22 *= invK;

    // ---- ssytrd (lower, N=3): one Householder annihilating c20 ----
    float e0, e1, d1c, d2c, tau1, v3;
    if (c20 == 0.0f) {                     // xnorm == 0 -> tau = 0, H = I
        tau1 = 0.0f; v3 = 0.0f;
        e0 = c10; d1c = c11; d2c = c22; e1 = c21;
    } else {
        float alpha = c10;
        float beta  = -f_sign(slapy2f(alpha, fabsf(c20)), alpha);
        tau1 = f_div(__fadd_rn(beta, -alpha), beta);
        v3   = f_div(c20, __fadd_rn(alpha, -beta));
        e0   = beta;
        float x1 = __fmul_rn(tau1, __fadd_rn(c11, __fmul_rn(c21, v3)));
        float x2 = __fmul_rn(tau1, __fadd_rn(c21, __fmul_rn(c22, v3)));
        float al = __fmul_rn(__fmul_rn(-0.5f, tau1),
                             __fadd_rn(x1, __fmul_rn(x2, v3)));
        float w1 = __fadd_rn(x1, al);
        float w2 = __fadd_rn(x2, __fmul_rn(al, v3));
        d1c = __fadd_rn(c11, -__fmul_rn(2.0f, w1));
        e1  = __fadd_rn(c21, -__fadd_rn(__fmul_rn(v3, w1), w2));
        d2c = __fadd_rn(c22, -__fmul_rn(__fmul_rn(2.0f, v3), w2));
    }

    float d[3] = { c00, d1c, d2c };
    float e[2] = { e0, e1 };
    float z[3][3] = { {1.f, 0.f, 0.f}, {0.f, 1.f, 0.f}, {0.f, 0.f, 1.f} };
    ssteqr3(d, e, z);

    // ---- sormtr: v_full = Q * z[:,0], Q = I - tau*u*u', u = (0,1,v3) ----
    float z1 = z[1][0], z2 = z[2][0];
    float q11 = 1.0f - tau1;
    float q12 = -__fmul_rn(tau1, v3);
    float q22 = 1.0f - __fmul_rn(tau1, __fmul_rn(v3, v3));
    float vx = z[0][0];
    float vy = __fadd_rn(__fmul_rn(q11, z1), __fmul_rn(q12, z2));
    float vz = __fadd_rn(__fmul_rn(q12, z1), __fmul_rn(q22, z2));

    float nn = fmaxf(f_sqrt(vx * vx + vy * vy + vz * vz), 1e-12f);
    g_norm[i * 3 + 0] = f_div(vx, nn);
    g_norm[i * 3 + 1] = f_div(vy, nn);
    g_norm[i * 3 + 2] = f_div(vz, nn);
}

// ---------------------------------------------------------------------------
// Warp per point: 16 edges; fd2 via warp reduce; scalar terms per-lane.
__global__ void edge_kernel(const float* __restrict__ rgb,
                            const int* __restrict__ target, int N) {
    int warp = (blockIdx.x * blockDim.x + threadIdx.x) >> 5;
    int lane = threadIdx.x & 31;
    if (warp >= N) return;
    int i = warp;

    float f0 = g_featn[i * 64 + lane];
    float f1 = g_featn[i * 64 + 32 + lane];
    int   ti = target[i];
    float nix = g_norm[i * 3 + 0], niy = g_norm[i * 3 + 1], niz = g_norm[i * 3 + 2];
    float rix = rgb[i * 3 + 0],    riy = rgb[i * 3 + 1],    riz = rgb[i * 3 + 2];

    float acc = 0.0f;
    #pragma unroll
    for (int t = 0; t < KNB; t++) {
        int j = g_nbr[i * KNB + t];
        float d0 = f0 - g_featn[j * 64 + lane];
        float d1 = f1 - g_featn[j * 64 + 32 + lane];
        float s  = d0 * d0 + d1 * d1;
        #pragma unroll
        for (int o = 16; o; o >>= 1) s += __shfl_xor_sync(FULLM, s, o);

        bool gate = (target[j] == ti);
        float dx = nix - g_norm[j * 3 + 0];
        float dy = niy - g_norm[j * 3 + 1];
        float dz = niz - g_norm[j * 3 + 2];
        float nd2 = dx * dx + dy * dy + dz * dz;
        float geo = expf(-nd2 * 50.0f);          // exp(-nd2 / (2*0.1^2))

        float cx = rix - rgb[j * 3 + 0];
        float cy = riy - rgb[j * 3 + 1];
        float cz = riz - rgb[j * 3 + 2];
        float rd2 = cx * cx + cy * cy + cz * cz;
        float inv = tanhf(5.0f * rd2);

        if (gate) acc += geo * inv * s;
    }
    if (lane == 0) atomicAdd(&g_acc, (double)acc);
}

// ---------------------------------------------------------------------------
__global__ void finalize_kernel(float* out, int N) {
    out[0] = (float)(g_acc / (double)((long long)N * KNB));
}

// ---------------------------------------------------------------------------
extern "C" void kernel_launch(void* const* d_in, const int* in_sizes, int n_in,
                              void* d_out, int out_size) {
    const float* features = (const float*)d_in[0];
    const float* pos      = (const float*)d_in[1];
    const float* rgb      = (const float*)d_in[2];
    const int*   target   = (const int*)d_in[3];
    // d_in[4] = batch (sorted equal segments; implied by N/NSEG)

    int N = in_sizes[3];
    if (N > MAXN) N = MAXN;
    int M = N / NSEG;
    int Mpad = (M + 63) & ~63;                    // 64-aligned (2 cand/lane)

    zero_acc_kernel<<<1, 1>>>();

    int warpBlocks = (N + 3) / 4;                 // 4 warps (128 thr) per block
    featnorm_kernel<<<warpBlocks, 128>>>(features, N);

    int bps = (M + QPB - 1) / QPB;                // blocks per segment
    size_t smem = (size_t)Mpad * sizeof(float4)   // staged positions
                + (size_t)QPB * CAP * sizeof(int);// capture buffers
    cudaFuncSetAttribute(knn_kernel,
                         cudaFuncAttributeMaxDynamicSharedMemorySize,
                         (int)smem);
    knn_kernel<<<NSEG * bps, QPB * 32, smem>>>(pos, M, Mpad, bps);

    normals_kernel<<<(N + 127) / 128, 128>>>(pos, N);

    edge_kernel<<<warpBlocks, 128>>>(rgb, target, N);

    finalize_kernel<<<1, 1>>>((float*)d_out, N);
}

// round 16
// speedup vs baseline: 2.4015x; 1.0707x over previous
#include <cuda_runtime.h>
#include <math.h>

// Problem constants: K=16 neighbors, B=4 segments, sigma_g=0.1 -> exp(-nd2*50),
// lambda_tex=5, weight=1, D=64 features.
#define KNB   16
#define KP1   17
#define NSEG  4
#define MAXN  20480
#define QPB   16            // queries per block = warps per block (512 threads)
#define CAP   256           // per-warp capture buffer entries
#define FULLM 0xffffffffu

// Scratch (static __device__ — no allocation allowed)
__device__ float  g_featn[MAXN * 64];   // normalized features
__device__ int    g_nbr[MAXN * KNB];    // global neighbor indices
__device__ float  g_norm[MAXN * 3];     // unit normals (LAPACK-sign-faithful)
__device__ double g_acc;                // loss accumulator
__device__ int    g_done;               // last-block ticket (self-resetting)

// ---------------------------------------------------------------------------
// Warp per row: L2-normalize 64-d features. lane holds elems {lane, lane+32}.
// Also zeroes g_acc (kernel-boundary ordering guarantees visibility to the
// edge kernel, which is the only consumer).
__global__ void featnorm_kernel(const float* __restrict__ f, int N) {
    if (blockIdx.x == 0 && threadIdx.x == 0) g_acc = 0.0;
    int warp = (blockIdx.x * blockDim.x + threadIdx.x) >> 5;
    int lane = threadIdx.x & 31;
    if (warp >= N) return;
    float a = f[warp * 64 + lane];
    float b = f[warp * 64 + 32 + lane];
    float s = a * a + b * b;
    #pragma unroll
    for (int o = 16; o; o >>= 1) s += __shfl_xor_sync(FULLM, s, o);
    float n = fmaxf(__fsqrt_rn(s), 1e-12f);
    g_featn[warp * 64 + lane]      = __fdiv_rn(a, n);
    g_featn[warp * 64 + 32 + lane] = __fdiv_rn(b, n);
}

// ---------------------------------------------------------------------------
// Warp-per-query KNN: single main scan with capture buffer + tiny filter pass.
//
// SPEC FACTS (R3..R15, all bench-validated):
//  * Count check makes selection SELF-CERTIFYING: any thr with
//    #{d2 <= thr} == 17 forces the exact 17-smallest set; other counts ->
//    exact R5 fallback chain.
//  * Key-only max-evict is multiset-safe; thr is selection-algorithm-indep.
//  * Emission in ascending index order reproduces rel_err 2.621058e-07.
//  * CAPTURE INVARIANT: curmax is non-increasing and ends at thr, so every
//    final-set member has d2 <= curmax at its scan time -> capturing with the
//    NON-STRICT test guarantees final set ⊆ captured ids (appended in
//    ascending index order). Filtering the buffer by d2 <= thr + count check
//    is therefore exact; overflow (cnt > CAP) falls back to a full scan.
//  * Max-recompute via redux.sync on the order-preserving unsigned encoding
//    (bit-identical to the shfl reduce, 1 instr).
//  * R16: main scan unrolled x4 (128 cand/round) — batches processed in
//    ascending index order, so capture/thr/emission identical.
__device__ __forceinline__ float cand_d2(float4 Q, float4 P) {
    float dot = __fadd_rn(__fadd_rn(__fmul_rn(Q.x, P.x),
                                    __fmul_rn(Q.y, P.y)),
                          __fmul_rn(Q.z, P.z));
    return __fadd_rn(__fadd_rn(Q.w, P.w), __fmul_rn(-2.0f, dot));
}

// Order-preserving float <-> unsigned (total order, handles negatives).
__device__ __forceinline__ unsigned f2u(float f) {
    unsigned b = __float_as_uint(f);
    return (b & 0x80000000u) ? ~b : (b | 0x80000000u);
}
__device__ __forceinline__ float u2f(unsigned u) {
    return __uint_as_float((u & 0x80000000u) ? (u ^ 0x80000000u) : ~u);
}

__global__ void __launch_bounds__(QPB * 32, 2)
knn_kernel(const float* __restrict__ pos, int M, int Mpad, int bps) {
    extern __shared__ float4 sp[];
    int* capbuf = (int*)(sp + Mpad);    // QPB * CAP ints
    int seg  = blockIdx.x / bps;
    int lb   = blockIdx.x % bps;
    int base = seg * M;
    const float INF = __int_as_float(0x7f800000);

    for (int t = threadIdx.x; t < Mpad; t += blockDim.x) {
        if (t < M) {
            float x = pos[(base + t) * 3 + 0];
            float y = pos[(base + t) * 3 + 1];
            float z = pos[(base + t) * 3 + 2];
            float sq = __fadd_rn(__fadd_rn(__fmul_rn(x, x), __fmul_rn(y, y)),
                                 __fmul_rn(z, z));
            sp[t] = make_float4(x, y, z, sq);
        } else {
            sp[t] = make_float4(0.0f, 0.0f, 0.0f, INF);  // d2=+inf: never captured
        }
    }
    __syncthreads();

    int warp = threadIdx.x >> 5;
    int lane = threadIdx.x & 31;
    int q = lb * QPB + warp;
    if (q >= M) return;                 // uniform per warp

    float4 Q = sp[q];
    int* mybuf = capbuf + warp * CAP;

    // ---- Main scan: distributed key-only top-17 + capture (4 cand/lane) ----
    float kkey   = 3.4e38f;             // lane t (t<=16): one unsorted slot
    float curmax = 3.4e38f;             // uniform: max over slots 0..16
    int   cnt    = 0;                   // captures (uniform)

    #define PROC(MASK, D2VAR, JBASE)                                        \
        while (MASK) {                                                      \
            int src = __ffs(MASK) - 1;                                      \
            MASK &= MASK - 1;                                               \
            float kd = __shfl_sync(FULLM, D2VAR, src);                      \
            if (kd <= curmax) {         /* uniform recheck, non-strict */   \
                int ki = (JBASE) + src;                                     \
                if (cnt < CAP) { if (lane == 0) mybuf[cnt] = ki; }          \
                cnt++;                                                      \
                if (kd < curmax) {      /* strict: structure update */      \
                    unsigned mx = __ballot_sync(FULLM,                      \
                                      (lane < KP1) && (kkey == curmax));    \
                    if (lane == __ffs(mx) - 1) kkey = kd;                   \
                    unsigned enc = (lane < KP1) ? f2u(kkey) : 0u;           \
                    curmax = u2f(__reduce_max_sync(FULLM, enc));            \
                }                                                           \
            }                                                               \
        }

    for (int j0 = 0; j0 < Mpad; j0 += 128) {
        float d2a = cand_d2(Q, sp[j0 + lane]);
        float d2b = cand_d2(Q, sp[j0 + 32 + lane]);
        float d2c = cand_d2(Q, sp[j0 + 64 + lane]);
        float d2d = cand_d2(Q, sp[j0 + 96 + lane]);
        // Batches a->b->c->d fully in order: ascending candidate index.
        unsigned ma = __ballot_sync(FULLM, d2a <= curmax);
        PROC(ma, d2a, j0);
        unsigned mb = __ballot_sync(FULLM, d2b <= curmax);
        PROC(mb, d2b, j0 + 32);
        unsigned mc = __ballot_sync(FULLM, d2c <= curmax);
        PROC(mc, d2c, j0 + 64);
        unsigned md = __ballot_sync(FULLM, d2d <= curmax);
        PROC(md, d2d, j0 + 96);
    }
    #undef PROC
    float thr = curmax;
    __syncwarp();                       // lane-0 capture writes -> all lanes

    // ---- Filter pass: emit captured ids with d2 <= thr, index order ----
    int outp = (base + q) * KNB;
    int w = 0;                          // non-self emitted (uniform)
    if (cnt <= CAP) {
        for (int b0 = 0; b0 < cnt; b0 += 32) {
            int idx = b0 + lane;
            bool valid = (idx < cnt);
            int id = valid ? mybuf[idx] : 0;
            float d2 = valid ? cand_d2(Q, sp[id]) : INF;
            bool emit = valid && (d2 <= thr) && (id != q);
            unsigned em = __ballot_sync(FULLM, emit);
            int pos = w + __popc(em & ((1u << lane) - 1u));
            if (emit && pos < KNB)
                g_nbr[outp + pos] = base + id;
            w += __popc(em);
        }
    } else {
        // Overflow (adversarial only): full threshold scan, index order.
        for (int j0 = 0; j0 < Mpad; j0 += 32) {
            int j = j0 + lane;
            float d2 = cand_d2(Q, sp[j]);
            bool emit = (d2 <= thr) && (j != q);
            unsigned em = __ballot_sync(FULLM, emit);
            int pos = w + __popc(em & ((1u << lane) - 1u));
            if (emit && pos < KNB)
                g_nbr[outp + pos] = base + j;
            w += __popc(em);
        }
    }

    // ---- Rare exact fallback: count != 17 -> verbatim R5 id-chain ----
    if (w + 1 != KP1) {
        float fk[KP1];
        int   fi[KP1];
        #pragma unroll
        for (int t = 0; t < KP1; t++) { fk[t] = 3.4e38f; fi[t] = -1; }
        for (int j0 = 0; j0 < Mpad; j0 += 32) {
            float d2 = cand_d2(Q, sp[j0 + lane]);
            unsigned m = __ballot_sync(FULLM, d2 < fk[KP1 - 1]);
            while (m) {
                int src = __ffs(m) - 1;
                m &= m - 1;
                float kd = __shfl_sync(FULLM, d2, src);
                int   ki = j0 + src;
                if (kd < fk[KP1 - 1]) {
                    #pragma unroll
                    for (int t = 0; t < KP1; t++) {
                        if (kd < fk[t]) {
                            float tk = fk[t]; fk[t] = kd; kd = tk;
                            int   ti = fi[t]; fi[t] = ki; ki = ti;
                        }
                    }
                }
            }
        }
        if (lane == 0) {
            int w2 = 0;
            #pragma unroll
            for (int t = 0; t < KP1; t++) {
                if (fi[t] != q && w2 < KNB) {
                    g_nbr[outp + w2] = base + fi[t]; w2++;
                }
            }
        }
    }
}

// ===========================================================================
// Faithful fp32 port of the LAPACK ssyevd(N=3, jobz='V', uplo='L') path:
// ssytrd (slarfg Householder) -> ssteqr('I') -> sormtr. All math in
// round-to-nearest intrinsics so fast-math flags cannot change decisions.
// ===========================================================================
__device__ __forceinline__ float f_div(float a, float b) { return __fdiv_rn(a, b); }
__device__ __forceinline__ float f_sqrt(float a)         { return __fsqrt_rn(a); }
// Fortran SIGN(a,b): |a| if b >= 0 (incl. -0.0 since -0>=0 in C), else -|a|.
__device__ __forceinline__ float f_sign(float a, float b) {
    float aa = fabsf(a);
    return (b >= 0.0f) ? aa : -aa;
}

__device__ float slapy2f(float x, float y) {
    float xa = fabsf(x), ya = fabsf(y);
    float w = fmaxf(xa, ya), zm = fminf(xa, ya);
    if (zm == 0.0f) return w;
    float q = f_div(zm, w);
    return __fmul_rn(w, f_sqrt(__fadd_rn(1.0f, __fmul_rn(q, q))));
}

// LAPACK >= 3.10 slartg (unscaled branch; our magnitudes are mid-range).
__device__ void slartgf(float f, float g, float* c, float* s, float* r) {
    if (g == 0.0f)      { *c = 1.0f; *s = 0.0f; *r = f; }
    else if (f == 0.0f) { *c = 0.0f; *s = f_sign(1.0f, g); *r = fabsf(g); }
    else {
        float d = f_sqrt(__fadd_rn(__fmul_rn(f, f), __fmul_rn(g, g)));
        *c = f_div(fabsf(f), d);
        *r = f_sign(d, f);
        *s = f_div(g, *r);
    }
}

__device__ void slaev2f(float a, float b, float c_, float* rt1, float* rt2,
                        float* cs1, float* sn1) {
    float sm  = __fadd_rn(a, c_);
    float df  = __fadd_rn(a, -c_);
    float adf = fabsf(df);
    float tb  = __fadd_rn(b, b);
    float ab  = fabsf(tb);
    float acmx, acmn;
    if (fabsf(a) > fabsf(c_)) { acmx = a; acmn = c_; }
    else                      { acmx = c_; acmn = a; }
    float rt;
    if (adf > ab) {
        float q = f_div(ab, adf);
        rt = __fmul_rn(adf, f_sqrt(__fadd_rn(1.0f, __fmul_rn(q, q))));
    } else if (adf < ab) {
        float q = f_div(adf, ab);
        rt = __fmul_rn(ab, f_sqrt(__fadd_rn(1.0f, __fmul_rn(q, q))));
    } else {
        rt = __fmul_rn(ab, f_sqrt(2.0f));
    }
    int sgn1;
    if (sm < 0.0f) {
        *rt1 = __fmul_rn(0.5f, __fadd_rn(sm, -rt)); sgn1 = -1;
        *rt2 = __fadd_rn(__fmul_rn(f_div(acmx, *rt1), acmn),
                         -__fmul_rn(f_div(b, *rt1), b));
    } else if (sm > 0.0f) {
        *rt1 = __fmul_rn(0.5f, __fadd_rn(sm, rt)); sgn1 = 1;
        *rt2 = __fadd_rn(__fmul_rn(f_div(acmx, *rt1), acmn),
                         -__fmul_rn(f_div(b, *rt1), b));
    } else {
        *rt1 = __fmul_rn(0.5f, rt); *rt2 = __fmul_rn(-0.5f, rt); sgn1 = 1;
    }
    float cs; int sgn2;
    if (df >= 0.0f) { cs = __fadd_rn(df, rt);  sgn2 = 1;  }
    else            { cs = __fadd_rn(df, -rt); sgn2 = -1; }
    float acs = fabsf(cs);
    float c1, s1;
    if (acs > ab) {
        float ct = f_div(-tb, cs);
        s1 = f_div(1.0f, f_sqrt(__fadd_rn(1.0f, __fmul_rn(ct, ct))));
        c1 = __fmul_rn(ct, s1);
    } else {
        if (ab == 0.0f) { c1 = 1.0f; s1 = 0.0f; }
        else {
            float tn = f_div(-cs, tb);
            c1 = f_div(1.0f, f_sqrt(__fadd_rn(1.0f, __fmul_rn(tn, tn))));
            s1 = __fmul_rn(tn, c1);
        }
    }
    if (sgn1 == sgn2) { float tn = c1; c1 = -s1; s1 = tn; }
    *cs1 = c1; *sn1 = s1;
}

// ssteqr('I', n=3): d[3], e[2], z = identity on entry; eigenvectors of the
// tridiagonal in z columns, ascending eigenvalues, LAPACK sign conventions.
__device__ void ssteqr3(float* d, float* e, float z[3][3]) {
    const float eps    = 5.9604645e-08f;   // slamch('E') fp32 = 2^-24
    const float eps2   = eps * eps;
    const float safmin = 1.1754944e-38f;
    const int   n = 3;
    const int   nmaxit = n * 30;
    int jtot = 0;
    int l1 = 1;                            // 1-based throughout

    for (int guard = 0; guard < 64; guard++) {
        if (l1 > n) break;
        if (l1 > 1) e[l1 - 2] = 0.0f;
        int m;
        for (m = l1; m <= n - 1; m++) {
            float tst = fabsf(e[m - 1]);
            if (tst == 0.0f) break;
            if (tst <= __fmul_rn(__fmul_rn(f_sqrt(fabsf(d[m - 1])),
                                           f_sqrt(fabsf(d[m]))), eps)) {
                e[m - 1] = 0.0f;
                break;
            }
        }
        int l = l1, lsv = l, lend = m, lendsv = lend;
        l1 = m + 1;
        if (lend == l) continue;

        if (fabsf(d[lend - 1]) < fabsf(d[l - 1])) { lend = lsv; l = lendsv; }

        if (lend > l) {
            // ---- QL iteration ----
            for (;;) {
                int mm_;
                for (mm_ = l; mm_ <= lend - 1; mm_++) {
                    float tst = __fmul_rn(e[mm_ - 1], e[mm_ - 1]);
                    if (tst <= __fadd_rn(__fmul_rn(__fmul_rn(eps2, fabsf(d[mm_ - 1])),
                                                   fabsf(d[mm_])), safmin))
                        break;
                }
                int m2 = mm_;                        // == lend if no break
                if (m2 < lend) e[m2 - 1] = 0.0f;
                float p = d[l - 1];
                if (m2 == l) {                       // eigenvalue found
                    d[l - 1] = p;
                    l++;
                    if (l <= lend) continue;
                    break;
                }
                if (m2 == l + 1) {                   // 2x2: slaev2
                    float rt1, rt2, cc, ss;
                    slaev2f(d[l - 1], e[l - 1], d[l], &rt1, &rt2, &cc, &ss);
                    for (int i2 = 0; i2 < 3; i2++) { // slasr 'R','V','B', 2 cols
                        float t = z[i2][l];
                        z[i2][l]     = __fadd_rn(__fmul_rn(cc, t), -__fmul_rn(ss, z[i2][l - 1]));
                        z[i2][l - 1] = __fadd_rn(__fmul_rn(ss, t),  __fmul_rn(cc, z[i2][l - 1]));
                    }
                    d[l - 1] = rt1; d[l] = rt2; e[l - 1] = 0.0f;
                    l += 2;
                    if (l <= lend) continue;
                    break;
                }
                if (jtot == nmaxit) break;
                jtot++;
                float g = f_div(__fadd_rn(d[l], -p), __fmul_rn(2.0f, e[l - 1]));
                float r = slapy2f(g, 1.0f);
                g = __fadd_rn(__fadd_rn(d[m2 - 1], -p),
                              f_div(e[l - 1], __fadd_rn(g, f_sign(r, g))));
                float s = 1.0f, c = 1.0f;
                p = 0.0f;
                float csv[2], snv[2];
                for (int i2 = m2 - 1; i2 >= l; i2--) {
                    float fv = __fmul_rn(s, e[i2 - 1]);
                    float bv = __fmul_rn(c, e[i2 - 1]);
                    slartgf(g, fv, &c, &s, &r);
                    if (i2 != m2 - 1) e[i2] = r;
                    g = __fadd_rn(d[i2], -p);
                    r = __fadd_rn(__fmul_rn(__fadd_rn(d[i2 - 1], -g), s),
                                  __fmul_rn(__fmul_rn(2.0f, c), bv));
                    p = __fmul_rn(s, r);
                    d[i2] = __fadd_rn(g, p);
                    g = __fadd_rn(__fmul_rn(c, r), -bv);
                    csv[i2 - l] = c; snv[i2 - l] = -s;
                }
                int cnt = m2 - l + 1;               // slasr 'R','V','B'
                for (int jj = cnt - 1; jj >= 1; jj--) {
                    float cc = csv[jj - 1], ss = snv[jj - 1];
                    for (int i2 = 0; i2 < 3; i2++) {
                        float t = z[i2][l - 1 + jj];
                        z[i2][l - 1 + jj]     = __fadd_rn(__fmul_rn(cc, t), -__fmul_rn(ss, z[i2][l - 2 + jj]));
                        z[i2][l - 2 + jj]     = __fadd_rn(__fmul_rn(ss, t),  __fmul_rn(cc, z[i2][l - 2 + jj]));
                    }
                }
                d[l - 1] = __fadd_rn(d[l - 1], -p);
                e[l - 1] = g;
            }
        } else {
            // ---- QR iteration (lend < l) ----
            for (;;) {
                int mm_;
                for (mm_ = l; mm_ >= lend + 1; mm_--) {
                    float tst = __fmul_rn(e[mm_ - 2], e[mm_ - 2]);
                    if (tst <= __fadd_rn(__fmul_rn(__fmul_rn(eps2, fabsf(d[mm_ - 1])),
                                                   fabsf(d[mm_ - 2])), safmin))
                        break;
                }
                int m2 = mm_;                        // == lend if no break
                if (m2 > lend) e[m2 - 2] = 0.0f;
                float p = d[l - 1];
                if (m2 == l) {
                    d[l - 1] = p;
                    l--;
                    if (l >= lend) continue;
                    break;
                }
                if (m2 == l - 1) {
                    float rt1, rt2, cc, ss;
                    slaev2f(d[l - 2], e[l - 2], d[l - 1], &rt1, &rt2, &cc, &ss);
                    for (int i2 = 0; i2 < 3; i2++) { // slasr 'R','V','F', 2 cols
                        float t = z[i2][l - 1];
                        z[i2][l - 1] = __fadd_rn(__fmul_rn(cc, t), -__fmul_rn(ss, z[i2][l - 2]));
                        z[i2][l - 2] = __fadd_rn(__fmul_rn(ss, t),  __fmul_rn(cc, z[i2][l - 2]));
                    }
                    d[l - 2] = rt1; d[l - 1] = rt2; e[l - 2] = 0.0f;
                    l -= 2;
                    if (l >= lend) continue;
                    break;
                }
                if (jtot == nmaxit) break;
                jtot++;
                float g = f_div(__fadd_rn(d[l - 2], -p), __fmul_rn(2.0f, e[l - 2]));
                float r = slapy2f(g, 1.0f);
                g = __fadd_rn(__fadd_rn(d[m2 - 1], -p),
                              f_div(e[l - 2], __fadd_rn(g, f_sign(r, g))));
                float s = 1.0f, c = 1.0f;
                p = 0.0f;
                float csv[2], snv[2];
                for (int i2 = m2; i2 <= l - 1; i2++) {
                    float fv = __fmul_rn(s, e[i2 - 1]);
                    float bv = __fmul_rn(c, e[i2 - 1]);
                    slartgf(g, fv, &c, &s, &r);
                    if (i2 != m2) e[i2 - 2] = r;
                    g = __fadd_rn(d[i2 - 1], -p);
                    r = __fadd_rn(__fmul_rn(__fadd_rn(d[i2], -g), s),
                                  __fmul_rn(__fmul_rn(2.0f, c), bv));
                    p = __fmul_rn(s, r);
                    d[i2 - 1] = __fadd_rn(g, p);
                    g = __fadd_rn(__fmul_rn(c, r), -bv);
                    csv[i2 - m2] = c; snv[i2 - m2] = s;
                }
                int cnt = l - m2 + 1;               // slasr 'R','V','F'
                for (int jj = 1; jj <= cnt - 1; jj++) {
                    float cc = csv[jj - 1], ss = snv[jj - 1];
                    for (int i2 = 0; i2 < 3; i2++) {
                        float t = z[i2][m2 - 1 + jj];
                        z[i2][m2 - 1 + jj] = __fadd_rn(__fmul_rn(cc, t), -__fmul_rn(ss, z[i2][m2 - 2 + jj]));
                        z[i2][m2 - 2 + jj] = __fadd_rn(__fmul_rn(ss, t),  __fmul_rn(cc, z[i2][m2 - 2 + jj]));
                    }
                }
                d[l - 1] = __fadd_rn(d[l - 1], -p);
                e[l - 2] = g;
            }
        }
    }

    // Sort eigenvalues ascending, swapping columns (no sign change).
    for (int ii = 2; ii <= n; ii++) {
        int i = ii - 1, k = i;
        float p = d[i - 1];
        for (int jj = ii; jj <= n; jj++)
            if (d[jj - 1] < p) { k = jj; p = d[jj - 1]; }
        if (k != i) {
            d[k - 1] = d[i - 1]; d[i - 1] = p;
            for (int r_ = 0; r_ < 3; r_++) {
                float t = z[r_][i - 1]; z[r_][i - 1] = z[r_][k - 1]; z[r_][k - 1] = t;
            }
        }
    }
}

// One thread per point: covariance of K neighbors, then LAPACK-faithful
// smallest-eigenvalue eigenvector (ssytrd + ssteqr + Householder apply).
__global__ void normals_kernel(const float* __restrict__ pos, int N) {
    int i = blockIdx.x * blockDim.x + threadIdx.x;
    if (i >= N) return;

    float px[KNB], py[KNB], pz[KNB];
    float mx = 0.f, my = 0.f, mz = 0.f;
    #pragma unroll
    for (int t = 0; t < KNB; t++) {
        int j = g_nbr[i * KNB + t];
        px[t] = pos[j * 3 + 0];
        py[t] = pos[j * 3 + 1];
        pz[t] = pos[j * 3 + 2];
        mx += px[t]; my += py[t]; mz += pz[t];
    }
    const float invK = 1.0f / (float)KNB;
    mx *= invK; my *= invK; mz *= invK;

    float c00 = 0.f, c10 = 0.f, c20 = 0.f, c11 = 0.f, c21 = 0.f, c22 = 0.f;
    #pragma unroll
    for (int t = 0; t < KNB; t++) {
        float dx = px[t] - mx, dy = py[t] - my, dz = pz[t] - mz;
        c00 += dx * dx; c10 += dy * dx; c20 += dz * dx;
        c11 += dy * dy; c21 += dz * dy; c22 += dz * dz;
    }
    c00 *= invK; c10 *= invK; c20 *= invK;
    c11 *= invK; c21 *= invK; c22 *= invK;

    // ---- ssytrd (lower, N=3): one Householder annihilating c20 ----
    float e0, e1, d1c, d2c, tau1, v3;
    if (c20 == 0.0f) {                     // xnorm == 0 -> tau = 0, H = I
        tau1 = 0.0f; v3 = 0.0f;
        e0 = c10; d1c = c11; d2c = c22; e1 = c21;
    } else {
        float alpha = c10;
        float beta  = -f_sign(slapy2f(alpha, fabsf(c20)), alpha);
        tau1 = f_div(__fadd_rn(beta, -alpha), beta);
        v3   = f_div(c20, __fadd_rn(alpha, -beta));
        e0   = beta;
        float x1 = __fmul_rn(tau1, __fadd_rn(c11, __fmul_rn(c21, v3)));
        float x2 = __fmul_rn(tau1, __fadd_rn(c21, __fmul_rn(c22, v3)));
        float al = __fmul_rn(__fmul_rn(-0.5f, tau1),
                             __fadd_rn(x1, __fmul_rn(x2, v3)));
        float w1 = __fadd_rn(x1, al);
        float w2 = __fadd_rn(x2, __fmul_rn(al, v3));
        d1c = __fadd_rn(c11, -__fmul_rn(2.0f, w1));
        e1  = __fadd_rn(c21, -__fadd_rn(__fmul_rn(v3, w1), w2));
        d2c = __fadd_rn(c22, -__fmul_rn(__fmul_rn(2.0f, v3), w2));
    }

    float d[3] = { c00, d1c, d2c };
    float e[2] = { e0, e1 };
    float z[3][3] = { {1.f, 0.f, 0.f}, {0.f, 1.f, 0.f}, {0.f, 0.f, 1.f} };
    ssteqr3(d, e, z);

    // ---- sormtr: v_full = Q * z[:,0], Q = I - tau*u*u', u = (0,1,v3) ----
    float z1 = z[1][0], z2 = z[2][0];
    float q11 = 1.0f - tau1;
    float q12 = -__fmul_rn(tau1, v3);
    float q22 = 1.0f - __fmul_rn(tau1, __fmul_rn(v3, v3));
    float vx = z[0][0];
    float vy = __fadd_rn(__fmul_rn(q11, z1), __fmul_rn(q12, z2));
    float vz = __fadd_rn(__fmul_rn(q12, z1), __fmul_rn(q22, z2));

    float nn = fmaxf(f_sqrt(vx * vx + vy * vy + vz * vz), 1e-12f);
    g_norm[i * 3 + 0] = f_div(vx, nn);
    g_norm[i * 3 + 1] = f_div(vy, nn);
    g_norm[i * 3 + 2] = f_div(vz, nn);
}

// ---------------------------------------------------------------------------
// Warp per point: 16 edges; fd2 via warp reduce; scalar terms per-lane.
// Last block (ticket) writes the final mean (fused finalize; counter
// self-resets so the kernel is graph-replay safe).
__global__ void edge_kernel(const float* __restrict__ rgb,
                            const int* __restrict__ target, int N,
                            float* __restrict__ out) {
    int warp = (blockIdx.x * blockDim.x + threadIdx.x) >> 5;
    int lane = threadIdx.x & 31;
    int i = warp;

    if (i < N) {
        float f0 = g_featn[i * 64 + lane];
        float f1 = g_featn[i * 64 + 32 + lane];
        int   ti = target[i];
        float nix = g_norm[i * 3 + 0], niy = g_norm[i * 3 + 1], niz = g_norm[i * 3 + 2];
        float rix = rgb[i * 3 + 0],    riy = rgb[i * 3 + 1],    riz = rgb[i * 3 + 2];

        float acc = 0.0f;
        #pragma unroll
        for (int t = 0; t < KNB; t++) {
            int j = g_nbr[i * KNB + t];
            float d0 = f0 - g_featn[j * 64 + lane];
            float d1 = f1 - g_featn[j * 64 + 32 + lane];
            float s  = d0 * d0 + d1 * d1;
            #pragma unroll
            for (int o = 16; o; o >>= 1) s += __shfl_xor_sync(FULLM, s, o);

            bool gate = (target[j] == ti);
            float dx = nix - g_norm[j * 3 + 0];
            float dy = niy - g_norm[j * 3 + 1];
            float dz = niz - g_norm[j * 3 + 2];
            float nd2 = dx * dx + dy * dy + dz * dz;
            float geo = expf(-nd2 * 50.0f);          // exp(-nd2 / (2*0.1^2))

            float cx = rix - rgb[j * 3 + 0];
            float cy = riy - rgb[j * 3 + 1];
            float cz = riz - rgb[j * 3 + 2];
            float rd2 = cx * cx + cy * cy + cz * cz;
            float inv = tanhf(5.0f * rd2);

            if (gate) acc += geo * inv * s;
        }
        if (lane == 0) atomicAdd(&g_acc, (double)acc);
    }

    // Fused finalize: last block to arrive writes the output.
    __syncthreads();
    __threadfence();
    if (threadIdx.x == 0) {
        int t = atomicAdd(&g_done, 1);
        if (t == (int)gridDim.x - 1) {
            g_done = 0;                             // reset for graph replay
            out[0] = (float)(g_acc / (double)((long long)N * KNB));
        }
    }
}

// ---------------------------------------------------------------------------
extern "C" void kernel_launch(void* const* d_in, const int* in_sizes, int n_in,
                              void* d_out, int out_size) {
    const float* features = (const float*)d_in[0];
    const float* pos      = (const float*)d_in[1];
    const float* rgb      = (const float*)d_in[2];
    const int*   target   = (const int*)d_in[3];
    // d_in[4] = batch (sorted equal segments; implied by N/NSEG)

    int N = in_sizes[3];
    if (N > MAXN) N = MAXN;
    int M = N / NSEG;
    int Mpad = (M + 127) & ~127;                  // 128-aligned (4 cand/lane)

    int warpBlocks = (N + 3) / 4;                 // 4 warps (128 thr) per block
    featnorm_kernel<<<warpBlocks, 128>>>(features, N);

    int bps = (M + QPB - 1) / QPB;                // blocks per segment
    size_t smem = (size_t)Mpad * sizeof(float4)   // staged positions
                + (size_t)QPB * CAP * sizeof(int);// capture buffers
    cudaFuncSetAttribute(knn_kernel,
                         cudaFuncAttributeMaxDynamicSharedMemorySize,
                         (int)smem);
    knn_kernel<<<NSEG * bps, QPB * 32, smem>>>(pos, M, Mpad, bps);

    normals_kernel<<<(N + 127) / 128, 128>>>(pos, N);

    edge_kernel<<<warpBlocks, 128>>>(rgb, target, N, (float*)d_out);
}

// round 17
// speedup vs baseline: 2.4522x; 1.0211x over previous
#include <cuda_runtime.h>
#include <math.h>

// Problem constants: K=16 neighbors, B=4 segments, sigma_g=0.1 -> exp(-nd2*50),
// lambda_tex=5, weight=1, D=64 features.
#define KNB   16
#define KP1   17
#define NSEG  4
#define MAXN  20480
#define QPB   16            // queries per block = warps per block (512 threads)
#define CAP   256           // per-warp capture buffer entries
#define FULLM 0xffffffffu

// Scratch (static __device__ — no allocation allowed)
__device__ float  g_featn[MAXN * 64];   // normalized features
__device__ int    g_nbr[MAXN * KNB];    // global neighbor indices
__device__ float  g_norm[MAXN * 3];     // unit normals (LAPACK-sign-faithful)
__device__ double g_acc;                // loss accumulator
__device__ int    g_done;               // last-block ticket (self-resetting)

// ---------------------------------------------------------------------------
// Warp per row: L2-normalize 64-d features. lane holds elems {lane, lane+32}.
// Also zeroes g_acc (kernel-boundary ordering guarantees visibility to the
// edge kernel, which is the only consumer).
__global__ void featnorm_kernel(const float* __restrict__ f, int N) {
    if (blockIdx.x == 0 && threadIdx.x == 0) g_acc = 0.0;
    int warp = (blockIdx.x * blockDim.x + threadIdx.x) >> 5;
    int lane = threadIdx.x & 31;
    if (warp >= N) return;
    float a = f[warp * 64 + lane];
    float b = f[warp * 64 + 32 + lane];
    float s = a * a + b * b;
    #pragma unroll
    for (int o = 16; o; o >>= 1) s += __shfl_xor_sync(FULLM, s, o);
    float n = fmaxf(__fsqrt_rn(s), 1e-12f);
    g_featn[warp * 64 + lane]      = __fdiv_rn(a, n);
    g_featn[warp * 64 + 32 + lane] = __fdiv_rn(b, n);
}

// ---------------------------------------------------------------------------
// Warp-per-query KNN: single main scan with capture buffer + tiny filter pass.
//
// SPEC FACTS (R3..R16, all bench-validated):
//  * Count check makes selection SELF-CERTIFYING: any thr with
//    #{d2 <= thr} == 17 forces the exact 17-smallest set; other counts ->
//    exact R5 fallback chain.
//  * Key-only max-evict is multiset-safe; thr is selection-algorithm-indep.
//  * Emission in ascending index order reproduces rel_err ~2.62e-07.
//  * CAPTURE INVARIANT: curmax is non-increasing and ends at thr, so every
//    final-set member has d2 <= curmax at its scan time -> capturing with the
//    NON-STRICT test guarantees final set ⊆ captured ids (appended in
//    ascending index order). Filtering the buffer by d2 <= thr + count check
//    is therefore exact; overflow (cnt > CAP) falls back to a full scan.
//  * Max-recompute via redux.sync on the order-preserving unsigned encoding.
//  * Main scan unrolled x4 (128 cand/round), batches in ascending order.
__device__ __forceinline__ float cand_d2(float4 Q, float4 P) {
    float dot = __fadd_rn(__fadd_rn(__fmul_rn(Q.x, P.x),
                                    __fmul_rn(Q.y, P.y)),
                          __fmul_rn(Q.z, P.z));
    return __fadd_rn(__fadd_rn(Q.w, P.w), __fmul_rn(-2.0f, dot));
}

// Order-preserving float <-> unsigned (total order, handles negatives).
__device__ __forceinline__ unsigned f2u(float f) {
    unsigned b = __float_as_uint(f);
    return (b & 0x80000000u) ? ~b : (b | 0x80000000u);
}
__device__ __forceinline__ float u2f(unsigned u) {
    return __uint_as_float((u & 0x80000000u) ? (u ^ 0x80000000u) : ~u);
}

__global__ void __launch_bounds__(QPB * 32, 2)
knn_kernel(const float* __restrict__ pos, int M, int Mpad, int bps) {
    extern __shared__ float4 sp[];
    int* capbuf = (int*)(sp + Mpad);    // QPB * CAP ints
    int seg  = blockIdx.x / bps;
    int lb   = blockIdx.x % bps;
    int base = seg * M;
    const float INF = __int_as_float(0x7f800000);

    for (int t = threadIdx.x; t < Mpad; t += blockDim.x) {
        if (t < M) {
            float x = pos[(base + t) * 3 + 0];
            float y = pos[(base + t) * 3 + 1];
            float z = pos[(base + t) * 3 + 2];
            float sq = __fadd_rn(__fadd_rn(__fmul_rn(x, x), __fmul_rn(y, y)),
                                 __fmul_rn(z, z));
            sp[t] = make_float4(x, y, z, sq);
        } else {
            sp[t] = make_float4(0.0f, 0.0f, 0.0f, INF);  // d2=+inf: never captured
        }
    }
    __syncthreads();

    int warp = threadIdx.x >> 5;
    int lane = threadIdx.x & 31;
    int q = lb * QPB + warp;
    if (q >= M) return;                 // uniform per warp

    float4 Q = sp[q];
    int* mybuf = capbuf + warp * CAP;

    // ---- Main scan: distributed key-only top-17 + capture (4 cand/lane) ----
    float kkey   = 3.4e38f;             // lane t (t<=16): one unsorted slot
    float curmax = 3.4e38f;             // uniform: max over slots 0..16
    int   cnt    = 0;                   // captures (uniform)

    #define PROC(MASK, D2VAR, JBASE)                                        \
        while (MASK) {                                                      \
            int src = __ffs(MASK) - 1;                                      \
            MASK &= MASK - 1;                                               \
            float kd = __shfl_sync(FULLM, D2VAR, src);                      \
            if (kd <= curmax) {         /* uniform recheck, non-strict */   \
                int ki = (JBASE) + src;                                     \
                if (cnt < CAP) { if (lane == 0) mybuf[cnt] = ki; }          \
                cnt++;                                                      \
                if (kd < curmax) {      /* strict: structure update */      \
                    unsigned mx = __ballot_sync(FULLM,                      \
                                      (lane < KP1) && (kkey == curmax));    \
                    if (lane == __ffs(mx) - 1) kkey = kd;                   \
                    unsigned enc = (lane < KP1) ? f2u(kkey) : 0u;           \
                    curmax = u2f(__reduce_max_sync(FULLM, enc));            \
                }                                                           \
            }                                                               \
        }

    for (int j0 = 0; j0 < Mpad; j0 += 128) {
        float d2a = cand_d2(Q, sp[j0 + lane]);
        float d2b = cand_d2(Q, sp[j0 + 32 + lane]);
        float d2c = cand_d2(Q, sp[j0 + 64 + lane]);
        float d2d = cand_d2(Q, sp[j0 + 96 + lane]);
        // Batches a->b->c->d fully in order: ascending candidate index.
        unsigned ma = __ballot_sync(FULLM, d2a <= curmax);
        PROC(ma, d2a, j0);
        unsigned mb = __ballot_sync(FULLM, d2b <= curmax);
        PROC(mb, d2b, j0 + 32);
        unsigned mc = __ballot_sync(FULLM, d2c <= curmax);
        PROC(mc, d2c, j0 + 64);
        unsigned md = __ballot_sync(FULLM, d2d <= curmax);
        PROC(md, d2d, j0 + 96);
    }
    #undef PROC
    float thr = curmax;
    __syncwarp();                       // lane-0 capture writes -> all lanes

    // ---- Filter pass: emit captured ids with d2 <= thr, index order ----
    int outp = (base + q) * KNB;
    int w = 0;                          // non-self emitted (uniform)
    if (cnt <= CAP) {
        for (int b0 = 0; b0 < cnt; b0 += 32) {
            int idx = b0 + lane;
            bool valid = (idx < cnt);
            int id = valid ? mybuf[idx] : 0;
            float d2 = valid ? cand_d2(Q, sp[id]) : INF;
            bool emit = valid && (d2 <= thr) && (id != q);
            unsigned em = __ballot_sync(FULLM, emit);
            int pos = w + __popc(em & ((1u << lane) - 1u));
            if (emit && pos < KNB)
                g_nbr[outp + pos] = base + id;
            w += __popc(em);
        }
    } else {
        // Overflow (adversarial only): full threshold scan, index order.
        for (int j0 = 0; j0 < Mpad; j0 += 32) {
            int j = j0 + lane;
            float d2 = cand_d2(Q, sp[j]);
            bool emit = (d2 <= thr) && (j != q);
            unsigned em = __ballot_sync(FULLM, emit);
            int pos = w + __popc(em & ((1u << lane) - 1u));
            if (emit && pos < KNB)
                g_nbr[outp + pos] = base + j;
            w += __popc(em);
        }
    }

    // ---- Rare exact fallback: count != 17 -> verbatim R5 id-chain ----
    if (w + 1 != KP1) {
        float fk[KP1];
        int   fi[KP1];
        #pragma unroll
        for (int t = 0; t < KP1; t++) { fk[t] = 3.4e38f; fi[t] = -1; }
        for (int j0 = 0; j0 < Mpad; j0 += 32) {
            float d2 = cand_d2(Q, sp[j0 + lane]);
            unsigned m = __ballot_sync(FULLM, d2 < fk[KP1 - 1]);
            while (m) {
                int src = __ffs(m) - 1;
                m &= m - 1;
                float kd = __shfl_sync(FULLM, d2, src);
                int   ki = j0 + src;
                if (kd < fk[KP1 - 1]) {
                    #pragma unroll
                    for (int t = 0; t < KP1; t++) {
                        if (kd < fk[t]) {
                            float tk = fk[t]; fk[t] = kd; kd = tk;
                            int   ti = fi[t]; fi[t] = ki; ki = ti;
                        }
                    }
                }
            }
        }
        if (lane == 0) {
            int w2 = 0;
            #pragma unroll
            for (int t = 0; t < KP1; t++) {
                if (fi[t] != q && w2 < KNB) {
                    g_nbr[outp + w2] = base + fi[t]; w2++;
                }
            }
        }
    }
}

// ===========================================================================
// Faithful fp32 port of the LAPACK ssyevd(N=3, jobz='V', uplo='L') path:
// ssytrd (slarfg Householder) -> ssteqr('I') -> sormtr. All math in
// round-to-nearest intrinsics so fast-math flags cannot change decisions.
// ===========================================================================
__device__ __forceinline__ float f_div(float a, float b) { return __fdiv_rn(a, b); }
__device__ __forceinline__ float f_sqrt(float a)         { return __fsqrt_rn(a); }
// Fortran SIGN(a,b): |a| if b >= 0 (incl. -0.0 since -0>=0 in C), else -|a|.
__device__ __forceinline__ float f_sign(float a, float b) {
    float aa = fabsf(a);
    return (b >= 0.0f) ? aa : -aa;
}

__device__ float slapy2f(float x, float y) {
    float xa = fabsf(x), ya = fabsf(y);
    float w = fmaxf(xa, ya), zm = fminf(xa, ya);
    if (zm == 0.0f) return w;
    float q = f_div(zm, w);
    return __fmul_rn(w, f_sqrt(__fadd_rn(1.0f, __fmul_rn(q, q))));
}

// LAPACK >= 3.10 slartg (unscaled branch; our magnitudes are mid-range).
__device__ void slartgf(float f, float g, float* c, float* s, float* r) {
    if (g == 0.0f)      { *c = 1.0f; *s = 0.0f; *r = f; }
    else if (f == 0.0f) { *c = 0.0f; *s = f_sign(1.0f, g); *r = fabsf(g); }
    else {
        float d = f_sqrt(__fadd_rn(__fmul_rn(f, f), __fmul_rn(g, g)));
        *c = f_div(fabsf(f), d);
        *r = f_sign(d, f);
        *s = f_div(g, *r);
    }
}

__device__ void slaev2f(float a, float b, float c_, float* rt1, float* rt2,
                        float* cs1, float* sn1) {
    float sm  = __fadd_rn(a, c_);
    float df  = __fadd_rn(a, -c_);
    float adf = fabsf(df);
    float tb  = __fadd_rn(b, b);
    float ab  = fabsf(tb);
    float acmx, acmn;
    if (fabsf(a) > fabsf(c_)) { acmx = a; acmn = c_; }
    else                      { acmx = c_; acmn = a; }
    float rt;
    if (adf > ab) {
        float q = f_div(ab, adf);
        rt = __fmul_rn(adf, f_sqrt(__fadd_rn(1.0f, __fmul_rn(q, q))));
    } else if (adf < ab) {
        float q = f_div(adf, ab);
        rt = __fmul_rn(ab, f_sqrt(__fadd_rn(1.0f, __fmul_rn(q, q))));
    } else {
        rt = __fmul_rn(ab, f_sqrt(2.0f));
    }
    int sgn1;
    if (sm < 0.0f) {
        *rt1 = __fmul_rn(0.5f, __fadd_rn(sm, -rt)); sgn1 = -1;
        *rt2 = __fadd_rn(__fmul_rn(f_div(acmx, *rt1), acmn),
                         -__fmul_rn(f_div(b, *rt1), b));
    } else if (sm > 0.0f) {
        *rt1 = __fmul_rn(0.5f, __fadd_rn(sm, rt)); sgn1 = 1;
        *rt2 = __fadd_rn(__fmul_rn(f_div(acmx, *rt1), acmn),
                         -__fmul_rn(f_div(b, *rt1), b));
    } else {
        *rt1 = __fmul_rn(0.5f, rt); *rt2 = __fmul_rn(-0.5f, rt); sgn1 = 1;
    }
    float cs; int sgn2;
    if (df >= 0.0f) { cs = __fadd_rn(df, rt);  sgn2 = 1;  }
    else            { cs = __fadd_rn(df, -rt); sgn2 = -1; }
    float acs = fabsf(cs);
    float c1, s1;
    if (acs > ab) {
        float ct = f_div(-tb, cs);
        s1 = f_div(1.0f, f_sqrt(__fadd_rn(1.0f, __fmul_rn(ct, ct))));
        c1 = __fmul_rn(ct, s1);
    } else {
        if (ab == 0.0f) { c1 = 1.0f; s1 = 0.0f; }
        else {
            float tn = f_div(-cs, tb);
            c1 = f_div(1.0f, f_sqrt(__fadd_rn(1.0f, __fmul_rn(tn, tn))));
            s1 = __fmul_rn(tn, c1);
        }
    }
    if (sgn1 == sgn2) { float tn = c1; c1 = -s1; s1 = tn; }
    *cs1 = c1; *sn1 = s1;
}

// ssteqr('I', n=3): d[3], e[2], z = identity on entry; eigenvectors of the
// tridiagonal in z columns, ascending eigenvalues, LAPACK sign conventions.
__device__ void ssteqr3(float* d, float* e, float z[3][3]) {
    const float eps    = 5.9604645e-08f;   // slamch('E') fp32 = 2^-24
    const float eps2   = eps * eps;
    const float safmin = 1.1754944e-38f;
    const int   n = 3;
    const int   nmaxit = n * 30;
    int jtot = 0;
    int l1 = 1;                            // 1-based throughout

    for (int guard = 0; guard < 64; guard++) {
        if (l1 > n) break;
        if (l1 > 1) e[l1 - 2] = 0.0f;
        int m;
        for (m = l1; m <= n - 1; m++) {
            float tst = fabsf(e[m - 1]);
            if (tst == 0.0f) break;
            if (tst <= __fmul_rn(__fmul_rn(f_sqrt(fabsf(d[m - 1])),
                                           f_sqrt(fabsf(d[m]))), eps)) {
                e[m - 1] = 0.0f;
                break;
            }
        }
        int l = l1, lsv = l, lend = m, lendsv = lend;
        l1 = m + 1;
        if (lend == l) continue;

        if (fabsf(d[lend - 1]) < fabsf(d[l - 1])) { lend = lsv; l = lendsv; }

        if (lend > l) {
            // ---- QL iteration ----
            for (;;) {
                int mm_;
                for (mm_ = l; mm_ <= lend - 1; mm_++) {
                    float tst = __fmul_rn(e[mm_ - 1], e[mm_ - 1]);
                    if (tst <= __fadd_rn(__fmul_rn(__fmul_rn(eps2, fabsf(d[mm_ - 1])),
                                                   fabsf(d[mm_])), safmin))
                        break;
                }
                int m2 = mm_;                        // == lend if no break
                if (m2 < lend) e[m2 - 1] = 0.0f;
                float p = d[l - 1];
                if (m2 == l) {                       // eigenvalue found
                    d[l - 1] = p;
                    l++;
                    if (l <= lend) continue;
                    break;
                }
                if (m2 == l + 1) {                   // 2x2: slaev2
                    float rt1, rt2, cc, ss;
                    slaev2f(d[l - 1], e[l - 1], d[l], &rt1, &rt2, &cc, &ss);
                    for (int i2 = 0; i2 < 3; i2++) { // slasr 'R','V','B', 2 cols
                        float t = z[i2][l];
                        z[i2][l]     = __fadd_rn(__fmul_rn(cc, t), -__fmul_rn(ss, z[i2][l - 1]));
                        z[i2][l - 1] = __fadd_rn(__fmul_rn(ss, t),  __fmul_rn(cc, z[i2][l - 1]));
                    }
                    d[l - 1] = rt1; d[l] = rt2; e[l - 1] = 0.0f;
                    l += 2;
                    if (l <= lend) continue;
                    break;
                }
                if (jtot == nmaxit) break;
                jtot++;
                float g = f_div(__fadd_rn(d[l], -p), __fmul_rn(2.0f, e[l - 1]));
                float r = slapy2f(g, 1.0f);
                g = __fadd_rn(__fadd_rn(d[m2 - 1], -p),
                              f_div(e[l - 1], __fadd_rn(g, f_sign(r, g))));
                float s = 1.0f, c = 1.0f;
                p = 0.0f;
                float csv[2], snv[2];
                for (int i2 = m2 - 1; i2 >= l; i2--) {
                    float fv = __fmul_rn(s, e[i2 - 1]);
                    float bv = __fmul_rn(c, e[i2 - 1]);
                    slartgf(g, fv, &c, &s, &r);
                    if (i2 != m2 - 1) e[i2] = r;
                    g = __fadd_rn(d[i2], -p);
                    r = __fadd_rn(__fmul_rn(__fadd_rn(d[i2 - 1], -g), s),
                                  __fmul_rn(__fmul_rn(2.0f, c), bv));
                    p = __fmul_rn(s, r);
                    d[i2] = __fadd_rn(g, p);
                    g = __fadd_rn(__fmul_rn(c, r), -bv);
                    csv[i2 - l] = c; snv[i2 - l] = -s;
                }
                int cnt = m2 - l + 1;               // slasr 'R','V','B'
                for (int jj = cnt - 1; jj >= 1; jj--) {
                    float cc = csv[jj - 1], ss = snv[jj - 1];
                    for (int i2 = 0; i2 < 3; i2++) {
                        float t = z[i2][l - 1 + jj];
                        z[i2][l - 1 + jj]     = __fadd_rn(__fmul_rn(cc, t), -__fmul_rn(ss, z[i2][l - 2 + jj]));
                        z[i2][l - 2 + jj]     = __fadd_rn(__fmul_rn(ss, t),  __fmul_rn(cc, z[i2][l - 2 + jj]));
                    }
                }
                d[l - 1] = __fadd_rn(d[l - 1], -p);
                e[l - 1] = g;
            }
        } else {
            // ---- QR iteration (lend < l) ----
            for (;;) {
                int mm_;
                for (mm_ = l; mm_ >= lend + 1; mm_--) {
                    float tst = __fmul_rn(e[mm_ - 2], e[mm_ - 2]);
                    if (tst <= __fadd_rn(__fmul_rn(__fmul_rn(eps2, fabsf(d[mm_ - 1])),
                                                   fabsf(d[mm_ - 2])), safmin))
                        break;
                }
                int m2 = mm_;                        // == lend if no break
                if (m2 > lend) e[m2 - 2] = 0.0f;
                float p = d[l - 1];
                if (m2 == l) {
                    d[l - 1] = p;
                    l--;
                    if (l >= lend) continue;
                    break;
                }
                if (m2 == l - 1) {
                    float rt1, rt2, cc, ss;
                    slaev2f(d[l - 2], e[l - 2], d[l - 1], &rt1, &rt2, &cc, &ss);
                    for (int i2 = 0; i2 < 3; i2++) { // slasr 'R','V','F', 2 cols
                        float t = z[i2][l - 1];
                        z[i2][l - 1] = __fadd_rn(__fmul_rn(cc, t), -__fmul_rn(ss, z[i2][l - 2]));
                        z[i2][l - 2] = __fadd_rn(__fmul_rn(ss, t),  __fmul_rn(cc, z[i2][l - 2]));
                    }
                    d[l - 2] = rt1; d[l - 1] = rt2; e[l - 2] = 0.0f;
                    l -= 2;
                    if (l >= lend) continue;
                    break;
                }
                if (jtot == nmaxit) break;
                jtot++;
                float g = f_div(__fadd_rn(d[l - 2], -p), __fmul_rn(2.0f, e[l - 2]));
                float r = slapy2f(g, 1.0f);
                g = __fadd_rn(__fadd_rn(d[m2 - 1], -p),
                              f_div(e[l - 2], __fadd_rn(g, f_sign(r, g))));
                float s = 1.0f, c = 1.0f;
                p = 0.0f;
                float csv[2], snv[2];
                for (int i2 = m2; i2 <= l - 1; i2++) {
                    float fv = __fmul_rn(s, e[i2 - 1]);
                    float bv = __fmul_rn(c, e[i2 - 1]);
                    slartgf(g, fv, &c, &s, &r);
                    if (i2 != m2) e[i2 - 2] = r;
                    g = __fadd_rn(d[i2 - 1], -p);
                    r = __fadd_rn(__fmul_rn(__fadd_rn(d[i2], -g), s),
                                  __fmul_rn(__fmul_rn(2.0f, c), bv));
                    p = __fmul_rn(s, r);
                    d[i2 - 1] = __fadd_rn(g, p);
                    g = __fadd_rn(__fmul_rn(c, r), -bv);
                    csv[i2 - m2] = c; snv[i2 - m2] = s;
                }
                int cnt = l - m2 + 1;               // slasr 'R','V','F'
                for (int jj = 1; jj <= cnt - 1; jj++) {
                    float cc = csv[jj - 1], ss = snv[jj - 1];
                    for (int i2 = 0; i2 < 3; i2++) {
                        float t = z[i2][m2 - 1 + jj];
                        z[i2][m2 - 1 + jj] = __fadd_rn(__fmul_rn(cc, t), -__fmul_rn(ss, z[i2][m2 - 2 + jj]));
                        z[i2][m2 - 2 + jj] = __fadd_rn(__fmul_rn(ss, t),  __fmul_rn(cc, z[i2][m2 - 2 + jj]));
                    }
                }
                d[l - 1] = __fadd_rn(d[l - 1], -p);
                e[l - 2] = g;
            }
        }
    }

    // Sort eigenvalues ascending, swapping columns (no sign change).
    for (int ii = 2; ii <= n; ii++) {
        int i = ii - 1, k = i;
        float p = d[i - 1];
        for (int jj = ii; jj <= n; jj++)
            if (d[jj - 1] < p) { k = jj; p = d[jj - 1]; }
        if (k != i) {
            d[k - 1] = d[i - 1]; d[i - 1] = p;
            for (int r_ = 0; r_ < 3; r_++) {
                float t = z[r_][i - 1]; z[r_][i - 1] = z[r_][k - 1]; z[r_][k - 1] = t;
            }
        }
    }
}

// One thread per point: covariance of K neighbors, then LAPACK-faithful
// smallest-eigenvalue eigenvector (ssytrd + ssteqr + Householder apply).
__global__ void normals_kernel(const float* __restrict__ pos, int N) {
    int i = blockIdx.x * blockDim.x + threadIdx.x;
    if (i >= N) return;

    float px[KNB], py[KNB], pz[KNB];
    float mx = 0.f, my = 0.f, mz = 0.f;
    #pragma unroll
    for (int t = 0; t < KNB; t++) {
        int j = g_nbr[i * KNB + t];
        px[t] = pos[j * 3 + 0];
        py[t] = pos[j * 3 + 1];
        pz[t] = pos[j * 3 + 2];
        mx += px[t]; my += py[t]; mz += pz[t];
    }
    const float invK = 1.0f / (float)KNB;
    mx *= invK; my *= invK; mz *= invK;

    float c00 = 0.f, c10 = 0.f, c20 = 0.f, c11 = 0.f, c21 = 0.f, c22 = 0.f;
    #pragma unroll
    for (int t = 0; t < KNB; t++) {
        float dx = px[t] - mx, dy = py[t] - my, dz = pz[t] - mz;
        c00 += dx * dx; c10 += dy * dx; c20 += dz * dx;
        c11 += dy * dy; c21 += dz * dy; c22 += dz * dz;
    }
    c00 *= invK; c10 *= invK; c20 *= invK;
    c11 *= invK; c21 *= invK; c22 *= invK;

    // ---- ssytrd (lower, N=3): one Householder annihilating c20 ----
    float e0, e1, d1c, d2c, tau1, v3;
    if (c20 == 0.0f) {                     // xnorm == 0 -> tau = 0, H = I
        tau1 = 0.0f; v3 = 0.0f;
        e0 = c10; d1c = c11; d2c = c22; e1 = c21;
    } else {
        float alpha = c10;
        float beta  = -f_sign(slapy2f(alpha, fabsf(c20)), alpha);
        tau1 = f_div(__fadd_rn(beta, -alpha), beta);
        v3   = f_div(c20, __fadd_rn(alpha, -beta));
        e0   = beta;
        float x1 = __fmul_rn(tau1, __fadd_rn(c11, __fmul_rn(c21, v3)));
        float x2 = __fmul_rn(tau1, __fadd_rn(c21, __fmul_rn(c22, v3)));
        float al = __fmul_rn(__fmul_rn(-0.5f, tau1),
                             __fadd_rn(x1, __fmul_rn(x2, v3)));
        float w1 = __fadd_rn(x1, al);
        float w2 = __fadd_rn(x2, __fmul_rn(al, v3));
        d1c = __fadd_rn(c11, -__fmul_rn(2.0f, w1));
        e1  = __fadd_rn(c21, -__fadd_rn(__fmul_rn(v3, w1), w2));
        d2c = __fadd_rn(c22, -__fmul_rn(__fmul_rn(2.0f, v3), w2));
    }

    float d[3] = { c00, d1c, d2c };
    float e[2] = { e0, e1 };
    float z[3][3] = { {1.f, 0.f, 0.f}, {0.f, 1.f, 0.f}, {0.f, 0.f, 1.f} };
    ssteqr3(d, e, z);

    // ---- sormtr: v_full = Q * z[:,0], Q = I - tau*u*u', u = (0,1,v3) ----
    float z1 = z[1][0], z2 = z[2][0];
    float q11 = 1.0f - tau1;
    float q12 = -__fmul_rn(tau1, v3);
    float q22 = 1.0f - __fmul_rn(tau1, __fmul_rn(v3, v3));
    float vx = z[0][0];
    float vy = __fadd_rn(__fmul_rn(q11, z1), __fmul_rn(q12, z2));
    float vz = __fadd_rn(__fmul_rn(q12, z1), __fmul_rn(q22, z2));

    float nn = fmaxf(f_sqrt(vx * vx + vy * vy + vz * vz), 1e-12f);
    g_norm[i * 3 + 0] = f_div(vx, nn);
    g_norm[i * 3 + 1] = f_div(vy, nn);
    g_norm[i * 3 + 2] = f_div(vz, nn);
}

// ---------------------------------------------------------------------------
// Warp per point, two-phase. Phase 1: per edge t, fd2 via warp reduce
// (identical arithmetic to R16); lane t retains (fd2_t, j_t). Phase 2:
// lanes 0..15 compute the scalar chain (gate/exp/tanh) ONCE for their edge,
// then a 16-lane tree reduce -> lane 0 atomicAdd. Last block (ticket) writes
// the final mean (self-resetting counter -> graph-replay safe).
__global__ void edge_kernel(const float* __restrict__ rgb,
                            const int* __restrict__ target, int N,
                            float* __restrict__ out) {
    int warp = (blockIdx.x * blockDim.x + threadIdx.x) >> 5;
    int lane = threadIdx.x & 31;
    int i = warp;

    if (i < N) {
        float f0 = g_featn[i * 64 + lane];
        float f1 = g_featn[i * 64 + 32 + lane];

        // Phase 1: fd2 for each edge; lane t keeps edge t's results.
        float myfd2 = 0.0f;
        int   myj   = 0;
        #pragma unroll
        for (int t = 0; t < KNB; t++) {
            int j = g_nbr[i * KNB + t];             // uniform (broadcast)
            float d0 = f0 - g_featn[j * 64 + lane];
            float d1 = f1 - g_featn[j * 64 + 32 + lane];
            float s  = d0 * d0 + d1 * d1;
            #pragma unroll
            for (int o = 16; o; o >>= 1) s += __shfl_xor_sync(FULLM, s, o);
            if (lane == t) { myfd2 = s; myj = j; }
        }

        // Phase 2: lane t computes scalar terms once for edge t.
        float term = 0.0f;
        if (lane < KNB) {
            int j = myj;
            bool gate = (target[j] == target[i]);
            float dx = g_norm[i * 3 + 0] - g_norm[j * 3 + 0];
            float dy = g_norm[i * 3 + 1] - g_norm[j * 3 + 1];
            float dz = g_norm[i * 3 + 2] - g_norm[j * 3 + 2];
            float nd2 = dx * dx + dy * dy + dz * dz;
            float geo = expf(-nd2 * 50.0f);         // exp(-nd2 / (2*0.1^2))

            float cx = rgb[i * 3 + 0] - rgb[j * 3 + 0];
            float cy = rgb[i * 3 + 1] - rgb[j * 3 + 1];
            float cz = rgb[i * 3 + 2] - rgb[j * 3 + 2];
            float rd2 = cx * cx + cy * cy + cz * cz;
            float inv = tanhf(5.0f * rd2);

            term = gate ? geo * inv * myfd2 : 0.0f;
        }
        // Tree reduce over the 16 lanes (lanes >= 16 contribute 0 and the
        // o<=8 butterfly stays within 16-lane halves).
        #pragma unroll
        for (int o = 8; o; o >>= 1) term += __shfl_xor_sync(FULLM, term, o);
        if (lane == 0) atomicAdd(&g_acc, (double)term);
    }

    // Fused finalize: last block to arrive writes the output.
    __syncthreads();
    __threadfence();
    if (threadIdx.x == 0) {
        int t = atomicAdd(&g_done, 1);
        if (t == (int)gridDim.x - 1) {
            g_done = 0;                             // reset for graph replay
            out[0] = (float)(g_acc / (double)((long long)N * KNB));
        }
    }
}

// ---------------------------------------------------------------------------
extern "C" void kernel_launch(void* const* d_in, const int* in_sizes, int n_in,
                              void* d_out, int out_size) {
    const float* features = (const float*)d_in[0];
    const float* pos      = (const float*)d_in[1];
    const float* rgb      = (const float*)d_in[2];
    const int*   target   = (const int*)d_in[3];
    // d_in[4] = batch (sorted equal segments; implied by N/NSEG)

    int N = in_sizes[3];
    if (N > MAXN) N = MAXN;
    int M = N / NSEG;
    int Mpad = (M + 127) & ~127;                  // 128-aligned (4 cand/lane)

    int warpBlocks = (N + 3) / 4;                 // 4 warps (128 thr) per block
    featnorm_kernel<<<warpBlocks, 128>>>(features, N);

    int bps = (M + QPB - 1) / QPB;                // blocks per segment
    size_t smem = (size_t)Mpad * sizeof(float4)   // staged positions
                + (size_t)QPB * CAP * sizeof(int);// capture buffers
    cudaFuncSetAttribute(knn_kernel,
                         cudaFuncAttributeMaxDynamicSharedMemorySize,
                         (int)smem);
    knn_kernel<<<NSEG * bps, QPB * 32, smem>>>(pos, M, Mpad, bps);

    normals_kernel<<<(N + 127) / 128, 128>>>(pos, N);

    edge_kernel<<<warpBlocks, 128>>>(rgb, target, N, (float*)d_out);
}